// round 1
// baseline (speedup 1.0000x reference)
#include <cuda_runtime.h>
#include <math.h>

#define Bn   16
#define Cn   256
#define HWn  1024
#define ADn  16
#define SCn  32
#define CRn  64
#define C4n  1024
#define NPIX (Bn*HWn)   // 16384

// ---------------- device scratch (no allocations allowed) ----------------
__device__ float g_s[Bn*Cn];            // SE gate (post-sigmoid)
__device__ float g_q[Bn*HWn*ADn];       // [b][m][16]
__device__ float g_k[Bn*HWn*ADn];       // [b][m][16]
__device__ float g_v[Bn*HWn*SCn];       // [b][m][32]
__device__ float g_y[Cn*NPIX];          // [c][p], p = b*1024+n  (FFN input)
__device__ float g_h[C4n*NPIX];         // [j][p]               (FFN hidden)

// ---------------- kernel 1: squeeze-excite gate ----------------
__global__ __launch_bounds__(256) void se_kernel(
    const float* __restrict__ x,
    const float* __restrict__ fc1_w, const float* __restrict__ fc1_b,
    const float* __restrict__ fc2_w, const float* __restrict__ fc2_b)
{
    __shared__ float mean[Cn];
    __shared__ float s1[CRn];
    int b = blockIdx.x;
    int tid = threadIdx.x, warp = tid >> 5, lane = tid & 31;

    const float4* xb = (const float4*)(x + (size_t)b*Cn*HWn);
    for (int c = warp; c < Cn; c += 8) {
        const float4* row = xb + (size_t)c*(HWn/4);
        float sum = 0.f;
        #pragma unroll
        for (int j = 0; j < HWn/4/32; j++) {
            float4 v = row[lane + 32*j];
            sum += v.x + v.y + v.z + v.w;
        }
        #pragma unroll
        for (int o = 16; o > 0; o >>= 1) sum += __shfl_xor_sync(0xffffffffu, sum, o);
        if (lane == 0) mean[c] = sum * (1.0f/HWn);
    }
    __syncthreads();

    if (tid < CRn) {
        float acc = fc1_b[tid];
        const float* wr = fc1_w + tid*Cn;
        #pragma unroll 8
        for (int c = 0; c < Cn; c++) acc += wr[c]*mean[c];
        s1[tid] = fmaxf(acc, 0.f);
    }
    __syncthreads();
    {
        float acc = fc2_b[tid];
        const float* wr = fc2_w + tid*CRn;
        #pragma unroll 8
        for (int j = 0; j < CRn; j++) acc += wr[j]*s1[j];
        g_s[b*Cn + tid] = 1.f/(1.f + __expf(-acc));
    }
}

// ---------------- kernel 2: qkv projection on gated attn channels ----------------
__global__ __launch_bounds__(256) void qkv_kernel(
    const float* __restrict__ x,
    const float* __restrict__ qkv_w, const float* __restrict__ qkv_b)
{
    __shared__ float w[SCn][64];   // transposed: [c][o]
    __shared__ float bias[64];
    __shared__ float sg[SCn];

    int b = blockIdx.y;
    int tid = threadIdx.x;
    int m = blockIdx.x*256 + tid;

    for (int i = tid; i < 64*SCn; i += 256) { int o = i / SCn, c = i % SCn; w[c][o] = qkv_w[i]; }
    if (tid < 64)  bias[tid] = qkv_b[tid];
    if (tid < SCn) sg[tid]   = g_s[b*Cn + tid];
    __syncthreads();

    float acc[64];
    #pragma unroll
    for (int o = 0; o < 64; o++) acc[o] = bias[o];

    const float* xb = x + (size_t)b*Cn*HWn + m;
    #pragma unroll
    for (int c = 0; c < SCn; c++) {
        float xv = xb[(size_t)c*HWn] * sg[c];
        #pragma unroll
        for (int o4 = 0; o4 < 16; o4++) {
            float4 wv = *(const float4*)&w[c][o4*4];
            acc[o4*4+0] += wv.x*xv;
            acc[o4*4+1] += wv.y*xv;
            acc[o4*4+2] += wv.z*xv;
            acc[o4*4+3] += wv.w*xv;
        }
    }

    float* qo = g_q + (size_t)(b*HWn + m)*ADn;
    float* ko = g_k + (size_t)(b*HWn + m)*ADn;
    float* vo = g_v + (size_t)(b*HWn + m)*SCn;
    #pragma unroll
    for (int i = 0; i < ADn/4; i++) ((float4*)qo)[i] = make_float4(acc[4*i], acc[4*i+1], acc[4*i+2], acc[4*i+3]);
    #pragma unroll
    for (int i = 0; i < ADn/4; i++) ((float4*)ko)[i] = make_float4(acc[ADn+4*i], acc[ADn+4*i+1], acc[ADn+4*i+2], acc[ADn+4*i+3]);
    #pragma unroll
    for (int i = 0; i < SCn/4; i++) ((float4*)vo)[i] = make_float4(acc[2*ADn+4*i], acc[2*ADn+4*i+1], acc[2*ADn+4*i+2], acc[2*ADn+4*i+3]);
}

// ---------------- kernel 3: gate non-attn channels into y ----------------
__global__ __launch_bounds__(256) void gate_y_kernel(const float* __restrict__ x)
{
    int idx = blockIdx.x*256 + threadIdx.x;       // over 16*224*1024
    int n = idx & (HWn-1);
    int t = idx >> 10;
    int c = SCn + (t % (Cn - SCn));
    int b = t / (Cn - SCn);
    float s = g_s[b*Cn + c];
    g_y[(size_t)c*NPIX + b*HWn + n] = x[((size_t)b*Cn + c)*HWn + n] * s;
}

// ---------------- kernel 4: attention (scores+softmax+V-agg+proj) ----------------
// grid (8, 16): blockIdx.y = batch, blockIdx.x = 128-row chunk. 256 threads,
// 2 threads (adjacent lanes) per output row, splitting the m dimension by parity.
#define ATTN_SMEM_FLOATS (HWn*ADn + HWn*SCn + SCn*SCn + SCn)
__global__ __launch_bounds__(256) void attn_kernel(
    const float* __restrict__ proj_w, const float* __restrict__ proj_b)
{
    extern __shared__ float sm[];
    float* kT = sm;                       // [1024][16]
    float* vT = sm + HWn*ADn;             // [1024][32]
    float* pw = vT + HWn*SCn;             // [32][32]
    float* pb = pw + SCn*SCn;             // [32]

    int b = blockIdx.y;
    int tid = threadIdx.x;

    // stage k, v, proj weights into smem (pure float4 copies)
    {
        const float4* gk = (const float4*)(g_k + (size_t)b*HWn*ADn);
        float4* s4 = (float4*)kT;
        for (int i = tid; i < HWn*ADn/4; i += 256) s4[i] = gk[i];
        const float4* gv = (const float4*)(g_v + (size_t)b*HWn*SCn);
        float4* v4 = (float4*)vT;
        for (int i = tid; i < HWn*SCn/4; i += 256) v4[i] = gv[i];
        for (int i = tid; i < SCn*SCn; i += 256) pw[i] = proj_w[i];
        if (tid < SCn) pb[tid] = proj_b[tid];
    }
    __syncthreads();

    int r  = tid >> 1;
    int hh = tid & 1;
    int n  = blockIdx.x*128 + r;

    float q[16];
    {
        const float4* qg = (const float4*)(g_q + (size_t)(b*HWn + n)*ADn);
        #pragma unroll
        for (int i = 0; i < 4; i++) {
            float4 t = qg[i];
            q[4*i] = t.x; q[4*i+1] = t.y; q[4*i+2] = t.z; q[4*i+3] = t.w;
        }
    }

    const float scale = 0.25f;   // AD^-0.5

    // pass 1: online max + sum of exp over this lane's half of m
    float mx = -1e30f, se = 0.f;
    for (int j = 0; j < HWn/2; j++) {
        int m = 2*j + hh;
        const float4* kv = (const float4*)(kT + m*ADn);
        float4 a = kv[0], c4 = kv[1], d4 = kv[2], e4 = kv[3];
        float s = q[0]*a.x + q[1]*a.y + q[2]*a.z + q[3]*a.w
                + q[4]*c4.x + q[5]*c4.y + q[6]*c4.z + q[7]*c4.w
                + q[8]*d4.x + q[9]*d4.y + q[10]*d4.z + q[11]*d4.w
                + q[12]*e4.x + q[13]*e4.y + q[14]*e4.z + q[15]*e4.w;
        s *= scale;
        if (s > mx) { se = se*__expf(mx - s) + 1.f; mx = s; }
        else        { se += __expf(s - mx); }
    }
    // combine the row's two halves (adjacent lanes)
    float mx2 = __shfl_xor_sync(0xffffffffu, mx, 1);
    float se2 = __shfl_xor_sync(0xffffffffu, se, 1);
    float M   = fmaxf(mx, mx2);
    float SE  = se*__expf(mx - M) + se2*__expf(mx2 - M);
    float inv = 1.f/SE;

    // pass 2: accumulate out[c] = sum_m p[m] * v[c][m]
    float vacc[SCn];
    #pragma unroll
    for (int c = 0; c < SCn; c++) vacc[c] = 0.f;

    for (int j = 0; j < HWn/2; j++) {
        int m = 2*j + hh;
        const float4* kv = (const float4*)(kT + m*ADn);
        float4 a = kv[0], c4 = kv[1], d4 = kv[2], e4 = kv[3];
        float s = q[0]*a.x + q[1]*a.y + q[2]*a.z + q[3]*a.w
                + q[4]*c4.x + q[5]*c4.y + q[6]*c4.z + q[7]*c4.w
                + q[8]*d4.x + q[9]*d4.y + q[10]*d4.z + q[11]*d4.w
                + q[12]*e4.x + q[13]*e4.y + q[14]*e4.z + q[15]*e4.w;
        float p = __expf(s*scale - M) * inv;
        const float4* vv = (const float4*)(vT + m*SCn);
        #pragma unroll
        for (int c8 = 0; c8 < 8; c8++) {
            float4 v4 = vv[c8];
            vacc[4*c8+0] += p*v4.x;
            vacc[4*c8+1] += p*v4.y;
            vacc[4*c8+2] += p*v4.z;
            vacc[4*c8+3] += p*v4.w;
        }
    }
    // pair-reduce: both lanes end with the full row result
    #pragma unroll
    for (int c = 0; c < SCn; c++) vacc[c] += __shfl_xor_sync(0xffffffffu, vacc[c], 1);

    // proj (32x32): even lane writes out channels 0..15, odd lane 16..31
    #pragma unroll
    for (int i = 0; i < 16; i++) {
        int oc = hh*16 + i;
        float a = pb[oc];
        #pragma unroll
        for (int c8 = 0; c8 < 8; c8++) {
            float4 w4 = *(const float4*)&pw[oc*SCn + c8*4];
            a += w4.x*vacc[4*c8+0] + w4.y*vacc[4*c8+1] + w4.z*vacc[4*c8+2] + w4.w*vacc[4*c8+3];
        }
        g_y[(size_t)oc*NPIX + b*HWn + n] = a;
    }
}

// ---------------- kernel 5/6: SGEMM 128x128, 8x8 register tiles ----------------
// C[M,N] = A[M,K] @ B[K,N] + bias[m], optional relu.
// OUTMODE 0: C row-major [M][N]. OUTMODE 1: C = d_out [b][M][1024], p = b*1024+n.
template<bool RELU, int OUTMODE>
__global__ __launch_bounds__(256) void sgemm128(
    const float* __restrict__ A, const float* __restrict__ Bm,
    const float* __restrict__ bias, float* __restrict__ Cm,
    int M, int N, int K)
{
    __shared__ float As[2][8][132];
    __shared__ float Bs[2][8][128];

    int tid = threadIdx.x;
    int tx = tid & 15, ty = tid >> 4;
    int m0 = blockIdx.y*128, n0 = blockIdx.x*128;

    float acc[8][8];
    #pragma unroll
    for (int i = 0; i < 8; i++)
        #pragma unroll
        for (int j = 0; j < 8; j++) acc[i][j] = 0.f;

    int arow = tid >> 1;
    int ak   = (tid & 1) * 4;
    int brow = tid >> 5;
    int bcol = (tid & 31) * 4;
    const float* Aptr = A  + (size_t)(m0 + arow)*K + ak;
    const float* Bptr = Bm + (size_t)brow*N + n0 + bcol;

    { // prologue
        float4 av = *(const float4*)Aptr;
        As[0][ak+0][arow] = av.x; As[0][ak+1][arow] = av.y;
        As[0][ak+2][arow] = av.z; As[0][ak+3][arow] = av.w;
        float4 bv = *(const float4*)Bptr;
        *(float4*)&Bs[0][brow][bcol] = bv;
    }
    __syncthreads();

    int nk = K/8;
    for (int ks = 0; ks < nk; ks++) {
        int cur = ks & 1, nxt = cur ^ 1;
        if (ks + 1 < nk) {
            float4 av = *(const float4*)(Aptr + (ks+1)*8);
            float4 bv = *(const float4*)(Bptr + (size_t)(ks+1)*8*N);
            As[nxt][ak+0][arow] = av.x; As[nxt][ak+1][arow] = av.y;
            As[nxt][ak+2][arow] = av.z; As[nxt][ak+3][arow] = av.w;
            *(float4*)&Bs[nxt][brow][bcol] = bv;
        }
        #pragma unroll
        for (int kk = 0; kk < 8; kk++) {
            float a[8], bb[8];
            *(float4*)&a[0]  = *(const float4*)&As[cur][kk][ty*8];
            *(float4*)&a[4]  = *(const float4*)&As[cur][kk][ty*8 + 4];
            *(float4*)&bb[0] = *(const float4*)&Bs[cur][kk][tx*8];
            *(float4*)&bb[4] = *(const float4*)&Bs[cur][kk][tx*8 + 4];
            #pragma unroll
            for (int i = 0; i < 8; i++)
                #pragma unroll
                for (int j = 0; j < 8; j++)
                    acc[i][j] += a[i]*bb[j];
        }
        __syncthreads();
    }

    #pragma unroll
    for (int i = 0; i < 8; i++) {
        int mrow = m0 + ty*8 + i;
        float bi = bias[mrow];
        float4 lo = make_float4(acc[i][0]+bi, acc[i][1]+bi, acc[i][2]+bi, acc[i][3]+bi);
        float4 hi = make_float4(acc[i][4]+bi, acc[i][5]+bi, acc[i][6]+bi, acc[i][7]+bi);
        if (RELU) {
            lo.x = fmaxf(lo.x,0.f); lo.y = fmaxf(lo.y,0.f); lo.z = fmaxf(lo.z,0.f); lo.w = fmaxf(lo.w,0.f);
            hi.x = fmaxf(hi.x,0.f); hi.y = fmaxf(hi.y,0.f); hi.z = fmaxf(hi.z,0.f); hi.w = fmaxf(hi.w,0.f);
        }
        int ncol = n0 + tx*8;
        if (OUTMODE == 0) {
            float* dst = Cm + (size_t)mrow*N + ncol;
            *(float4*)&dst[0] = lo;
            *(float4*)&dst[4] = hi;
        } else {
            int bb_ = ncol >> 10;
            int nn  = ncol & (HWn-1);
            float* dst = Cm + (size_t)bb_*Cn*HWn + (size_t)mrow*HWn + nn;
            *(float4*)&dst[0] = lo;
            *(float4*)&dst[4] = hi;
        }
    }
}

// ---------------- launch ----------------
extern "C" void kernel_launch(void* const* d_in, const int* in_sizes, int n_in,
                              void* d_out, int out_size)
{
    const float* x      = (const float*)d_in[0];
    const float* fc1_w  = (const float*)d_in[1];
    const float* fc1_b  = (const float*)d_in[2];
    const float* fc2_w  = (const float*)d_in[3];
    const float* fc2_b  = (const float*)d_in[4];
    const float* qkv_w  = (const float*)d_in[5];
    const float* qkv_b  = (const float*)d_in[6];
    const float* proj_w = (const float*)d_in[7];
    const float* proj_b = (const float*)d_in[8];
    const float* ffn1_w = (const float*)d_in[9];
    const float* ffn1_b = (const float*)d_in[10];
    const float* ffn2_w = (const float*)d_in[11];
    const float* ffn2_b = (const float*)d_in[12];
    float* out = (float*)d_out;

    const size_t attn_smem = (size_t)ATTN_SMEM_FLOATS * sizeof(float);
    cudaFuncSetAttribute(attn_kernel, cudaFuncAttributeMaxDynamicSharedMemorySize, (int)attn_smem);

    float *yp = nullptr, *hp = nullptr;
    cudaGetSymbolAddress((void**)&yp, g_y);
    cudaGetSymbolAddress((void**)&hp, g_h);

    se_kernel<<<Bn, 256>>>(x, fc1_w, fc1_b, fc2_w, fc2_b);
    qkv_kernel<<<dim3(4, Bn), 256>>>(x, qkv_w, qkv_b);
    gate_y_kernel<<<(Bn*(Cn-SCn)*HWn)/256, 256>>>(x);
    attn_kernel<<<dim3(8, Bn), 256, attn_smem>>>(proj_w, proj_b);
    sgemm128<true, 0><<<dim3(NPIX/128, C4n/128), 256>>>(ffn1_w, yp, ffn1_b, hp, C4n, NPIX, Cn);
    sgemm128<false, 1><<<dim3(NPIX/128, Cn/128), 256>>>(ffn2_w, hp, ffn2_b, out, Cn, NPIX, C4n);
}

// round 2
// speedup vs baseline: 1.0039x; 1.0039x over previous
#include <cuda_runtime.h>
#include <math.h>

#define Bn   16
#define Cn   256
#define HWn  1024
#define ADn  16
#define SCn  32
#define CRn  64
#define C4n  1024
#define NPIX (Bn*HWn)   // 16384

// ---------------- device scratch (no allocations allowed) ----------------
__device__ float g_s[Bn*Cn];            // SE gate (post-sigmoid)
__device__ float g_q[Bn*HWn*ADn];       // [b][m][16]
__device__ float g_k[Bn*HWn*ADn];       // [b][m][16]
__device__ float g_v[Bn*HWn*SCn];       // [b][m][32]
__device__ float g_y[Cn*NPIX];          // [c][p], p = b*1024+n  (FFN input)
__device__ float g_h[C4n*NPIX];         // [j][p]               (FFN hidden)

// ---------------- kernel 1: squeeze-excite gate ----------------
__global__ __launch_bounds__(256) void se_kernel(
    const float* __restrict__ x,
    const float* __restrict__ fc1_w, const float* __restrict__ fc1_b,
    const float* __restrict__ fc2_w, const float* __restrict__ fc2_b)
{
    __shared__ float mean[Cn];
    __shared__ float s1[CRn];
    int b = blockIdx.x;
    int tid = threadIdx.x, warp = tid >> 5, lane = tid & 31;

    const float4* xb = (const float4*)(x + (size_t)b*Cn*HWn);
    for (int c = warp; c < Cn; c += 8) {
        const float4* row = xb + (size_t)c*(HWn/4);
        float sum = 0.f;
        #pragma unroll
        for (int j = 0; j < HWn/4/32; j++) {
            float4 v = row[lane + 32*j];
            sum += v.x + v.y + v.z + v.w;
        }
        #pragma unroll
        for (int o = 16; o > 0; o >>= 1) sum += __shfl_xor_sync(0xffffffffu, sum, o);
        if (lane == 0) mean[c] = sum * (1.0f/HWn);
    }
    __syncthreads();

    if (tid < CRn) {
        float acc = fc1_b[tid];
        const float* wr = fc1_w + tid*Cn;
        #pragma unroll 8
        for (int c = 0; c < Cn; c++) acc += wr[c]*mean[c];
        s1[tid] = fmaxf(acc, 0.f);
    }
    __syncthreads();
    {
        float acc = fc2_b[tid];
        const float* wr = fc2_w + tid*CRn;
        #pragma unroll 8
        for (int j = 0; j < CRn; j++) acc += wr[j]*s1[j];
        g_s[b*Cn + tid] = 1.f/(1.f + __expf(-acc));
    }
}

// ---------------- kernel 2: qkv projection on gated attn channels ----------------
__global__ __launch_bounds__(256) void qkv_kernel(
    const float* __restrict__ x,
    const float* __restrict__ qkv_w, const float* __restrict__ qkv_b)
{
    __shared__ float w[SCn][64];   // transposed: [c][o]
    __shared__ float bias[64];
    __shared__ float sg[SCn];

    int b = blockIdx.y;
    int tid = threadIdx.x;
    int m = blockIdx.x*256 + tid;

    for (int i = tid; i < 64*SCn; i += 256) { int o = i / SCn, c = i % SCn; w[c][o] = qkv_w[i]; }
    if (tid < 64)  bias[tid] = qkv_b[tid];
    if (tid < SCn) sg[tid]   = g_s[b*Cn + tid];
    __syncthreads();

    float acc[64];
    #pragma unroll
    for (int o = 0; o < 64; o++) acc[o] = bias[o];

    const float* xb = x + (size_t)b*Cn*HWn + m;
    #pragma unroll
    for (int c = 0; c < SCn; c++) {
        float xv = xb[(size_t)c*HWn] * sg[c];
        #pragma unroll
        for (int o4 = 0; o4 < 16; o4++) {
            float4 wv = *(const float4*)&w[c][o4*4];
            acc[o4*4+0] += wv.x*xv;
            acc[o4*4+1] += wv.y*xv;
            acc[o4*4+2] += wv.z*xv;
            acc[o4*4+3] += wv.w*xv;
        }
    }

    float* qo = g_q + (size_t)(b*HWn + m)*ADn;
    float* ko = g_k + (size_t)(b*HWn + m)*ADn;
    float* vo = g_v + (size_t)(b*HWn + m)*SCn;
    #pragma unroll
    for (int i = 0; i < ADn/4; i++) ((float4*)qo)[i] = make_float4(acc[4*i], acc[4*i+1], acc[4*i+2], acc[4*i+3]);
    #pragma unroll
    for (int i = 0; i < ADn/4; i++) ((float4*)ko)[i] = make_float4(acc[ADn+4*i], acc[ADn+4*i+1], acc[ADn+4*i+2], acc[ADn+4*i+3]);
    #pragma unroll
    for (int i = 0; i < SCn/4; i++) ((float4*)vo)[i] = make_float4(acc[2*ADn+4*i], acc[2*ADn+4*i+1], acc[2*ADn+4*i+2], acc[2*ADn+4*i+3]);
}

// ---------------- kernel 3: gate non-attn channels into y ----------------
__global__ __launch_bounds__(256) void gate_y_kernel(const float* __restrict__ x)
{
    int idx = blockIdx.x*256 + threadIdx.x;       // over 16*224*1024
    int n = idx & (HWn-1);
    int t = idx >> 10;
    int c = SCn + (t % (Cn - SCn));
    int b = t / (Cn - SCn);
    float s = g_s[b*Cn + c];
    g_y[(size_t)c*NPIX + b*HWn + n] = x[((size_t)b*Cn + c)*HWn + n] * s;
}

// ---------------- kernel 4: attention (scores+softmax+V-agg+proj) ----------------
// grid (8, 16): blockIdx.y = batch, blockIdx.x = 128-row chunk. 256 threads,
// 2 threads (adjacent lanes) per output row, splitting the m dimension by parity.
#define ATTN_SMEM_FLOATS (HWn*ADn + HWn*SCn + SCn*SCn + SCn)
__global__ __launch_bounds__(256) void attn_kernel(
    const float* __restrict__ proj_w, const float* __restrict__ proj_b)
{
    extern __shared__ float sm[];
    float* kT = sm;                       // [1024][16]
    float* vT = sm + HWn*ADn;             // [1024][32]
    float* pw = vT + HWn*SCn;             // [32][32]
    float* pb = pw + SCn*SCn;             // [32]

    int b = blockIdx.y;
    int tid = threadIdx.x;

    // stage k, v, proj weights into smem (pure float4 copies)
    {
        const float4* gk = (const float4*)(g_k + (size_t)b*HWn*ADn);
        float4* s4 = (float4*)kT;
        for (int i = tid; i < HWn*ADn/4; i += 256) s4[i] = gk[i];
        const float4* gv = (const float4*)(g_v + (size_t)b*HWn*SCn);
        float4* v4 = (float4*)vT;
        for (int i = tid; i < HWn*SCn/4; i += 256) v4[i] = gv[i];
        for (int i = tid; i < SCn*SCn; i += 256) pw[i] = proj_w[i];
        if (tid < SCn) pb[tid] = proj_b[tid];
    }
    __syncthreads();

    int r  = tid >> 1;
    int hh = tid & 1;
    int n  = blockIdx.x*128 + r;

    float q[16];
    {
        const float4* qg = (const float4*)(g_q + (size_t)(b*HWn + n)*ADn);
        #pragma unroll
        for (int i = 0; i < 4; i++) {
            float4 t = qg[i];
            q[4*i] = t.x; q[4*i+1] = t.y; q[4*i+2] = t.z; q[4*i+3] = t.w;
        }
    }

    const float scale = 0.25f;   // AD^-0.5

    // pass 1: online max + sum of exp over this lane's half of m
    float mx = -1e30f, se = 0.f;
    for (int j = 0; j < HWn/2; j++) {
        int m = 2*j + hh;
        const float4* kv = (const float4*)(kT + m*ADn);
        float4 a = kv[0], c4 = kv[1], d4 = kv[2], e4 = kv[3];
        float s = q[0]*a.x + q[1]*a.y + q[2]*a.z + q[3]*a.w
                + q[4]*c4.x + q[5]*c4.y + q[6]*c4.z + q[7]*c4.w
                + q[8]*d4.x + q[9]*d4.y + q[10]*d4.z + q[11]*d4.w
                + q[12]*e4.x + q[13]*e4.y + q[14]*e4.z + q[15]*e4.w;
        s *= scale;
        if (s > mx) { se = se*__expf(mx - s) + 1.f; mx = s; }
        else        { se += __expf(s - mx); }
    }
    // combine the row's two halves (adjacent lanes)
    float mx2 = __shfl_xor_sync(0xffffffffu, mx, 1);
    float se2 = __shfl_xor_sync(0xffffffffu, se, 1);
    float M   = fmaxf(mx, mx2);
    float SE  = se*__expf(mx - M) + se2*__expf(mx2 - M);
    float inv = 1.f/SE;

    // pass 2: accumulate out[c] = sum_m p[m] * v[c][m]
    float vacc[SCn];
    #pragma unroll
    for (int c = 0; c < SCn; c++) vacc[c] = 0.f;

    for (int j = 0; j < HWn/2; j++) {
        int m = 2*j + hh;
        const float4* kv = (const float4*)(kT + m*ADn);
        float4 a = kv[0], c4 = kv[1], d4 = kv[2], e4 = kv[3];
        float s = q[0]*a.x + q[1]*a.y + q[2]*a.z + q[3]*a.w
                + q[4]*c4.x + q[5]*c4.y + q[6]*c4.z + q[7]*c4.w
                + q[8]*d4.x + q[9]*d4.y + q[10]*d4.z + q[11]*d4.w
                + q[12]*e4.x + q[13]*e4.y + q[14]*e4.z + q[15]*e4.w;
        float p = __expf(s*scale - M) * inv;
        const float4* vv = (const float4*)(vT + m*SCn);
        #pragma unroll
        for (int c8 = 0; c8 < 8; c8++) {
            float4 v4 = vv[c8];
            vacc[4*c8+0] += p*v4.x;
            vacc[4*c8+1] += p*v4.y;
            vacc[4*c8+2] += p*v4.z;
            vacc[4*c8+3] += p*v4.w;
        }
    }
    // pair-reduce: both lanes end with the full row result
    #pragma unroll
    for (int c = 0; c < SCn; c++) vacc[c] += __shfl_xor_sync(0xffffffffu, vacc[c], 1);

    // proj (32x32): even lane writes out channels 0..15, odd lane 16..31
    #pragma unroll
    for (int i = 0; i < 16; i++) {
        int oc = hh*16 + i;
        float a = pb[oc];
        #pragma unroll
        for (int c8 = 0; c8 < 8; c8++) {
            float4 w4 = *(const float4*)&pw[oc*SCn + c8*4];
            a += w4.x*vacc[4*c8+0] + w4.y*vacc[4*c8+1] + w4.z*vacc[4*c8+2] + w4.w*vacc[4*c8+3];
        }
        g_y[(size_t)oc*NPIX + b*HWn + n] = a;
    }
}

// ---------------- kernel 5/6: SGEMM 128x128, 8x8 register tiles ----------------
// C[M,N] = A[M,K] @ B[K,N] + bias[m], optional relu.
// OUTMODE 0: C row-major [M][N]. OUTMODE 1: C = d_out [b][M][1024], p = b*1024+n.
template<bool RELU, int OUTMODE>
__global__ __launch_bounds__(256) void sgemm128(
    const float* __restrict__ A, const float* __restrict__ Bm,
    const float* __restrict__ bias, float* __restrict__ Cm,
    int M, int N, int K)
{
    __shared__ float As[2][8][132];
    __shared__ float Bs[2][8][128];

    int tid = threadIdx.x;
    int tx = tid & 15, ty = tid >> 4;
    int m0 = blockIdx.y*128, n0 = blockIdx.x*128;

    float acc[8][8];
    #pragma unroll
    for (int i = 0; i < 8; i++)
        #pragma unroll
        for (int j = 0; j < 8; j++) acc[i][j] = 0.f;

    int arow = tid >> 1;
    int ak   = (tid & 1) * 4;
    int brow = tid >> 5;
    int bcol = (tid & 31) * 4;
    const float* Aptr = A  + (size_t)(m0 + arow)*K + ak;
    const float* Bptr = Bm + (size_t)brow*N + n0 + bcol;

    { // prologue
        float4 av = *(const float4*)Aptr;
        As[0][ak+0][arow] = av.x; As[0][ak+1][arow] = av.y;
        As[0][ak+2][arow] = av.z; As[0][ak+3][arow] = av.w;
        float4 bv = *(const float4*)Bptr;
        *(float4*)&Bs[0][brow][bcol] = bv;
    }
    __syncthreads();

    int nk = K/8;
    for (int ks = 0; ks < nk; ks++) {
        int cur = ks & 1, nxt = cur ^ 1;
        if (ks + 1 < nk) {
            float4 av = *(const float4*)(Aptr + (ks+1)*8);
            float4 bv = *(const float4*)(Bptr + (size_t)(ks+1)*8*N);
            As[nxt][ak+0][arow] = av.x; As[nxt][ak+1][arow] = av.y;
            As[nxt][ak+2][arow] = av.z; As[nxt][ak+3][arow] = av.w;
            *(float4*)&Bs[nxt][brow][bcol] = bv;
        }
        #pragma unroll
        for (int kk = 0; kk < 8; kk++) {
            float a[8], bb[8];
            *(float4*)&a[0]  = *(const float4*)&As[cur][kk][ty*8];
            *(float4*)&a[4]  = *(const float4*)&As[cur][kk][ty*8 + 4];
            *(float4*)&bb[0] = *(const float4*)&Bs[cur][kk][tx*8];
            *(float4*)&bb[4] = *(const float4*)&Bs[cur][kk][tx*8 + 4];
            #pragma unroll
            for (int i = 0; i < 8; i++)
                #pragma unroll
                for (int j = 0; j < 8; j++)
                    acc[i][j] += a[i]*bb[j];
        }
        __syncthreads();
    }

    #pragma unroll
    for (int i = 0; i < 8; i++) {
        int mrow = m0 + ty*8 + i;
        float bi = bias[mrow];
        float4 lo = make_float4(acc[i][0]+bi, acc[i][1]+bi, acc[i][2]+bi, acc[i][3]+bi);
        float4 hi = make_float4(acc[i][4]+bi, acc[i][5]+bi, acc[i][6]+bi, acc[i][7]+bi);
        if (RELU) {
            lo.x = fmaxf(lo.x,0.f); lo.y = fmaxf(lo.y,0.f); lo.z = fmaxf(lo.z,0.f); lo.w = fmaxf(lo.w,0.f);
            hi.x = fmaxf(hi.x,0.f); hi.y = fmaxf(hi.y,0.f); hi.z = fmaxf(hi.z,0.f); hi.w = fmaxf(hi.w,0.f);
        }
        int ncol = n0 + tx*8;
        if (OUTMODE == 0) {
            float* dst = Cm + (size_t)mrow*N + ncol;
            *(float4*)&dst[0] = lo;
            *(float4*)&dst[4] = hi;
        } else {
            int bb_ = ncol >> 10;
            int nn  = ncol & (HWn-1);
            float* dst = Cm + (size_t)bb_*Cn*HWn + (size_t)mrow*HWn + nn;
            *(float4*)&dst[0] = lo;
            *(float4*)&dst[4] = hi;
        }
    }
}

// ---------------- launch ----------------
extern "C" void kernel_launch(void* const* d_in, const int* in_sizes, int n_in,
                              void* d_out, int out_size)
{
    const float* x      = (const float*)d_in[0];
    const float* fc1_w  = (const float*)d_in[1];
    const float* fc1_b  = (const float*)d_in[2];
    const float* fc2_w  = (const float*)d_in[3];
    const float* fc2_b  = (const float*)d_in[4];
    const float* qkv_w  = (const float*)d_in[5];
    const float* qkv_b  = (const float*)d_in[6];
    const float* proj_w = (const float*)d_in[7];
    const float* proj_b = (const float*)d_in[8];
    const float* ffn1_w = (const float*)d_in[9];
    const float* ffn1_b = (const float*)d_in[10];
    const float* ffn2_w = (const float*)d_in[11];
    const float* ffn2_b = (const float*)d_in[12];
    float* out = (float*)d_out;

    const size_t attn_smem = (size_t)ATTN_SMEM_FLOATS * sizeof(float);
    cudaFuncSetAttribute(attn_kernel, cudaFuncAttributeMaxDynamicSharedMemorySize, (int)attn_smem);

    float *yp = nullptr, *hp = nullptr;
    cudaGetSymbolAddress((void**)&yp, g_y);
    cudaGetSymbolAddress((void**)&hp, g_h);

    se_kernel<<<Bn, 256>>>(x, fc1_w, fc1_b, fc2_w, fc2_b);
    qkv_kernel<<<dim3(4, Bn), 256>>>(x, qkv_w, qkv_b);
    gate_y_kernel<<<(Bn*(Cn-SCn)*HWn)/256, 256>>>(x);
    attn_kernel<<<dim3(8, Bn), 256, attn_smem>>>(proj_w, proj_b);
    sgemm128<true, 0><<<dim3(NPIX/128, C4n/128), 256>>>(ffn1_w, yp, ffn1_b, hp, C4n, NPIX, Cn);
    sgemm128<false, 1><<<dim3(NPIX/128, Cn/128), 256>>>(ffn2_w, hp, ffn2_b, out, Cn, NPIX, C4n);
}

// round 4
// speedup vs baseline: 1.6414x; 1.6350x over previous
#include <cuda_runtime.h>
#include <cuda_bf16.h>
#include <cstdint>
#include <math.h>

#define Bn   16
#define Cn   256
#define HWn  1024
#define ADn  16
#define SCn  32
#define CRn  64
#define C4n  1024
#define NPIX (Bn*HWn)   // 16384

// ======================= device scratch =======================
__device__ float g_s[Bn*Cn];
__device__ float g_q[Bn*HWn*ADn];
__device__ float g_k[Bn*HWn*ADn];
__device__ float g_v[Bn*HWn*SCn];
// FFN operands, bf16 split hi/lo, pixel-major (row-major A for MMA)
__device__ __align__(256) __nv_bfloat16 g_yh[NPIX*Cn];
__device__ __align__(256) __nv_bfloat16 g_yl[NPIX*Cn];
__device__ __align__(256) __nv_bfloat16 g_hh[NPIX*C4n];
__device__ __align__(256) __nv_bfloat16 g_hl[NPIX*C4n];
// weights transposed to [K][N] bf16 hi/lo
__device__ __align__(256) __nv_bfloat16 g_w1h[Cn*C4n];
__device__ __align__(256) __nv_bfloat16 g_w1l[Cn*C4n];
__device__ __align__(256) __nv_bfloat16 g_w2h[C4n*Cn];
__device__ __align__(256) __nv_bfloat16 g_w2l[C4n*Cn];

// ======================= mma helpers (non-'a' PTX, HMMA path) ==================
__device__ __forceinline__ uint32_t smem_to_u32(const void* p) {
    uint32_t a;
    asm("{ .reg .u64 t; cvta.to.shared.u64 t, %1; cvt.u32.u64 %0, t; }" : "=r"(a) : "l"(p));
    return a;
}
__device__ __forceinline__ void ldsm_x4(uint32_t r[4], uint32_t addr) {
    asm volatile("ldmatrix.sync.aligned.m8n8.x4.shared.b16 {%0,%1,%2,%3}, [%4];"
        : "=r"(r[0]), "=r"(r[1]), "=r"(r[2]), "=r"(r[3]) : "r"(addr));
}
__device__ __forceinline__ void ldsm_x4_t(uint32_t r[4], uint32_t addr) {
    asm volatile("ldmatrix.sync.aligned.m8n8.x4.trans.shared.b16 {%0,%1,%2,%3}, [%4];"
        : "=r"(r[0]), "=r"(r[1]), "=r"(r[2]), "=r"(r[3]) : "r"(addr));
}
__device__ __forceinline__ void mma_bf16(float c[4], const uint32_t a[4], const uint32_t b[2]) {
    asm volatile("mma.sync.aligned.m16n8k16.row.col.f32.bf16.bf16.f32 "
        "{%0,%1,%2,%3}, {%4,%5,%6,%7}, {%8,%9}, {%0,%1,%2,%3};"
        : "+f"(c[0]), "+f"(c[1]), "+f"(c[2]), "+f"(c[3])
        : "r"(a[0]), "r"(a[1]), "r"(a[2]), "r"(a[3]), "r"(b[0]), "r"(b[1]));
}

// ======================= weight split + transpose =======================
// w: [O][K] fp32 -> th/tl: [K][O] bf16
__global__ __launch_bounds__(256) void convertw_T(
    const float* __restrict__ w, __nv_bfloat16* __restrict__ th, __nv_bfloat16* __restrict__ tl,
    int O, int K)
{
    int i = blockIdx.x*256 + threadIdx.x;
    if (i < O*K) {
        int o = i / K, k = i % K;
        float f = w[i];
        __nv_bfloat16 h = __float2bfloat16(f);
        th[(size_t)k*O + o] = h;
        tl[(size_t)k*O + o] = __float2bfloat16(f - __bfloat162float(h));
    }
}

// ======================= kernel 1: squeeze-excite gate =======================
__global__ __launch_bounds__(256) void se_kernel(
    const float* __restrict__ x,
    const float* __restrict__ fc1_w, const float* __restrict__ fc1_b,
    const float* __restrict__ fc2_w, const float* __restrict__ fc2_b)
{
    __shared__ float mean[Cn];
    __shared__ float s1[CRn];
    int b = blockIdx.x;
    int tid = threadIdx.x, warp = tid >> 5, lane = tid & 31;

    const float4* xb = (const float4*)(x + (size_t)b*Cn*HWn);
    for (int c = warp; c < Cn; c += 8) {
        const float4* row = xb + (size_t)c*(HWn/4);
        float sum = 0.f;
        #pragma unroll
        for (int j = 0; j < HWn/4/32; j++) {
            float4 v = row[lane + 32*j];
            sum += v.x + v.y + v.z + v.w;
        }
        #pragma unroll
        for (int o = 16; o > 0; o >>= 1) sum += __shfl_xor_sync(0xffffffffu, sum, o);
        if (lane == 0) mean[c] = sum * (1.0f/HWn);
    }
    __syncthreads();

    if (tid < CRn) {
        float acc = fc1_b[tid];
        const float* wr = fc1_w + tid*Cn;
        #pragma unroll 8
        for (int c = 0; c < Cn; c++) acc += wr[c]*mean[c];
        s1[tid] = fmaxf(acc, 0.f);
    }
    __syncthreads();
    {
        float acc = fc2_b[tid];
        const float* wr = fc2_w + tid*CRn;
        #pragma unroll 8
        for (int j = 0; j < CRn; j++) acc += wr[j]*s1[j];
        g_s[b*Cn + tid] = 1.f/(1.f + __expf(-acc));
    }
}

// ======================= kernel 2: qkv projection =======================
__global__ __launch_bounds__(256) void qkv_kernel(
    const float* __restrict__ x,
    const float* __restrict__ qkv_w, const float* __restrict__ qkv_b)
{
    __shared__ float w[SCn][64];
    __shared__ float bias[64];
    __shared__ float sg[SCn];

    int b = blockIdx.y;
    int tid = threadIdx.x;
    int m = blockIdx.x*256 + tid;

    for (int i = tid; i < 64*SCn; i += 256) { int o = i / SCn, c = i % SCn; w[c][o] = qkv_w[i]; }
    if (tid < 64)  bias[tid] = qkv_b[tid];
    if (tid < SCn) sg[tid]   = g_s[b*Cn + tid];
    __syncthreads();

    float acc[64];
    #pragma unroll
    for (int o = 0; o < 64; o++) acc[o] = bias[o];

    const float* xb = x + (size_t)b*Cn*HWn + m;
    #pragma unroll
    for (int c = 0; c < SCn; c++) {
        float xv = xb[(size_t)c*HWn] * sg[c];
        #pragma unroll
        for (int o4 = 0; o4 < 16; o4++) {
            float4 wv = *(const float4*)&w[c][o4*4];
            acc[o4*4+0] += wv.x*xv;
            acc[o4*4+1] += wv.y*xv;
            acc[o4*4+2] += wv.z*xv;
            acc[o4*4+3] += wv.w*xv;
        }
    }

    float* qo = g_q + (size_t)(b*HWn + m)*ADn;
    float* ko = g_k + (size_t)(b*HWn + m)*ADn;
    float* vo = g_v + (size_t)(b*HWn + m)*SCn;
    #pragma unroll
    for (int i = 0; i < ADn/4; i++) ((float4*)qo)[i] = make_float4(acc[4*i], acc[4*i+1], acc[4*i+2], acc[4*i+3]);
    #pragma unroll
    for (int i = 0; i < ADn/4; i++) ((float4*)ko)[i] = make_float4(acc[ADn+4*i], acc[ADn+4*i+1], acc[ADn+4*i+2], acc[ADn+4*i+3]);
    #pragma unroll
    for (int i = 0; i < SCn/4; i++) ((float4*)vo)[i] = make_float4(acc[2*ADn+4*i], acc[2*ADn+4*i+1], acc[2*ADn+4*i+2], acc[2*ADn+4*i+3]);
}

// ======================= kernel 3: gated non-attn channels -> yh/yl =======================
__global__ __launch_bounds__(256) void gate_y_kernel(const float* __restrict__ x)
{
    __shared__ float t[32][257];
    int b  = blockIdx.z;
    int c0 = SCn + blockIdx.y*32;
    int n0 = blockIdx.x*256;
    int tid = threadIdx.x;

    for (int i = tid; i < 32*256; i += 256) {
        int r = i >> 8, n = i & 255;
        t[r][n] = x[((size_t)b*Cn + (c0 + r))*HWn + n0 + n];
    }
    __syncthreads();

    int w = tid >> 5, l = tid & 31;
    float s = g_s[b*Cn + c0 + l];
    #pragma unroll 4
    for (int it = 0; it < 32; it++) {
        int n = w*32 + it;
        float v = t[l][n] * s;
        size_t p = (size_t)b*HWn + n0 + n;
        __nv_bfloat16 h = __float2bfloat16(v);
        g_yh[p*Cn + c0 + l] = h;
        g_yl[p*Cn + c0 + l] = __float2bfloat16(v - __bfloat162float(h));
    }
}

// ======================= kernel 4: attention =======================
#define ATTN_SMEM_FLOATS (HWn*ADn + HWn*SCn + SCn*SCn + SCn)
__global__ __launch_bounds__(256) void attn_kernel(
    const float* __restrict__ proj_w, const float* __restrict__ proj_b)
{
    extern __shared__ float sm[];
    float* kT = sm;
    float* vT = sm + HWn*ADn;
    float* pw = vT + HWn*SCn;
    float* pb = pw + SCn*SCn;

    int b = blockIdx.y;
    int tid = threadIdx.x;

    {
        const float4* gk = (const float4*)(g_k + (size_t)b*HWn*ADn);
        float4* s4 = (float4*)kT;
        for (int i = tid; i < HWn*ADn/4; i += 256) s4[i] = gk[i];
        const float4* gv = (const float4*)(g_v + (size_t)b*HWn*SCn);
        float4* v4 = (float4*)vT;
        for (int i = tid; i < HWn*SCn/4; i += 256) v4[i] = gv[i];
        for (int i = tid; i < SCn*SCn; i += 256) pw[i] = proj_w[i];
        if (tid < SCn) pb[tid] = proj_b[tid];
    }
    __syncthreads();

    int r  = tid >> 1;
    int hh = tid & 1;
    int n  = blockIdx.x*128 + r;

    float q[16];
    {
        const float4* qg = (const float4*)(g_q + (size_t)(b*HWn + n)*ADn);
        #pragma unroll
        for (int i = 0; i < 4; i++) {
            float4 t = qg[i];
            q[4*i] = t.x; q[4*i+1] = t.y; q[4*i+2] = t.z; q[4*i+3] = t.w;
        }
    }

    const float scale = 0.25f;

    float mx = -1e30f, se = 0.f;
    for (int j = 0; j < HWn/2; j++) {
        int m = 2*j + hh;
        const float4* kv = (const float4*)(kT + m*ADn);
        float4 a = kv[0], c4 = kv[1], d4 = kv[2], e4 = kv[3];
        float s = q[0]*a.x + q[1]*a.y + q[2]*a.z + q[3]*a.w
                + q[4]*c4.x + q[5]*c4.y + q[6]*c4.z + q[7]*c4.w
                + q[8]*d4.x + q[9]*d4.y + q[10]*d4.z + q[11]*d4.w
                + q[12]*e4.x + q[13]*e4.y + q[14]*e4.z + q[15]*e4.w;
        s *= scale;
        if (s > mx) { se = se*__expf(mx - s) + 1.f; mx = s; }
        else        { se += __expf(s - mx); }
    }
    float mx2 = __shfl_xor_sync(0xffffffffu, mx, 1);
    float se2 = __shfl_xor_sync(0xffffffffu, se, 1);
    float M   = fmaxf(mx, mx2);
    float SE  = se*__expf(mx - M) + se2*__expf(mx2 - M);
    float inv = 1.f/SE;

    float vacc[SCn];
    #pragma unroll
    for (int c = 0; c < SCn; c++) vacc[c] = 0.f;

    for (int j = 0; j < HWn/2; j++) {
        int m = 2*j + hh;
        const float4* kv = (const float4*)(kT + m*ADn);
        float4 a = kv[0], c4 = kv[1], d4 = kv[2], e4 = kv[3];
        float s = q[0]*a.x + q[1]*a.y + q[2]*a.z + q[3]*a.w
                + q[4]*c4.x + q[5]*c4.y + q[6]*c4.z + q[7]*c4.w
                + q[8]*d4.x + q[9]*d4.y + q[10]*d4.z + q[11]*d4.w
                + q[12]*e4.x + q[13]*e4.y + q[14]*e4.z + q[15]*e4.w;
        float p = __expf(s*scale - M) * inv;
        const float4* vv = (const float4*)(vT + m*SCn);
        #pragma unroll
        for (int c8 = 0; c8 < 8; c8++) {
            float4 v4 = vv[c8];
            vacc[4*c8+0] += p*v4.x;
            vacc[4*c8+1] += p*v4.y;
            vacc[4*c8+2] += p*v4.z;
            vacc[4*c8+3] += p*v4.w;
        }
    }
    #pragma unroll
    for (int c = 0; c < SCn; c++) vacc[c] += __shfl_xor_sync(0xffffffffu, vacc[c], 1);

    size_t p = (size_t)b*HWn + n;
    #pragma unroll
    for (int i = 0; i < 16; i++) {
        int oc = hh*16 + i;
        float a = pb[oc];
        #pragma unroll
        for (int c8 = 0; c8 < 8; c8++) {
            float4 w4 = *(const float4*)&pw[oc*SCn + c8*4];
            a += w4.x*vacc[4*c8+0] + w4.y*vacc[4*c8+1] + w4.z*vacc[4*c8+2] + w4.w*vacc[4*c8+3];
        }
        __nv_bfloat16 h = __float2bfloat16(a);
        g_yh[p*Cn + oc] = h;
        g_yl[p*Cn + oc] = __float2bfloat16(a - __bfloat162float(h));
    }
}

// ======================= kernels 5/6: mma.sync bf16-split GEMM =======================
// D[128 pix, 128 ch] per block. A: [p][K] bf16 hi/lo row-major. W: [K][N] bf16 hi/lo.
// 3-term split: Ah*Wh + Ah*Wl + Al*Wh, fp32 accumulate.
// MODE 1: relu(D+bias) -> Hh/Hl bf16 split, row-major [p][NTOT].
// MODE 2: D+bias -> Out fp32 [b][co][nn] via smem transpose.
#define KCh 32
#define A_STRIDE 40     // bf16 elems per A smem row (32 + 8 pad)
#define W_STRIDE 136    // bf16 elems per W smem row (128 + 8 pad)
#define OFF_AH 0
#define OFF_AL (128*A_STRIDE*2)
#define OFF_WH (2*128*A_STRIDE*2)
#define OFF_WL (2*128*A_STRIDE*2 + KCh*W_STRIDE*2)
#define STAGE_BYTES (2*128*A_STRIDE*2 + 2*KCh*W_STRIDE*2)   // 37888
#define GEMM_SMEM (2*STAGE_BYTES)                           // 75776

template<int NTOT, int KTOT, int MODE>
__global__ __launch_bounds__(256)
void mma_gemm_kernel(const __nv_bfloat16* __restrict__ Ah_g, const __nv_bfloat16* __restrict__ Al_g,
                     const __nv_bfloat16* __restrict__ Wh_g, const __nv_bfloat16* __restrict__ Wl_g,
                     const float* __restrict__ bias,
                     __nv_bfloat16* __restrict__ Hh, __nv_bfloat16* __restrict__ Hl,
                     float* __restrict__ Out)
{
    extern __shared__ char smraw[];
    const uint32_t smem_base = smem_to_u32(smraw);

    const int tid = threadIdx.x;
    const int lane = tid & 31, wid = tid >> 5;
    const int warp_m = wid & 3;         // 4 warps over M (32 rows each)
    const int warp_n = wid >> 2;        // 2 warps over N (64 cols each)
    const int m0 = blockIdx.y*128, n0 = blockIdx.x*128;
    constexpr int NC = KTOT / KCh;

    float acc[2][8][4];
    #pragma unroll
    for (int mt = 0; mt < 2; mt++)
        #pragma unroll
        for (int nt = 0; nt < 8; nt++)
            #pragma unroll
            for (int i = 0; i < 4; i++) acc[mt][nt][i] = 0.f;

    // staging registers
    uint4 ra_h[2], ra_l[2], rw_h[2], rw_l[2];
    const int a_row = tid >> 2, a_part = (tid & 3);          // +256: row+64
    const int w_row = tid >> 4, w_part = (tid & 15);         // +256: row+16

    auto LOAD = [&](int kc) {
        const __nv_bfloat16* ah = Ah_g + (size_t)(m0)*KTOT + kc*KCh;
        const __nv_bfloat16* al = Al_g + (size_t)(m0)*KTOT + kc*KCh;
        #pragma unroll
        for (int q = 0; q < 2; q++) {
            int row = a_row + q*64;
            ra_h[q] = *(const uint4*)(ah + (size_t)row*KTOT + a_part*8);
            ra_l[q] = *(const uint4*)(al + (size_t)row*KTOT + a_part*8);
        }
        const __nv_bfloat16* wh = Wh_g + (size_t)(kc*KCh)*NTOT + n0;
        const __nv_bfloat16* wl = Wl_g + (size_t)(kc*KCh)*NTOT + n0;
        #pragma unroll
        for (int q = 0; q < 2; q++) {
            int row = w_row + q*16;
            rw_h[q] = *(const uint4*)(wh + (size_t)row*NTOT + w_part*8);
            rw_l[q] = *(const uint4*)(wl + (size_t)row*NTOT + w_part*8);
        }
    };
    auto STORE = [&](int buf) {
        char* s = smraw + buf*STAGE_BYTES;
        #pragma unroll
        for (int q = 0; q < 2; q++) {
            int row = a_row + q*64;
            *(uint4*)(s + OFF_AH + (row*A_STRIDE + a_part*8)*2) = ra_h[q];
            *(uint4*)(s + OFF_AL + (row*A_STRIDE + a_part*8)*2) = ra_l[q];
            int wrow = w_row + q*16;
            *(uint4*)(s + OFF_WH + (wrow*W_STRIDE + w_part*8)*2) = rw_h[q];
            *(uint4*)(s + OFF_WL + (wrow*W_STRIDE + w_part*8)*2) = rw_l[q];
        }
    };
    auto COMPUTE = [&](int buf) {
        uint32_t sb = smem_base + buf*STAGE_BYTES;
        #pragma unroll
        for (int ks = 0; ks < 2; ks++) {
            int k0 = ks*16;
            uint32_t ah[2][4], al[2][4];
            #pragma unroll
            for (int mt = 0; mt < 2; mt++) {
                uint32_t off = ((warp_m*32 + mt*16 + (lane & 15))*A_STRIDE + k0 + ((lane >> 4) << 3))*2;
                ldsm_x4(ah[mt], sb + OFF_AH + off);
                ldsm_x4(al[mt], sb + OFF_AL + off);
            }
            uint32_t bh[8][2], bl[8][2];
            #pragma unroll
            for (int np = 0; np < 4; np++) {
                uint32_t off = ((k0 + (lane & 15))*W_STRIDE + warp_n*64 + np*16 + ((lane >> 4) << 3))*2;
                uint32_t r[4];
                ldsm_x4_t(r, sb + OFF_WH + off);
                bh[2*np][0] = r[0]; bh[2*np][1] = r[1];
                bh[2*np+1][0] = r[2]; bh[2*np+1][1] = r[3];
                ldsm_x4_t(r, sb + OFF_WL + off);
                bl[2*np][0] = r[0]; bl[2*np][1] = r[1];
                bl[2*np+1][0] = r[2]; bl[2*np+1][1] = r[3];
            }
            #pragma unroll
            for (int mt = 0; mt < 2; mt++)
                #pragma unroll
                for (int nt = 0; nt < 8; nt++) {
                    mma_bf16(acc[mt][nt], ah[mt], bh[nt]);
                    mma_bf16(acc[mt][nt], ah[mt], bl[nt]);
                    mma_bf16(acc[mt][nt], al[mt], bh[nt]);
                }
        }
    };

    LOAD(0); STORE(0);
    __syncthreads();
    for (int kc = 0; kc < NC; kc++) {
        if (kc + 1 < NC) LOAD(kc + 1);
        COMPUTE(kc & 1);
        if (kc + 1 < NC) STORE((kc + 1) & 1);
        __syncthreads();
    }

    if (MODE == 1) {
        #pragma unroll
        for (int mt = 0; mt < 2; mt++)
            #pragma unroll
            for (int half = 0; half < 2; half++) {
                int row = m0 + warp_m*32 + mt*16 + (lane >> 2) + half*8;
                #pragma unroll
                for (int nt = 0; nt < 8; nt++) {
                    int col = n0 + warp_n*64 + nt*8 + (lane & 3)*2;
                    float f0 = acc[mt][nt][half*2+0] + bias[col];
                    float f1 = acc[mt][nt][half*2+1] + bias[col+1];
                    f0 = fmaxf(f0, 0.f); f1 = fmaxf(f1, 0.f);
                    __nv_bfloat16 h0 = __float2bfloat16(f0), h1 = __float2bfloat16(f1);
                    __nv_bfloat16 l0 = __float2bfloat16(f0 - __bfloat162float(h0));
                    __nv_bfloat16 l1 = __float2bfloat16(f1 - __bfloat162float(h1));
                    uint32_t ph = (uint32_t)__bfloat16_as_ushort(h0) | ((uint32_t)__bfloat16_as_ushort(h1) << 16);
                    uint32_t pl = (uint32_t)__bfloat16_as_ushort(l0) | ((uint32_t)__bfloat16_as_ushort(l1) << 16);
                    *(uint32_t*)(Hh + (size_t)row*NTOT + col) = ph;
                    *(uint32_t*)(Hl + (size_t)row*NTOT + col) = pl;
                }
            }
    } else {
        // transpose through smem for coalesced channel-major stores
        float* Ct = (float*)smraw;            // [128][129]
        #pragma unroll
        for (int mt = 0; mt < 2; mt++)
            #pragma unroll
            for (int half = 0; half < 2; half++) {
                int rl = warp_m*32 + mt*16 + (lane >> 2) + half*8;
                #pragma unroll
                for (int nt = 0; nt < 8; nt++) {
                    int cl = warp_n*64 + nt*8 + (lane & 3)*2;
                    Ct[rl*129 + cl]     = acc[mt][nt][half*2+0];
                    Ct[rl*129 + cl + 1] = acc[mt][nt][half*2+1];
                }
            }
        __syncthreads();
        // 8 warps x 16 channels each; lanes sweep 128 pixels (coalesced 128B stores)
        int bb = m0 >> 10, nn0 = m0 & (HWn-1);
        #pragma unroll
        for (int cc = 0; cc < 16; cc++) {
            int col = wid*16 + cc;
            int co = n0 + col;
            float bi = bias[co];
            float* ob = Out + (size_t)bb*Cn*HWn + (size_t)co*HWn + nn0;
            #pragma unroll
            for (int j = 0; j < 4; j++) {
                int r = lane + 32*j;
                ob[r] = Ct[r*129 + col] + bi;
            }
        }
    }
}

// ======================= launch =======================
extern "C" void kernel_launch(void* const* d_in, const int* in_sizes, int n_in,
                              void* d_out, int out_size)
{
    const float* x      = (const float*)d_in[0];
    const float* fc1_w  = (const float*)d_in[1];
    const float* fc1_b  = (const float*)d_in[2];
    const float* fc2_w  = (const float*)d_in[3];
    const float* fc2_b  = (const float*)d_in[4];
    const float* qkv_w  = (const float*)d_in[5];
    const float* qkv_b  = (const float*)d_in[6];
    const float* proj_w = (const float*)d_in[7];
    const float* proj_b = (const float*)d_in[8];
    const float* ffn1_w = (const float*)d_in[9];
    const float* ffn1_b = (const float*)d_in[10];
    const float* ffn2_w = (const float*)d_in[11];
    const float* ffn2_b = (const float*)d_in[12];
    float* out = (float*)d_out;

    const size_t attn_smem = (size_t)ATTN_SMEM_FLOATS * sizeof(float);
    cudaFuncSetAttribute(attn_kernel, cudaFuncAttributeMaxDynamicSharedMemorySize, (int)attn_smem);
    cudaFuncSetAttribute((const void*)mma_gemm_kernel<C4n, Cn, 1>, cudaFuncAttributeMaxDynamicSharedMemorySize, GEMM_SMEM);
    cudaFuncSetAttribute((const void*)mma_gemm_kernel<Cn, C4n, 2>, cudaFuncAttributeMaxDynamicSharedMemorySize, GEMM_SMEM);

    __nv_bfloat16 *yh, *yl, *hh, *hl, *w1h, *w1l, *w2h, *w2l;
    cudaGetSymbolAddress((void**)&yh,  g_yh);
    cudaGetSymbolAddress((void**)&yl,  g_yl);
    cudaGetSymbolAddress((void**)&hh,  g_hh);
    cudaGetSymbolAddress((void**)&hl,  g_hl);
    cudaGetSymbolAddress((void**)&w1h, g_w1h);
    cudaGetSymbolAddress((void**)&w1l, g_w1l);
    cudaGetSymbolAddress((void**)&w2h, g_w2h);
    cudaGetSymbolAddress((void**)&w2l, g_w2l);

    convertw_T<<<(C4n*Cn)/256, 256>>>(ffn1_w, w1h, w1l, C4n, Cn);
    convertw_T<<<(Cn*C4n)/256, 256>>>(ffn2_w, w2h, w2l, Cn, C4n);

    se_kernel<<<Bn, 256>>>(x, fc1_w, fc1_b, fc2_w, fc2_b);
    qkv_kernel<<<dim3(4, Bn), 256>>>(x, qkv_w, qkv_b);
    gate_y_kernel<<<dim3(4, 7, Bn), 256>>>(x);
    attn_kernel<<<dim3(8, Bn), 256, attn_smem>>>(proj_w, proj_b);

    mma_gemm_kernel<C4n, Cn, 1><<<dim3(C4n/128, NPIX/128), 256, GEMM_SMEM>>>(
        yh, yl, w1h, w1l, ffn1_b, hh, hl, nullptr);
    mma_gemm_kernel<Cn, C4n, 2><<<dim3(Cn/128, NPIX/128), 256, GEMM_SMEM>>>(
        hh, hl, w2h, w2l, ffn2_b, nullptr, nullptr, out);
}

// round 5
// speedup vs baseline: 2.2837x; 1.3913x over previous
#include <cuda_runtime.h>
#include <cuda_bf16.h>
#include <cstdint>
#include <math.h>

#define Bn   16
#define Cn   256
#define HWn  1024
#define ADn  16
#define SCn  32
#define CRn  64
#define C4n  1024
#define NPIX (Bn*HWn)   // 16384

// ======================= device scratch =======================
__device__ float g_s[Bn*Cn];
// q/k/v bf16 hi/lo split: q,k [b][m][16], v [b][m][32]
__device__ __align__(256) __nv_bfloat16 g_qh[Bn*HWn*ADn];
__device__ __align__(256) __nv_bfloat16 g_ql[Bn*HWn*ADn];
__device__ __align__(256) __nv_bfloat16 g_kh[Bn*HWn*ADn];
__device__ __align__(256) __nv_bfloat16 g_kl[Bn*HWn*ADn];
__device__ __align__(256) __nv_bfloat16 g_vh[Bn*HWn*SCn];
__device__ __align__(256) __nv_bfloat16 g_vl[Bn*HWn*SCn];
// FFN operands, bf16 split hi/lo, pixel-major
__device__ __align__(256) __nv_bfloat16 g_yh[NPIX*Cn];
__device__ __align__(256) __nv_bfloat16 g_yl[NPIX*Cn];
__device__ __align__(256) __nv_bfloat16 g_hh[NPIX*C4n];
__device__ __align__(256) __nv_bfloat16 g_hl[NPIX*C4n];
// weights transposed to [K][N] bf16 hi/lo
__device__ __align__(256) __nv_bfloat16 g_w1h[Cn*C4n];
__device__ __align__(256) __nv_bfloat16 g_w1l[Cn*C4n];
__device__ __align__(256) __nv_bfloat16 g_w2h[C4n*Cn];
__device__ __align__(256) __nv_bfloat16 g_w2l[C4n*Cn];

// ======================= mma helpers (non-'a' PTX, HMMA path) ==================
__device__ __forceinline__ uint32_t smem_to_u32(const void* p) {
    uint32_t a;
    asm("{ .reg .u64 t; cvta.to.shared.u64 t, %1; cvt.u32.u64 %0, t; }" : "=r"(a) : "l"(p));
    return a;
}
__device__ __forceinline__ void ldsm_x4(uint32_t r[4], uint32_t addr) {
    asm volatile("ldmatrix.sync.aligned.m8n8.x4.shared.b16 {%0,%1,%2,%3}, [%4];"
        : "=r"(r[0]), "=r"(r[1]), "=r"(r[2]), "=r"(r[3]) : "r"(addr));
}
__device__ __forceinline__ void ldsm_x4_t(uint32_t r[4], uint32_t addr) {
    asm volatile("ldmatrix.sync.aligned.m8n8.x4.trans.shared.b16 {%0,%1,%2,%3}, [%4];"
        : "=r"(r[0]), "=r"(r[1]), "=r"(r[2]), "=r"(r[3]) : "r"(addr));
}
__device__ __forceinline__ void mma_bf16(float c[4], const uint32_t a[4], const uint32_t b[2]) {
    asm volatile("mma.sync.aligned.m16n8k16.row.col.f32.bf16.bf16.f32 "
        "{%0,%1,%2,%3}, {%4,%5,%6,%7}, {%8,%9}, {%0,%1,%2,%3};"
        : "+f"(c[0]), "+f"(c[1]), "+f"(c[2]), "+f"(c[3])
        : "r"(a[0]), "r"(a[1]), "r"(a[2]), "r"(a[3]), "r"(b[0]), "r"(b[1]));
}
// split two fp32 into packed bf16 hi-word and lo-word
__device__ __forceinline__ void split2(float f0, float f1, uint32_t& hw, uint32_t& lw) {
    __nv_bfloat16 h0 = __float2bfloat16(f0), h1 = __float2bfloat16(f1);
    __nv_bfloat16 l0 = __float2bfloat16(f0 - __bfloat162float(h0));
    __nv_bfloat16 l1 = __float2bfloat16(f1 - __bfloat162float(h1));
    hw = (uint32_t)__bfloat16_as_ushort(h0) | ((uint32_t)__bfloat16_as_ushort(h1) << 16);
    lw = (uint32_t)__bfloat16_as_ushort(l0) | ((uint32_t)__bfloat16_as_ushort(l1) << 16);
}

// ======================= weight split + transpose =======================
__global__ __launch_bounds__(256) void convertw_T(
    const float* __restrict__ w, __nv_bfloat16* __restrict__ th, __nv_bfloat16* __restrict__ tl,
    int O, int K)
{
    int i = blockIdx.x*256 + threadIdx.x;
    if (i < O*K) {
        int o = i / K, k = i % K;
        float f = w[i];
        __nv_bfloat16 h = __float2bfloat16(f);
        th[(size_t)k*O + o] = h;
        tl[(size_t)k*O + o] = __float2bfloat16(f - __bfloat162float(h));
    }
}

// ======================= kernel 1: squeeze-excite gate =======================
__global__ __launch_bounds__(256) void se_kernel(
    const float* __restrict__ x,
    const float* __restrict__ fc1_w, const float* __restrict__ fc1_b,
    const float* __restrict__ fc2_w, const float* __restrict__ fc2_b)
{
    __shared__ float mean[Cn];
    __shared__ float s1[CRn];
    int b = blockIdx.x;
    int tid = threadIdx.x, warp = tid >> 5, lane = tid & 31;

    const float4* xb = (const float4*)(x + (size_t)b*Cn*HWn);
    for (int c = warp; c < Cn; c += 8) {
        const float4* row = xb + (size_t)c*(HWn/4);
        float sum = 0.f;
        #pragma unroll
        for (int j = 0; j < HWn/4/32; j++) {
            float4 v = row[lane + 32*j];
            sum += v.x + v.y + v.z + v.w;
        }
        #pragma unroll
        for (int o = 16; o > 0; o >>= 1) sum += __shfl_xor_sync(0xffffffffu, sum, o);
        if (lane == 0) mean[c] = sum * (1.0f/HWn);
    }
    __syncthreads();

    if (tid < CRn) {
        float acc = fc1_b[tid];
        const float* wr = fc1_w + tid*Cn;
        #pragma unroll 8
        for (int c = 0; c < Cn; c++) acc += wr[c]*mean[c];
        s1[tid] = fmaxf(acc, 0.f);
    }
    __syncthreads();
    {
        float acc = fc2_b[tid];
        const float* wr = fc2_w + tid*CRn;
        #pragma unroll 8
        for (int j = 0; j < CRn; j++) acc += wr[j]*s1[j];
        g_s[b*Cn + tid] = 1.f/(1.f + __expf(-acc));
    }
}

// ======================= kernel 2: qkv projection (split output) =======================
// grid 128 blocks (128 pixels each), warps 0-3: q+k, warps 4-7: v.
__global__ __launch_bounds__(256) void qkv_kernel(
    const float* __restrict__ x,
    const float* __restrict__ qkv_w, const float* __restrict__ qkv_b)
{
    __shared__ float ws[SCn][64];
    __shared__ float bias[64];
    __shared__ float sg[SCn];

    int blk = blockIdx.x;
    int b = blk >> 3;
    int tid = threadIdx.x, lane = tid & 31, wid = tid >> 5;
    int grp = wid >> 2, wl = wid & 3;
    int m = (blk & 7)*128 + wl*32 + lane;
    size_t pixg = (size_t)b*HWn + m;

    for (int i = tid; i < 64*SCn; i += 256) { int o = i >> 5, c = i & 31; ws[c][o] = qkv_w[i]; }
    if (tid < 64)  bias[tid] = qkv_b[tid];
    if (tid < SCn) sg[tid]   = g_s[b*Cn + tid];
    __syncthreads();

    float acc[32];
    #pragma unroll
    for (int o = 0; o < 32; o++) acc[o] = bias[grp*32 + o];

    const float* xb = x + (size_t)b*Cn*HWn + m;
    #pragma unroll 4
    for (int c = 0; c < SCn; c++) {
        float xv = xb[(size_t)c*HWn] * sg[c];
        #pragma unroll
        for (int o = 0; o < 32; o++) acc[o] += ws[c][grp*32 + o] * xv;
    }

    __align__(16) uint32_t hw[16], lw[16];
    if (grp == 0) {
        // q (scaled by AD^-0.5 = 0.25) then k
        #pragma unroll
        for (int i = 0; i < 8; i++) split2(acc[2*i]*0.25f, acc[2*i+1]*0.25f, hw[i], lw[i]);
        #pragma unroll
        for (int i = 8; i < 16; i++) split2(acc[2*i], acc[2*i+1], hw[i], lw[i]);
        *(uint4*)(g_qh + pixg*ADn)     = *(uint4*)&hw[0];
        *(uint4*)(g_qh + pixg*ADn + 8) = *(uint4*)&hw[4];
        *(uint4*)(g_ql + pixg*ADn)     = *(uint4*)&lw[0];
        *(uint4*)(g_ql + pixg*ADn + 8) = *(uint4*)&lw[4];
        *(uint4*)(g_kh + pixg*ADn)     = *(uint4*)&hw[8];
        *(uint4*)(g_kh + pixg*ADn + 8) = *(uint4*)&hw[12];
        *(uint4*)(g_kl + pixg*ADn)     = *(uint4*)&lw[8];
        *(uint4*)(g_kl + pixg*ADn + 8) = *(uint4*)&lw[12];
    } else {
        #pragma unroll
        for (int i = 0; i < 16; i++) split2(acc[2*i], acc[2*i+1], hw[i], lw[i]);
        #pragma unroll
        for (int q = 0; q < 4; q++) {
            *(uint4*)(g_vh + pixg*SCn + q*8) = *(uint4*)&hw[4*q];
            *(uint4*)(g_vl + pixg*SCn + q*8) = *(uint4*)&lw[4*q];
        }
    }
}

// ======================= kernel 3: gated non-attn channels -> yh/yl =======================
__global__ __launch_bounds__(256) void gate_y_kernel(const float* __restrict__ x)
{
    __shared__ float t[32][257];
    int b  = blockIdx.z;
    int c0 = SCn + blockIdx.y*32;
    int n0 = blockIdx.x*256;
    int tid = threadIdx.x;

    for (int i = tid; i < 32*256; i += 256) {
        int r = i >> 8, n = i & 255;
        t[r][n] = x[((size_t)b*Cn + (c0 + r))*HWn + n0 + n];
    }
    __syncthreads();

    int w = tid >> 5, l = tid & 31;
    float s = g_s[b*Cn + c0 + l];
    #pragma unroll 4
    for (int it = 0; it < 32; it++) {
        int n = w*32 + it;
        float v = t[l][n] * s;
        size_t p = (size_t)b*HWn + n0 + n;
        __nv_bfloat16 h = __float2bfloat16(v);
        g_yh[p*Cn + c0 + l] = h;
        g_yl[p*Cn + c0 + l] = __float2bfloat16(v - __bfloat162float(h));
    }
}

// ======================= kernel 4: flash attention on mma.sync =======================
// grid (8 tiles, 16 batches), 256 threads (8 warps x 16 query rows).
// smem element offsets (bf16 units)
#define ATT_QH  0
#define ATT_QL  3072
#define ATT_KH  6144
#define ATT_KL  9216
#define ATT_VH  12288
#define ATT_VL  17408
#define ATT_PWH 22528
#define ATT_PWL 23808
#define ATT_SMEM_BYTES (25088*2)   // 50176

__global__ __launch_bounds__(256) void attn_mma_kernel(
    const float* __restrict__ proj_w, const float* __restrict__ proj_b)
{
    extern __shared__ __nv_bfloat16 smb[];
    const uint32_t sb = smem_to_u32(smb);
    const int tid = threadIdx.x, lane = tid & 31, wid = tid >> 5;
    const int tile = blockIdx.x, b = blockIdx.y;
    const int m0 = tile*128;
    const size_t pixbase = (size_t)b*HWn + m0;

    // ---- stage Q (hi/lo) + proj weights ----
    {
        int row = tid >> 1, half = tid & 1;
        *(uint4*)(smb + ATT_QH + row*24 + half*8) = *(const uint4*)(g_qh + (pixbase + row)*ADn + half*8);
        *(uint4*)(smb + ATT_QL + row*24 + half*8) = *(const uint4*)(g_ql + (pixbase + row)*ADn + half*8);
    }
    for (int i = tid; i < SCn*SCn; i += 256) {
        int o = i >> 5, c = i & 31;
        float f = proj_w[i];
        __nv_bfloat16 h = __float2bfloat16(f);
        smb[ATT_PWH + o*40 + c] = h;
        smb[ATT_PWL + o*40 + c] = __float2bfloat16(f - __bfloat162float(h));
    }
    __syncthreads();

    uint32_t aqh[4], aql[4];
    ldsm_x4(aqh, sb + (ATT_QH + (wid*16 + (lane & 15))*24 + (lane >> 4)*8)*2);
    ldsm_x4(aql, sb + (ATT_QL + (wid*16 + (lane & 15))*24 + (lane >> 4)*8)*2);

    float o_acc[4][4];
    #pragma unroll
    for (int nt = 0; nt < 4; nt++)
        #pragma unroll
        for (int i = 0; i < 4; i++) o_acc[nt][i] = 0.f;
    float mA = -1e30f, mB = -1e30f, lA = 0.f, lB = 0.f;

    for (int kc = 0; kc < 8; kc++) {
        // ---- stage K/V chunk ----
        {
            size_t kb = (size_t)b*HWn + kc*128;
            int row = tid >> 1, half = tid & 1;
            *(uint4*)(smb + ATT_KH + row*24 + half*8) = *(const uint4*)(g_kh + (kb + row)*ADn + half*8);
            *(uint4*)(smb + ATT_KL + row*24 + half*8) = *(const uint4*)(g_kl + (kb + row)*ADn + half*8);
            #pragma unroll
            for (int q = 0; q < 2; q++) {
                int idx = tid + q*256;
                int vr = idx >> 2, part = idx & 3;
                *(uint4*)(smb + ATT_VH + vr*40 + part*8) = *(const uint4*)(g_vh + (kb + vr)*SCn + part*8);
                *(uint4*)(smb + ATT_VL + vr*40 + part*8) = *(const uint4*)(g_vl + (kb + vr)*SCn + part*8);
            }
        }
        __syncthreads();

        // ---- scores S = QK^T (3-term split), 16 n-tiles ----
        float s[16][4];
        #pragma unroll
        for (int t = 0; t < 16; t++)
            #pragma unroll
            for (int i = 0; i < 4; i++) s[t][i] = 0.f;

        #pragma unroll
        for (int pr = 0; pr < 8; pr++) {
            uint32_t bh4[4], bl4[4];
            ldsm_x4(bh4, sb + (ATT_KH + (pr*16 + (lane & 15))*24 + (lane >> 4)*8)*2);
            ldsm_x4(bl4, sb + (ATT_KL + (pr*16 + (lane & 15))*24 + (lane >> 4)*8)*2);
            uint32_t b0h[2] = {bh4[0], bh4[2]}, b1h[2] = {bh4[1], bh4[3]};
            uint32_t b0l[2] = {bl4[0], bl4[2]}, b1l[2] = {bl4[1], bl4[3]};
            mma_bf16(s[2*pr],   aqh, b0h);
            mma_bf16(s[2*pr],   aqh, b0l);
            mma_bf16(s[2*pr],   aql, b0h);
            mma_bf16(s[2*pr+1], aqh, b1h);
            mma_bf16(s[2*pr+1], aqh, b1l);
            mma_bf16(s[2*pr+1], aql, b1h);
        }

        // ---- online softmax (rows: A = lane/4, B = lane/4+8) ----
        float cmA = -1e30f, cmB = -1e30f;
        #pragma unroll
        for (int t = 0; t < 16; t++) {
            cmA = fmaxf(cmA, fmaxf(s[t][0], s[t][1]));
            cmB = fmaxf(cmB, fmaxf(s[t][2], s[t][3]));
        }
        #pragma unroll
        for (int off = 1; off < 4; off <<= 1) {
            cmA = fmaxf(cmA, __shfl_xor_sync(0xffffffffu, cmA, off));
            cmB = fmaxf(cmB, __shfl_xor_sync(0xffffffffu, cmB, off));
        }
        float nmA = fmaxf(mA, cmA), nmB = fmaxf(mB, cmB);
        float alA = __expf(mA - nmA), alB = __expf(mB - nmB);
        mA = nmA; mB = nmB;
        float sumA = 0.f, sumB = 0.f;
        #pragma unroll
        for (int t = 0; t < 16; t++) {
            s[t][0] = __expf(s[t][0] - mA);
            s[t][1] = __expf(s[t][1] - mA);
            s[t][2] = __expf(s[t][2] - mB);
            s[t][3] = __expf(s[t][3] - mB);
            sumA += s[t][0] + s[t][1];
            sumB += s[t][2] + s[t][3];
        }
        #pragma unroll
        for (int off = 1; off < 4; off <<= 1) {
            sumA += __shfl_xor_sync(0xffffffffu, sumA, off);
            sumB += __shfl_xor_sync(0xffffffffu, sumB, off);
        }
        lA = lA*alA + sumA;
        lB = lB*alB + sumB;
        #pragma unroll
        for (int nt = 0; nt < 4; nt++) {
            o_acc[nt][0] *= alA; o_acc[nt][1] *= alA;
            o_acc[nt][2] *= alB; o_acc[nt][3] *= alB;
        }

        // ---- O += P @ V (3-term split) ----
        #pragma unroll
        for (int j = 0; j < 8; j++) {
            uint32_t aph[4], apl[4];
            split2(s[2*j][0],   s[2*j][1],   aph[0], apl[0]);
            split2(s[2*j][2],   s[2*j][3],   aph[1], apl[1]);
            split2(s[2*j+1][0], s[2*j+1][1], aph[2], apl[2]);
            split2(s[2*j+1][2], s[2*j+1][3], aph[3], apl[3]);
            #pragma unroll
            for (int cb = 0; cb < 2; cb++) {
                uint32_t rh[4], rl[4];
                ldsm_x4_t(rh, sb + (ATT_VH + (j*16 + (lane & 15))*40 + cb*16 + (lane >> 4)*8)*2);
                ldsm_x4_t(rl, sb + (ATT_VL + (j*16 + (lane & 15))*40 + cb*16 + (lane >> 4)*8)*2);
                uint32_t b0h[2] = {rh[0], rh[1]}, b1h[2] = {rh[2], rh[3]};
                uint32_t b0l[2] = {rl[0], rl[1]}, b1l[2] = {rl[2], rl[3]};
                mma_bf16(o_acc[cb*2],   aph, b0h);
                mma_bf16(o_acc[cb*2],   aph, b0l);
                mma_bf16(o_acc[cb*2],   apl, b0h);
                mma_bf16(o_acc[cb*2+1], aph, b1h);
                mma_bf16(o_acc[cb*2+1], aph, b1l);
                mma_bf16(o_acc[cb*2+1], apl, b1h);
            }
        }
        __syncthreads();
    }

    // ---- normalize ----
    float invA = 1.f/lA, invB = 1.f/lB;
    #pragma unroll
    for (int nt = 0; nt < 4; nt++) {
        o_acc[nt][0] *= invA; o_acc[nt][1] *= invA;
        o_acc[nt][2] *= invB; o_acc[nt][3] *= invB;
    }

    // ---- proj (32x32) via mma, 3-term split ----
    float r[4][4];
    #pragma unroll
    for (int nt = 0; nt < 4; nt++)
        #pragma unroll
        for (int i = 0; i < 4; i++) r[nt][i] = 0.f;

    #pragma unroll
    for (int j = 0; j < 2; j++) {
        uint32_t aoh[4], aol[4];
        split2(o_acc[2*j][0],   o_acc[2*j][1],   aoh[0], aol[0]);
        split2(o_acc[2*j][2],   o_acc[2*j][3],   aoh[1], aol[1]);
        split2(o_acc[2*j+1][0], o_acc[2*j+1][1], aoh[2], aol[2]);
        split2(o_acc[2*j+1][2], o_acc[2*j+1][3], aoh[3], aol[3]);
        #pragma unroll
        for (int pr = 0; pr < 2; pr++) {
            uint32_t rh4[4], rl4[4];
            ldsm_x4(rh4, sb + (ATT_PWH + (pr*16 + (lane & 15))*40 + j*16 + (lane >> 4)*8)*2);
            ldsm_x4(rl4, sb + (ATT_PWL + (pr*16 + (lane & 15))*40 + j*16 + (lane >> 4)*8)*2);
            uint32_t b0h[2] = {rh4[0], rh4[2]}, b1h[2] = {rh4[1], rh4[3]};
            uint32_t b0l[2] = {rl4[0], rl4[2]}, b1l[2] = {rl4[1], rl4[3]};
            mma_bf16(r[pr*2],   aoh, b0h);
            mma_bf16(r[pr*2],   aoh, b0l);
            mma_bf16(r[pr*2],   aol, b0h);
            mma_bf16(r[pr*2+1], aoh, b1h);
            mma_bf16(r[pr*2+1], aoh, b1l);
            mma_bf16(r[pr*2+1], aol, b1h);
        }
    }

    // ---- store to yh/yl (attn channels 0-31) ----
    {
        size_t pA = pixbase + wid*16 + (lane >> 2);
        size_t pB = pA + 8;
        #pragma unroll
        for (int nt = 0; nt < 4; nt++) {
            int col = nt*8 + (lane & 3)*2;
            float b0 = proj_b[col], b1 = proj_b[col+1];
            uint32_t hw, lw;
            split2(r[nt][0] + b0, r[nt][1] + b1, hw, lw);
            *(uint32_t*)(g_yh + pA*Cn + col) = hw;
            *(uint32_t*)(g_yl + pA*Cn + col) = lw;
            split2(r[nt][2] + b0, r[nt][3] + b1, hw, lw);
            *(uint32_t*)(g_yh + pB*Cn + col) = hw;
            *(uint32_t*)(g_yl + pB*Cn + col) = lw;
        }
    }
}

// ======================= kernels 5/6: mma.sync bf16-split GEMM =======================
#define KCh 32
#define A_STRIDE 40
#define W_STRIDE 136
#define OFF_AH 0
#define OFF_AL (128*A_STRIDE*2)
#define OFF_WH (2*128*A_STRIDE*2)
#define OFF_WL (2*128*A_STRIDE*2 + KCh*W_STRIDE*2)
#define STAGE_BYTES (2*128*A_STRIDE*2 + 2*KCh*W_STRIDE*2)
#define GEMM_SMEM (2*STAGE_BYTES)

template<int NTOT, int KTOT, int MODE>
__global__ __launch_bounds__(256)
void mma_gemm_kernel(const __nv_bfloat16* __restrict__ Ah_g, const __nv_bfloat16* __restrict__ Al_g,
                     const __nv_bfloat16* __restrict__ Wh_g, const __nv_bfloat16* __restrict__ Wl_g,
                     const float* __restrict__ bias,
                     __nv_bfloat16* __restrict__ Hh, __nv_bfloat16* __restrict__ Hl,
                     float* __restrict__ Out)
{
    extern __shared__ char smraw[];
    const uint32_t smem_base = smem_to_u32(smraw);

    const int tid = threadIdx.x;
    const int lane = tid & 31, wid = tid >> 5;
    const int warp_m = wid & 3;
    const int warp_n = wid >> 2;
    const int m0 = blockIdx.y*128, n0 = blockIdx.x*128;
    constexpr int NC = KTOT / KCh;

    float acc[2][8][4];
    #pragma unroll
    for (int mt = 0; mt < 2; mt++)
        #pragma unroll
        for (int nt = 0; nt < 8; nt++)
            #pragma unroll
            for (int i = 0; i < 4; i++) acc[mt][nt][i] = 0.f;

    uint4 ra_h[2], ra_l[2], rw_h[2], rw_l[2];
    const int a_row = tid >> 2, a_part = (tid & 3);
    const int w_row = tid >> 4, w_part = (tid & 15);

    auto LOAD = [&](int kc) {
        const __nv_bfloat16* ah = Ah_g + (size_t)(m0)*KTOT + kc*KCh;
        const __nv_bfloat16* al = Al_g + (size_t)(m0)*KTOT + kc*KCh;
        #pragma unroll
        for (int q = 0; q < 2; q++) {
            int row = a_row + q*64;
            ra_h[q] = *(const uint4*)(ah + (size_t)row*KTOT + a_part*8);
            ra_l[q] = *(const uint4*)(al + (size_t)row*KTOT + a_part*8);
        }
        const __nv_bfloat16* wh = Wh_g + (size_t)(kc*KCh)*NTOT + n0;
        const __nv_bfloat16* wl = Wl_g + (size_t)(kc*KCh)*NTOT + n0;
        #pragma unroll
        for (int q = 0; q < 2; q++) {
            int row = w_row + q*16;
            rw_h[q] = *(const uint4*)(wh + (size_t)row*NTOT + w_part*8);
            rw_l[q] = *(const uint4*)(wl + (size_t)row*NTOT + w_part*8);
        }
    };
    auto STORE = [&](int buf) {
        char* s = smraw + buf*STAGE_BYTES;
        #pragma unroll
        for (int q = 0; q < 2; q++) {
            int row = a_row + q*64;
            *(uint4*)(s + OFF_AH + (row*A_STRIDE + a_part*8)*2) = ra_h[q];
            *(uint4*)(s + OFF_AL + (row*A_STRIDE + a_part*8)*2) = ra_l[q];
            int wrow = w_row + q*16;
            *(uint4*)(s + OFF_WH + (wrow*W_STRIDE + w_part*8)*2) = rw_h[q];
            *(uint4*)(s + OFF_WL + (wrow*W_STRIDE + w_part*8)*2) = rw_l[q];
        }
    };
    auto COMPUTE = [&](int buf) {
        uint32_t sbx = smem_base + buf*STAGE_BYTES;
        #pragma unroll
        for (int ks = 0; ks < 2; ks++) {
            int k0 = ks*16;
            uint32_t ah[2][4], al[2][4];
            #pragma unroll
            for (int mt = 0; mt < 2; mt++) {
                uint32_t off = ((warp_m*32 + mt*16 + (lane & 15))*A_STRIDE + k0 + ((lane >> 4) << 3))*2;
                ldsm_x4(ah[mt], sbx + OFF_AH + off);
                ldsm_x4(al[mt], sbx + OFF_AL + off);
            }
            uint32_t bh[8][2], bl[8][2];
            #pragma unroll
            for (int np = 0; np < 4; np++) {
                uint32_t off = ((k0 + (lane & 15))*W_STRIDE + warp_n*64 + np*16 + ((lane >> 4) << 3))*2;
                uint32_t rr[4];
                ldsm_x4_t(rr, sbx + OFF_WH + off);
                bh[2*np][0] = rr[0]; bh[2*np][1] = rr[1];
                bh[2*np+1][0] = rr[2]; bh[2*np+1][1] = rr[3];
                ldsm_x4_t(rr, sbx + OFF_WL + off);
                bl[2*np][0] = rr[0]; bl[2*np][1] = rr[1];
                bl[2*np+1][0] = rr[2]; bl[2*np+1][1] = rr[3];
            }
            #pragma unroll
            for (int mt = 0; mt < 2; mt++)
                #pragma unroll
                for (int nt = 0; nt < 8; nt++) {
                    mma_bf16(acc[mt][nt], ah[mt], bh[nt]);
                    mma_bf16(acc[mt][nt], ah[mt], bl[nt]);
                    mma_bf16(acc[mt][nt], al[mt], bh[nt]);
                }
        }
    };

    LOAD(0); STORE(0);
    __syncthreads();
    for (int kc = 0; kc < NC; kc++) {
        if (kc + 1 < NC) LOAD(kc + 1);
        COMPUTE(kc & 1);
        if (kc + 1 < NC) STORE((kc + 1) & 1);
        __syncthreads();
    }

    if (MODE == 1) {
        #pragma unroll
        for (int mt = 0; mt < 2; mt++)
            #pragma unroll
            for (int half = 0; half < 2; half++) {
                int row = m0 + warp_m*32 + mt*16 + (lane >> 2) + half*8;
                #pragma unroll
                for (int nt = 0; nt < 8; nt++) {
                    int col = n0 + warp_n*64 + nt*8 + (lane & 3)*2;
                    float f0 = acc[mt][nt][half*2+0] + bias[col];
                    float f1 = acc[mt][nt][half*2+1] + bias[col+1];
                    f0 = fmaxf(f0, 0.f); f1 = fmaxf(f1, 0.f);
                    uint32_t ph, pl;
                    split2(f0, f1, ph, pl);
                    *(uint32_t*)(Hh + (size_t)row*NTOT + col) = ph;
                    *(uint32_t*)(Hl + (size_t)row*NTOT + col) = pl;
                }
            }
    } else {
        float* Ct = (float*)smraw;
        #pragma unroll
        for (int mt = 0; mt < 2; mt++)
            #pragma unroll
            for (int half = 0; half < 2; half++) {
                int rl = warp_m*32 + mt*16 + (lane >> 2) + half*8;
                #pragma unroll
                for (int nt = 0; nt < 8; nt++) {
                    int cl = warp_n*64 + nt*8 + (lane & 3)*2;
                    Ct[rl*129 + cl]     = acc[mt][nt][half*2+0];
                    Ct[rl*129 + cl + 1] = acc[mt][nt][half*2+1];
                }
            }
        __syncthreads();
        int bb = m0 >> 10, nn0 = m0 & (HWn-1);
        #pragma unroll
        for (int cc = 0; cc < 16; cc++) {
            int col = wid*16 + cc;
            int co = n0 + col;
            float bi = bias[co];
            float* ob = Out + (size_t)bb*Cn*HWn + (size_t)co*HWn + nn0;
            #pragma unroll
            for (int j = 0; j < 4; j++) {
                int rr = lane + 32*j;
                ob[rr] = Ct[rr*129 + col] + bi;
            }
        }
    }
}

// ======================= launch =======================
extern "C" void kernel_launch(void* const* d_in, const int* in_sizes, int n_in,
                              void* d_out, int out_size)
{
    const float* x      = (const float*)d_in[0];
    const float* fc1_w  = (const float*)d_in[1];
    const float* fc1_b  = (const float*)d_in[2];
    const float* fc2_w  = (const float*)d_in[3];
    const float* fc2_b  = (const float*)d_in[4];
    const float* qkv_w  = (const float*)d_in[5];
    const float* qkv_b  = (const float*)d_in[6];
    const float* proj_w = (const float*)d_in[7];
    const float* proj_b = (const float*)d_in[8];
    const float* ffn1_w = (const float*)d_in[9];
    const float* ffn1_b = (const float*)d_in[10];
    const float* ffn2_w = (const float*)d_in[11];
    const float* ffn2_b = (const float*)d_in[12];
    float* out = (float*)d_out;

    cudaFuncSetAttribute(attn_mma_kernel, cudaFuncAttributeMaxDynamicSharedMemorySize, ATT_SMEM_BYTES);
    cudaFuncSetAttribute((const void*)mma_gemm_kernel<C4n, Cn, 1>, cudaFuncAttributeMaxDynamicSharedMemorySize, GEMM_SMEM);
    cudaFuncSetAttribute((const void*)mma_gemm_kernel<Cn, C4n, 2>, cudaFuncAttributeMaxDynamicSharedMemorySize, GEMM_SMEM);

    __nv_bfloat16 *yh, *yl, *hh, *hl, *w1h, *w1l, *w2h, *w2l;
    cudaGetSymbolAddress((void**)&yh,  g_yh);
    cudaGetSymbolAddress((void**)&yl,  g_yl);
    cudaGetSymbolAddress((void**)&hh,  g_hh);
    cudaGetSymbolAddress((void**)&hl,  g_hl);
    cudaGetSymbolAddress((void**)&w1h, g_w1h);
    cudaGetSymbolAddress((void**)&w1l, g_w1l);
    cudaGetSymbolAddress((void**)&w2h, g_w2h);
    cudaGetSymbolAddress((void**)&w2l, g_w2l);

    convertw_T<<<(C4n*Cn)/256, 256>>>(ffn1_w, w1h, w1l, C4n, Cn);
    convertw_T<<<(Cn*C4n)/256, 256>>>(ffn2_w, w2h, w2l, Cn, C4n);

    se_kernel<<<Bn, 256>>>(x, fc1_w, fc1_b, fc2_w, fc2_b);
    qkv_kernel<<<128, 256>>>(x, qkv_w, qkv_b);
    gate_y_kernel<<<dim3(4, 7, Bn), 256>>>(x);
    attn_mma_kernel<<<dim3(8, Bn), 256, ATT_SMEM_BYTES>>>(proj_w, proj_b);

    mma_gemm_kernel<C4n, Cn, 1><<<dim3(C4n/128, NPIX/128), 256, GEMM_SMEM>>>(
        yh, yl, w1h, w1l, ffn1_b, hh, hl, nullptr);
    mma_gemm_kernel<Cn, C4n, 2><<<dim3(Cn/128, NPIX/128), 256, GEMM_SMEM>>>(
        hh, hl, w2h, w2l, ffn2_b, nullptr, nullptr, out);
}

// round 6
// speedup vs baseline: 3.3646x; 1.4733x over previous
#include <cuda_runtime.h>
#include <cuda_fp16.h>
#include <cstdint>
#include <math.h>

#define Bn   16
#define Cn   256
#define HWn  1024
#define ADn  16
#define SCn  32
#define CRn  64
#define C4n  1024
#define NPIX (Bn*HWn)   // 16384

// ======================= device scratch =======================
__device__ float g_s[Bn*Cn];
// q/k fp16 hi/lo split [b][m][16]; v fp16 single [b][m][32]
__device__ __align__(256) __half g_qh[Bn*HWn*ADn];
__device__ __align__(256) __half g_ql[Bn*HWn*ADn];
__device__ __align__(256) __half g_kh[Bn*HWn*ADn];
__device__ __align__(256) __half g_kl[Bn*HWn*ADn];
__device__ __align__(256) __half g_v [Bn*HWn*SCn];
// FFN activations, fp16 single, pixel-major
__device__ __align__(256) __half g_y[NPIX*Cn];
__device__ __align__(256) __half g_h[NPIX*C4n];
// weights transposed to [K][N], fp16 hi/lo (exact split)
__device__ __align__(256) __half g_w1h[Cn*C4n];
__device__ __align__(256) __half g_w1l[Cn*C4n];
__device__ __align__(256) __half g_w2h[C4n*Cn];
__device__ __align__(256) __half g_w2l[C4n*Cn];

// ======================= PTX helpers =======================
__device__ __forceinline__ uint32_t smem_to_u32(const void* p) {
    uint32_t a;
    asm("{ .reg .u64 t; cvta.to.shared.u64 t, %1; cvt.u32.u64 %0, t; }" : "=r"(a) : "l"(p));
    return a;
}
__device__ __forceinline__ void ldsm_x4(uint32_t r[4], uint32_t addr) {
    asm volatile("ldmatrix.sync.aligned.m8n8.x4.shared.b16 {%0,%1,%2,%3}, [%4];"
        : "=r"(r[0]), "=r"(r[1]), "=r"(r[2]), "=r"(r[3]) : "r"(addr));
}
__device__ __forceinline__ void ldsm_x4_t(uint32_t r[4], uint32_t addr) {
    asm volatile("ldmatrix.sync.aligned.m8n8.x4.trans.shared.b16 {%0,%1,%2,%3}, [%4];"
        : "=r"(r[0]), "=r"(r[1]), "=r"(r[2]), "=r"(r[3]) : "r"(addr));
}
__device__ __forceinline__ void mma_f16(float c[4], const uint32_t a[4], const uint32_t b[2]) {
    asm volatile("mma.sync.aligned.m16n8k16.row.col.f32.f16.f16.f32 "
        "{%0,%1,%2,%3}, {%4,%5,%6,%7}, {%8,%9}, {%0,%1,%2,%3};"
        : "+f"(c[0]), "+f"(c[1]), "+f"(c[2]), "+f"(c[3])
        : "r"(a[0]), "r"(a[1]), "r"(a[2]), "r"(a[3]), "r"(b[0]), "r"(b[1]));
}
#define CP_ASYNC16(dst, src) \
    asm volatile("cp.async.cg.shared.global [%0], [%1], 16;" :: "r"(dst), "l"(src))
#define CP_COMMIT() asm volatile("cp.async.commit_group;")
#define CP_WAIT(n)  asm volatile("cp.async.wait_group %0;" :: "n"(n))

__device__ __forceinline__ uint32_t pack2h(float f0, float f1) {
    __half2 h = __floats2half2_rn(f0, f1);
    return *(uint32_t*)&h;
}
__device__ __forceinline__ void split2h(float f0, float f1, uint32_t& hw, uint32_t& lw) {
    __half h0 = __float2half_rn(f0), h1 = __float2half_rn(f1);
    float r0 = f0 - __half2float(h0), r1 = f1 - __half2float(h1);
    hw = pack2h(__half2float(h0), __half2float(h1));
    lw = pack2h(r0, r1);
}

// ======================= weight split + transpose =======================
// w: [O][K] fp32 -> th/tl: [K][O] fp16 hi/lo
__global__ __launch_bounds__(256) void convertw_T(
    const float* __restrict__ w, __half* __restrict__ th, __half* __restrict__ tl,
    int O, int K)
{
    int i = blockIdx.x*256 + threadIdx.x;
    if (i < O*K) {
        int o = i / K, k = i % K;
        float f = w[i];
        __half h = __float2half_rn(f);
        th[(size_t)k*O + o] = h;
        tl[(size_t)k*O + o] = __float2half_rn(f - __half2float(h));
    }
}

// ======================= kernel 1: squeeze-excite gate =======================
__global__ __launch_bounds__(256) void se_kernel(
    const float* __restrict__ x,
    const float* __restrict__ fc1_w, const float* __restrict__ fc1_b,
    const float* __restrict__ fc2_w, const float* __restrict__ fc2_b)
{
    __shared__ float mean[Cn];
    __shared__ float s1[CRn];
    int b = blockIdx.x;
    int tid = threadIdx.x, warp = tid >> 5, lane = tid & 31;

    const float4* xb = (const float4*)(x + (size_t)b*Cn*HWn);
    for (int c = warp; c < Cn; c += 8) {
        const float4* row = xb + (size_t)c*(HWn/4);
        float sum = 0.f;
        #pragma unroll
        for (int j = 0; j < HWn/4/32; j++) {
            float4 v = row[lane + 32*j];
            sum += v.x + v.y + v.z + v.w;
        }
        #pragma unroll
        for (int o = 16; o > 0; o >>= 1) sum += __shfl_xor_sync(0xffffffffu, sum, o);
        if (lane == 0) mean[c] = sum * (1.0f/HWn);
    }
    __syncthreads();

    if (tid < CRn) {
        float acc = fc1_b[tid];
        const float* wr = fc1_w + tid*Cn;
        #pragma unroll 8
        for (int c = 0; c < Cn; c++) acc += wr[c]*mean[c];
        s1[tid] = fmaxf(acc, 0.f);
    }
    __syncthreads();
    {
        float acc = fc2_b[tid];
        const float* wr = fc2_w + tid*CRn;
        #pragma unroll 8
        for (int j = 0; j < CRn; j++) acc += wr[j]*s1[j];
        g_s[b*Cn + tid] = 1.f/(1.f + __expf(-acc));
    }
}

// ======================= kernel 2: qkv projection =======================
// grid 128 blocks (128 pixels each), 512 threads, 4 groups of 16 outputs.
__global__ __launch_bounds__(512) void qkv_kernel(
    const float* __restrict__ x,
    const float* __restrict__ qkv_w, const float* __restrict__ qkv_b)
{
    __shared__ float ws[SCn][64];
    __shared__ float bias[64];
    __shared__ float sg[SCn];

    int blk = blockIdx.x;
    int b = blk >> 3;
    int tid = threadIdx.x, lane = tid & 31, wid = tid >> 5;
    int grp = wid >> 2, wl = wid & 3;     // grp 0:q 1:k 2:v-lo 3:v-hi
    int m = (blk & 7)*128 + wl*32 + lane;
    size_t pixg = (size_t)b*HWn + m;

    for (int i = tid; i < 64*SCn; i += 512) { int o = i >> 5, c = i & 31; ws[c][o] = qkv_w[i]; }
    if (tid < 64)  bias[tid] = qkv_b[tid];
    if (tid < SCn) sg[tid]   = g_s[b*Cn + tid];
    __syncthreads();

    float acc[16];
    #pragma unroll
    for (int o = 0; o < 16; o++) acc[o] = bias[grp*16 + o];

    const float* xb = x + (size_t)b*Cn*HWn + m;
    #pragma unroll 4
    for (int c = 0; c < SCn; c++) {
        float xv = xb[(size_t)c*HWn] * sg[c];
        #pragma unroll
        for (int o = 0; o < 16; o++) acc[o] += ws[c][grp*16 + o] * xv;
    }

    if (grp == 0) {
        __align__(16) uint32_t hw[8], lw[8];
        #pragma unroll
        for (int i = 0; i < 8; i++) split2h(acc[2*i]*0.25f, acc[2*i+1]*0.25f, hw[i], lw[i]);
        *(uint4*)(g_qh + pixg*ADn)     = *(uint4*)&hw[0];
        *(uint4*)(g_qh + pixg*ADn + 8) = *(uint4*)&hw[4];
        *(uint4*)(g_ql + pixg*ADn)     = *(uint4*)&lw[0];
        *(uint4*)(g_ql + pixg*ADn + 8) = *(uint4*)&lw[4];
    } else if (grp == 1) {
        __align__(16) uint32_t hw[8], lw[8];
        #pragma unroll
        for (int i = 0; i < 8; i++) split2h(acc[2*i], acc[2*i+1], hw[i], lw[i]);
        *(uint4*)(g_kh + pixg*ADn)     = *(uint4*)&hw[0];
        *(uint4*)(g_kh + pixg*ADn + 8) = *(uint4*)&hw[4];
        *(uint4*)(g_kl + pixg*ADn)     = *(uint4*)&lw[0];
        *(uint4*)(g_kl + pixg*ADn + 8) = *(uint4*)&lw[4];
    } else {
        __align__(16) uint32_t pv[8];
        #pragma unroll
        for (int i = 0; i < 8; i++) pv[i] = pack2h(acc[2*i], acc[2*i+1]);
        int off = (grp - 2)*16;
        *(uint4*)(g_v + pixg*SCn + off)     = *(uint4*)&pv[0];
        *(uint4*)(g_v + pixg*SCn + off + 8) = *(uint4*)&pv[4];
    }
}

// ======================= kernel 3: gated non-attn channels -> y =======================
__global__ __launch_bounds__(256) void gate_y_kernel(const float* __restrict__ x)
{
    __shared__ float t[32][257];
    int b  = blockIdx.z;
    int c0 = SCn + blockIdx.y*32;
    int n0 = blockIdx.x*256;
    int tid = threadIdx.x;

    for (int i = tid; i < 32*256; i += 256) {
        int r = i >> 8, n = i & 255;
        t[r][n] = x[((size_t)b*Cn + (c0 + r))*HWn + n0 + n];
    }
    __syncthreads();

    int w = tid >> 5, l = tid & 31;
    float s = g_s[b*Cn + c0 + l];
    #pragma unroll 4
    for (int it = 0; it < 32; it++) {
        int n = w*32 + it;
        size_t p = (size_t)b*HWn + n0 + n;
        g_y[p*Cn + c0 + l] = __float2half_rn(t[l][n] * s);
    }
}

// ======================= kernel 4: flash attention on mma.sync (fp16) ==============
// smem offsets in halfs
#define ATT_QH  0
#define ATT_QL  3072
#define ATT_KH  6144
#define ATT_KL  9216
#define ATT_V   12288
#define ATT_PWH 17408
#define ATT_PWL 18688
#define ATT_SMEM_BYTES (19968*2)

__global__ __launch_bounds__(256) void attn_mma_kernel(
    const float* __restrict__ proj_w, const float* __restrict__ proj_b)
{
    extern __shared__ __half smb[];
    const uint32_t sb = smem_to_u32(smb);
    const int tid = threadIdx.x, lane = tid & 31, wid = tid >> 5;
    const int tile = blockIdx.x, b = blockIdx.y;
    const int m0 = tile*128;
    const size_t pixbase = (size_t)b*HWn + m0;

    // stage Q hi/lo + proj weights
    {
        int row = tid >> 1, half = tid & 1;
        *(uint4*)(smb + ATT_QH + row*24 + half*8) = *(const uint4*)(g_qh + (pixbase + row)*ADn + half*8);
        *(uint4*)(smb + ATT_QL + row*24 + half*8) = *(const uint4*)(g_ql + (pixbase + row)*ADn + half*8);
    }
    for (int i = tid; i < SCn*SCn; i += 256) {
        int o = i >> 5, c = i & 31;
        float f = proj_w[i];
        __half h = __float2half_rn(f);
        smb[ATT_PWH + o*40 + c] = h;
        smb[ATT_PWL + o*40 + c] = __float2half_rn(f - __half2float(h));
    }
    __syncthreads();

    uint32_t aqh[4], aql[4];
    ldsm_x4(aqh, sb + (ATT_QH + (wid*16 + (lane & 15))*24 + (lane >> 4)*8)*2);
    ldsm_x4(aql, sb + (ATT_QL + (wid*16 + (lane & 15))*24 + (lane >> 4)*8)*2);

    float o_acc[4][4];
    #pragma unroll
    for (int nt = 0; nt < 4; nt++)
        #pragma unroll
        for (int i = 0; i < 4; i++) o_acc[nt][i] = 0.f;
    float mA = -1e30f, mB = -1e30f, lA = 0.f, lB = 0.f;

    for (int kc = 0; kc < 8; kc++) {
        { // stage K hi/lo + V single
            size_t kb = (size_t)b*HWn + kc*128;
            int row = tid >> 1, half = tid & 1;
            *(uint4*)(smb + ATT_KH + row*24 + half*8) = *(const uint4*)(g_kh + (kb + row)*ADn + half*8);
            *(uint4*)(smb + ATT_KL + row*24 + half*8) = *(const uint4*)(g_kl + (kb + row)*ADn + half*8);
            #pragma unroll
            for (int q = 0; q < 2; q++) {
                int idx = tid + q*256;
                int vr = idx >> 2, part = idx & 3;
                *(uint4*)(smb + ATT_V + vr*40 + part*8) = *(const uint4*)(g_v + (kb + vr)*SCn + part*8);
            }
        }
        __syncthreads();

        // S = QK^T, 3-term
        float s[16][4];
        #pragma unroll
        for (int t = 0; t < 16; t++)
            #pragma unroll
            for (int i = 0; i < 4; i++) s[t][i] = 0.f;

        #pragma unroll
        for (int pr = 0; pr < 8; pr++) {
            uint32_t bh4[4], bl4[4];
            ldsm_x4(bh4, sb + (ATT_KH + (pr*16 + (lane & 15))*24 + (lane >> 4)*8)*2);
            ldsm_x4(bl4, sb + (ATT_KL + (pr*16 + (lane & 15))*24 + (lane >> 4)*8)*2);
            uint32_t b0h[2] = {bh4[0], bh4[2]}, b1h[2] = {bh4[1], bh4[3]};
            uint32_t b0l[2] = {bl4[0], bl4[2]}, b1l[2] = {bl4[1], bl4[3]};
            mma_f16(s[2*pr],   aqh, b0h);
            mma_f16(s[2*pr],   aqh, b0l);
            mma_f16(s[2*pr],   aql, b0h);
            mma_f16(s[2*pr+1], aqh, b1h);
            mma_f16(s[2*pr+1], aqh, b1l);
            mma_f16(s[2*pr+1], aql, b1h);
        }

        // online softmax
        float cmA = -1e30f, cmB = -1e30f;
        #pragma unroll
        for (int t = 0; t < 16; t++) {
            cmA = fmaxf(cmA, fmaxf(s[t][0], s[t][1]));
            cmB = fmaxf(cmB, fmaxf(s[t][2], s[t][3]));
        }
        #pragma unroll
        for (int off = 1; off < 4; off <<= 1) {
            cmA = fmaxf(cmA, __shfl_xor_sync(0xffffffffu, cmA, off));
            cmB = fmaxf(cmB, __shfl_xor_sync(0xffffffffu, cmB, off));
        }
        float nmA = fmaxf(mA, cmA), nmB = fmaxf(mB, cmB);
        float alA = __expf(mA - nmA), alB = __expf(mB - nmB);
        mA = nmA; mB = nmB;
        float sumA = 0.f, sumB = 0.f;
        #pragma unroll
        for (int t = 0; t < 16; t++) {
            s[t][0] = __expf(s[t][0] - mA);
            s[t][1] = __expf(s[t][1] - mA);
            s[t][2] = __expf(s[t][2] - mB);
            s[t][3] = __expf(s[t][3] - mB);
            sumA += s[t][0] + s[t][1];
            sumB += s[t][2] + s[t][3];
        }
        #pragma unroll
        for (int off = 1; off < 4; off <<= 1) {
            sumA += __shfl_xor_sync(0xffffffffu, sumA, off);
            sumB += __shfl_xor_sync(0xffffffffu, sumB, off);
        }
        lA = lA*alA + sumA;
        lB = lB*alB + sumB;
        #pragma unroll
        for (int nt = 0; nt < 4; nt++) {
            o_acc[nt][0] *= alA; o_acc[nt][1] *= alA;
            o_acc[nt][2] *= alB; o_acc[nt][3] *= alB;
        }

        // O += P @ V (P exact split, V single -> 2 terms)
        #pragma unroll
        for (int j = 0; j < 8; j++) {
            uint32_t aph[4], apl[4];
            split2h(s[2*j][0],   s[2*j][1],   aph[0], apl[0]);
            split2h(s[2*j][2],   s[2*j][3],   aph[1], apl[1]);
            split2h(s[2*j+1][0], s[2*j+1][1], aph[2], apl[2]);
            split2h(s[2*j+1][2], s[2*j+1][3], aph[3], apl[3]);
            #pragma unroll
            for (int cb = 0; cb < 2; cb++) {
                uint32_t rv[4];
                ldsm_x4_t(rv, sb + (ATT_V + (j*16 + (lane & 15))*40 + cb*16 + (lane >> 4)*8)*2);
                uint32_t b0[2] = {rv[0], rv[1]}, b1[2] = {rv[2], rv[3]};
                mma_f16(o_acc[cb*2],   aph, b0);
                mma_f16(o_acc[cb*2],   apl, b0);
                mma_f16(o_acc[cb*2+1], aph, b1);
                mma_f16(o_acc[cb*2+1], apl, b1);
            }
        }
        __syncthreads();
    }

    float invA = 1.f/lA, invB = 1.f/lB;
    #pragma unroll
    for (int nt = 0; nt < 4; nt++) {
        o_acc[nt][0] *= invA; o_acc[nt][1] *= invA;
        o_acc[nt][2] *= invB; o_acc[nt][3] *= invB;
    }

    // proj (32x32): O exact split x PW hi/lo, 3-term
    float r[4][4];
    #pragma unroll
    for (int nt = 0; nt < 4; nt++)
        #pragma unroll
        for (int i = 0; i < 4; i++) r[nt][i] = 0.f;

    #pragma unroll
    for (int j = 0; j < 2; j++) {
        uint32_t aoh[4], aol[4];
        split2h(o_acc[2*j][0],   o_acc[2*j][1],   aoh[0], aol[0]);
        split2h(o_acc[2*j][2],   o_acc[2*j][3],   aoh[1], aol[1]);
        split2h(o_acc[2*j+1][0], o_acc[2*j+1][1], aoh[2], aol[2]);
        split2h(o_acc[2*j+1][2], o_acc[2*j+1][3], aoh[3], aol[3]);
        #pragma unroll
        for (int pr = 0; pr < 2; pr++) {
            uint32_t rh4[4], rl4[4];
            ldsm_x4(rh4, sb + (ATT_PWH + (pr*16 + (lane & 15))*40 + j*16 + (lane >> 4)*8)*2);
            ldsm_x4(rl4, sb + (ATT_PWL + (pr*16 + (lane & 15))*40 + j*16 + (lane >> 4)*8)*2);
            uint32_t b0h[2] = {rh4[0], rh4[2]}, b1h[2] = {rh4[1], rh4[3]};
            uint32_t b0l[2] = {rl4[0], rl4[2]}, b1l[2] = {rl4[1], rl4[3]};
            mma_f16(r[pr*2],   aoh, b0h);
            mma_f16(r[pr*2],   aoh, b0l);
            mma_f16(r[pr*2],   aol, b0h);
            mma_f16(r[pr*2+1], aoh, b1h);
            mma_f16(r[pr*2+1], aoh, b1l);
            mma_f16(r[pr*2+1], aol, b1h);
        }
    }

    {
        size_t pA = pixbase + wid*16 + (lane >> 2);
        size_t pB = pA + 8;
        #pragma unroll
        for (int nt = 0; nt < 4; nt++) {
            int col = nt*8 + (lane & 3)*2;
            float b0 = proj_b[col], b1 = proj_b[col+1];
            *(uint32_t*)(g_y + pA*Cn + col) = pack2h(r[nt][0] + b0, r[nt][1] + b1);
            *(uint32_t*)(g_y + pB*Cn + col) = pack2h(r[nt][2] + b0, r[nt][3] + b1);
        }
    }
}

// ======================= kernels 5/6: fp16 2-term GEMM, cp.async 3-stage ============
// D[128 pix, 128 ch] per block. A: [p][K] fp16 single. W: [K][N] fp16 hi/lo.
#define KCh 32
#define A_STRIDE 56      // halfs/row (32 data + 24 pad): 112B rows, 16B-aligned, ldsm conflict-free
#define W_STRIDE 136     // halfs/row (128 data + 8 pad): 272B rows
#define OFF_A  0
#define OFF_WH (128*A_STRIDE*2)                        // 14336
#define OFF_WL (128*A_STRIDE*2 + KCh*W_STRIDE*2)       // 23040
#define STAGE_BYTES (128*A_STRIDE*2 + 2*KCh*W_STRIDE*2) // 31744
#define NSTAGE 3
#define GEMM_SMEM (NSTAGE*STAGE_BYTES)                  // 95232

template<int NTOT, int KTOT, int MODE>
__global__ __launch_bounds__(256)
void mma_gemm_kernel(const __half* __restrict__ Ag, 
                     const __half* __restrict__ Wh_g, const __half* __restrict__ Wl_g,
                     const float* __restrict__ bias,
                     __half* __restrict__ H, float* __restrict__ Out)
{
    extern __shared__ char smraw[];
    const uint32_t smem_base = smem_to_u32(smraw);

    const int tid = threadIdx.x;
    const int lane = tid & 31, wid = tid >> 5;
    const int warp_m = wid & 3;
    const int warp_n = wid >> 2;
    const int m0 = blockIdx.y*128, n0 = blockIdx.x*128;
    constexpr int NC = KTOT / KCh;

    float acc[2][8][4];
    #pragma unroll
    for (int mt = 0; mt < 2; mt++)
        #pragma unroll
        for (int nt = 0; nt < 8; nt++)
            #pragma unroll
            for (int i = 0; i < 4; i++) acc[mt][nt][i] = 0.f;

    // cp.async issue: A 512 16B segs (2/thread), W 1024 segs (4/thread)
    auto ISSUE = [&](int kc, int buf) {
        uint32_t sbase = smem_base + buf*STAGE_BYTES;
        #pragma unroll
        for (int q = 0; q < 2; q++) {
            int idx = tid + q*256;
            int row = idx >> 2, seg = idx & 3;
            uint32_t dst = sbase + OFF_A + row*(A_STRIDE*2) + seg*16;
            const __half* src = Ag + (size_t)(m0 + row)*KTOT + kc*KCh + seg*8;
            CP_ASYNC16(dst, src);
        }
        #pragma unroll
        for (int q = 0; q < 4; q++) {
            int idx = tid + q*256;
            int arr = idx >> 9;          // 0: Wh, 1: Wl
            int rem = idx & 511;
            int row = rem >> 4, seg = rem & 15;
            uint32_t dst = sbase + OFF_WH + arr*(KCh*W_STRIDE*2) + row*(W_STRIDE*2) + seg*16;
            const __half* wsrc = (arr ? Wl_g : Wh_g) + (size_t)(kc*KCh + row)*NTOT + n0 + seg*8;
            CP_ASYNC16(dst, wsrc);
        }
    };

    auto COMPUTE = [&](int buf) {
        uint32_t sbx = smem_base + buf*STAGE_BYTES;
        #pragma unroll
        for (int ks = 0; ks < 2; ks++) {
            int k0 = ks*16;
            uint32_t a[2][4];
            #pragma unroll
            for (int mt = 0; mt < 2; mt++) {
                uint32_t off = ((warp_m*32 + mt*16 + (lane & 15))*A_STRIDE + k0 + ((lane >> 4) << 3))*2;
                ldsm_x4(a[mt], sbx + OFF_A + off);
            }
            #pragma unroll
            for (int np = 0; np < 4; np++) {
                uint32_t off = ((k0 + (lane & 15))*W_STRIDE + warp_n*64 + np*16 + ((lane >> 4) << 3))*2;
                uint32_t rh[4], rl[4];
                ldsm_x4_t(rh, sbx + OFF_WH + off);
                ldsm_x4_t(rl, sbx + OFF_WL + off);
                uint32_t b0h[2] = {rh[0], rh[1]}, b1h[2] = {rh[2], rh[3]};
                uint32_t b0l[2] = {rl[0], rl[1]}, b1l[2] = {rl[2], rl[3]};
                #pragma unroll
                for (int mt = 0; mt < 2; mt++) {
                    mma_f16(acc[mt][2*np],   a[mt], b0h);
                    mma_f16(acc[mt][2*np],   a[mt], b0l);
                    mma_f16(acc[mt][2*np+1], a[mt], b1h);
                    mma_f16(acc[mt][2*np+1], a[mt], b1l);
                }
            }
        }
    };

    // prologue: stages 0,1
    ISSUE(0, 0); CP_COMMIT();
    if (NC > 1) { ISSUE(1, 1); }
    CP_COMMIT();

    for (int kc = 0; kc < NC; kc++) {
        CP_WAIT(NSTAGE - 2);
        __syncthreads();
        COMPUTE(kc % NSTAGE);
        if (kc + NSTAGE - 1 < NC) ISSUE(kc + NSTAGE - 1, (kc + NSTAGE - 1) % NSTAGE);
        CP_COMMIT();
    }
    CP_WAIT(0);

    if (MODE == 1) {
        #pragma unroll
        for (int mt = 0; mt < 2; mt++)
            #pragma unroll
            for (int half = 0; half < 2; half++) {
                int row = m0 + warp_m*32 + mt*16 + (lane >> 2) + half*8;
                #pragma unroll
                for (int nt = 0; nt < 8; nt++) {
                    int col = n0 + warp_n*64 + nt*8 + (lane & 3)*2;
                    float f0 = fmaxf(acc[mt][nt][half*2+0] + bias[col],   0.f);
                    float f1 = fmaxf(acc[mt][nt][half*2+1] + bias[col+1], 0.f);
                    *(uint32_t*)(H + (size_t)row*NTOT + col) = pack2h(f0, f1);
                }
            }
    } else {
        __syncthreads();
        float* Ct = (float*)smraw;    // [128][129]
        #pragma unroll
        for (int mt = 0; mt < 2; mt++)
            #pragma unroll
            for (int half = 0; half < 2; half++) {
                int rl = warp_m*32 + mt*16 + (lane >> 2) + half*8;
                #pragma unroll
                for (int nt = 0; nt < 8; nt++) {
                    int cl = warp_n*64 + nt*8 + (lane & 3)*2;
                    Ct[rl*129 + cl]     = acc[mt][nt][half*2+0];
                    Ct[rl*129 + cl + 1] = acc[mt][nt][half*2+1];
                }
            }
        __syncthreads();
        int bb = m0 >> 10, nn0 = m0 & (HWn-1);
        #pragma unroll
        for (int cc = 0; cc < 16; cc++) {
            int col = wid*16 + cc;
            int co = n0 + col;
            float bi = bias[co];
            float* ob = Out + (size_t)bb*Cn*HWn + (size_t)co*HWn + nn0;
            #pragma unroll
            for (int j = 0; j < 4; j++) {
                int rr = lane + 32*j;
                ob[rr] = Ct[rr*129 + col] + bi;
            }
        }
    }
}

// ======================= launch =======================
extern "C" void kernel_launch(void* const* d_in, const int* in_sizes, int n_in,
                              void* d_out, int out_size)
{
    const float* x      = (const float*)d_in[0];
    const float* fc1_w  = (const float*)d_in[1];
    const float* fc1_b  = (const float*)d_in[2];
    const float* fc2_w  = (const float*)d_in[3];
    const float* fc2_b  = (const float*)d_in[4];
    const float* qkv_w  = (const float*)d_in[5];
    const float* qkv_b  = (const float*)d_in[6];
    const float* proj_w = (const float*)d_in[7];
    const float* proj_b = (const float*)d_in[8];
    const float* ffn1_w = (const float*)d_in[9];
    const float* ffn1_b = (const float*)d_in[10];
    const float* ffn2_w = (const float*)d_in[11];
    const float* ffn2_b = (const float*)d_in[12];
    float* out = (float*)d_out;

    cudaFuncSetAttribute(attn_mma_kernel, cudaFuncAttributeMaxDynamicSharedMemorySize, ATT_SMEM_BYTES);
    cudaFuncSetAttribute((const void*)mma_gemm_kernel<C4n, Cn, 1>, cudaFuncAttributeMaxDynamicSharedMemorySize, GEMM_SMEM);
    cudaFuncSetAttribute((const void*)mma_gemm_kernel<Cn, C4n, 2>, cudaFuncAttributeMaxDynamicSharedMemorySize, GEMM_SMEM);

    __half *yp, *hp, *w1h, *w1l, *w2h, *w2l;
    cudaGetSymbolAddress((void**)&yp,  g_y);
    cudaGetSymbolAddress((void**)&hp,  g_h);
    cudaGetSymbolAddress((void**)&w1h, g_w1h);
    cudaGetSymbolAddress((void**)&w1l, g_w1l);
    cudaGetSymbolAddress((void**)&w2h, g_w2h);
    cudaGetSymbolAddress((void**)&w2l, g_w2l);

    convertw_T<<<(C4n*Cn)/256, 256>>>(ffn1_w, w1h, w1l, C4n, Cn);
    convertw_T<<<(Cn*C4n)/256, 256>>>(ffn2_w, w2h, w2l, Cn, C4n);

    se_kernel<<<Bn, 256>>>(x, fc1_w, fc1_b, fc2_w, fc2_b);
    qkv_kernel<<<128, 512>>>(x, qkv_w, qkv_b);
    gate_y_kernel<<<dim3(4, 7, Bn), 256>>>(x);
    attn_mma_kernel<<<dim3(8, Bn), 256, ATT_SMEM_BYTES>>>(proj_w, proj_b);

    mma_gemm_kernel<C4n, Cn, 1><<<dim3(C4n/128, NPIX/128), 256, GEMM_SMEM>>>(
        yp, w1h, w1l, ffn1_b, hp, nullptr);
    mma_gemm_kernel<Cn, C4n, 2><<<dim3(Cn/128, NPIX/128), 256, GEMM_SMEM>>>(
        hp, w2h, w2l, ffn2_b, nullptr, out);
}

// round 7
// speedup vs baseline: 4.4321x; 1.3173x over previous
#include <cuda_runtime.h>
#include <cuda_fp16.h>
#include <cstdint>
#include <math.h>

#define Bn   16
#define Cn   256
#define HWn  1024
#define ADn  16
#define SCn  32
#define CRn  64
#define C4n  1024
#define NPIX (Bn*HWn)   // 16384

// ======================= device scratch =======================
__device__ float g_s[Bn*Cn];
// q/k/v single fp16: q,k [b][m][16] (q pre-scaled by 0.25), v [b][m][32]
__device__ __align__(256) __half g_q[Bn*HWn*ADn];
__device__ __align__(256) __half g_k[Bn*HWn*ADn];
__device__ __align__(256) __half g_v[Bn*HWn*SCn];
// FFN activations fp16, pixel-major
__device__ __align__(256) __half g_y[NPIX*Cn];
__device__ __align__(256) __half g_h[NPIX*C4n];
// weights transposed to [K][N] fp16 single
__device__ __align__(256) __half g_w1[Cn*C4n];
__device__ __align__(256) __half g_w2[C4n*Cn];

// ======================= PTX helpers =======================
__device__ __forceinline__ uint32_t smem_to_u32(const void* p) {
    uint32_t a;
    asm("{ .reg .u64 t; cvta.to.shared.u64 t, %1; cvt.u32.u64 %0, t; }" : "=r"(a) : "l"(p));
    return a;
}
__device__ __forceinline__ void ldsm_x4(uint32_t r[4], uint32_t addr) {
    asm volatile("ldmatrix.sync.aligned.m8n8.x4.shared.b16 {%0,%1,%2,%3}, [%4];"
        : "=r"(r[0]), "=r"(r[1]), "=r"(r[2]), "=r"(r[3]) : "r"(addr));
}
__device__ __forceinline__ void ldsm_x4_t(uint32_t r[4], uint32_t addr) {
    asm volatile("ldmatrix.sync.aligned.m8n8.x4.trans.shared.b16 {%0,%1,%2,%3}, [%4];"
        : "=r"(r[0]), "=r"(r[1]), "=r"(r[2]), "=r"(r[3]) : "r"(addr));
}
__device__ __forceinline__ void mma_f16(float c[4], const uint32_t a[4], const uint32_t b[2]) {
    asm volatile("mma.sync.aligned.m16n8k16.row.col.f32.f16.f16.f32 "
        "{%0,%1,%2,%3}, {%4,%5,%6,%7}, {%8,%9}, {%0,%1,%2,%3};"
        : "+f"(c[0]), "+f"(c[1]), "+f"(c[2]), "+f"(c[3])
        : "r"(a[0]), "r"(a[1]), "r"(a[2]), "r"(a[3]), "r"(b[0]), "r"(b[1]));
}
#define CP_ASYNC16(dst, src) \
    asm volatile("cp.async.cg.shared.global [%0], [%1], 16;" :: "r"(dst), "l"(src))
#define CP_COMMIT() asm volatile("cp.async.commit_group;")
#define CP_WAIT(n)  asm volatile("cp.async.wait_group %0;" :: "n"(n))

__device__ __forceinline__ uint32_t pack2h(float f0, float f1) {
    __half2 h = __floats2half2_rn(f0, f1);
    return *(uint32_t*)&h;
}

// ======================= weight convert+transpose (tiled) =======================
// w: [O][K] fp32 -> t: [K][O] fp16
__global__ __launch_bounds__(256) void convertw_T(
    const float* __restrict__ w, __half* __restrict__ t, int O, int K)
{
    __shared__ float s[32][33];
    int k0 = blockIdx.x*32, o0 = blockIdx.y*32;
    int tid = threadIdx.x;
    #pragma unroll
    for (int i = tid; i < 1024; i += 256) {
        int o = i >> 5, k = i & 31;
        s[k][o] = w[(size_t)(o0 + o)*K + k0 + k];
    }
    __syncthreads();
    #pragma unroll
    for (int i = tid; i < 1024; i += 256) {
        int k = i >> 5, o = i & 31;
        t[(size_t)(k0 + k)*O + o0 + o] = __float2half_rn(s[k][o]);
    }
}

// ======================= kernel 1: squeeze-excite gate =======================
__global__ __launch_bounds__(256) void se_kernel(
    const float* __restrict__ x,
    const float* __restrict__ fc1_w, const float* __restrict__ fc1_b,
    const float* __restrict__ fc2_w, const float* __restrict__ fc2_b)
{
    __shared__ float mean[Cn];
    __shared__ float s1[CRn];
    int b = blockIdx.x;
    int tid = threadIdx.x, warp = tid >> 5, lane = tid & 31;

    const float4* xb = (const float4*)(x + (size_t)b*Cn*HWn);
    for (int c = warp; c < Cn; c += 8) {
        const float4* row = xb + (size_t)c*(HWn/4);
        float sum = 0.f;
        #pragma unroll
        for (int j = 0; j < HWn/4/32; j++) {
            float4 v = row[lane + 32*j];
            sum += v.x + v.y + v.z + v.w;
        }
        #pragma unroll
        for (int o = 16; o > 0; o >>= 1) sum += __shfl_xor_sync(0xffffffffu, sum, o);
        if (lane == 0) mean[c] = sum * (1.0f/HWn);
    }
    __syncthreads();

    if (tid < CRn) {
        float acc = fc1_b[tid];
        const float* wr = fc1_w + tid*Cn;
        #pragma unroll 8
        for (int c = 0; c < Cn; c++) acc += wr[c]*mean[c];
        s1[tid] = fmaxf(acc, 0.f);
    }
    __syncthreads();
    {
        float acc = fc2_b[tid];
        const float* wr = fc2_w + tid*CRn;
        #pragma unroll 8
        for (int j = 0; j < CRn; j++) acc += wr[j]*s1[j];
        g_s[b*Cn + tid] = 1.f/(1.f + __expf(-acc));
    }
}

// ======================= kernel 2: fused gate + qkv =======================
// grid (8 tiles, 16 b), 256 threads, 128 pixels/block. One pass over x:
// cg 0: compute q/k/v from gated attn channels; cg 1-7: gated y fp16.
__global__ __launch_bounds__(256) void gate_all_kernel(
    const float* __restrict__ x,
    const float* __restrict__ qkv_w, const float* __restrict__ qkv_b)
{
    __shared__ float t[32][132];
    __shared__ float ws[32][64];
    __shared__ float sgall[Cn];
    __shared__ float qb[64];

    int b = blockIdx.y, n0 = blockIdx.x*128;
    int tid = threadIdx.x;

    for (int i = tid; i < 64*SCn; i += 256) { int o = i >> 5, c = i & 31; ws[c][o] = qkv_w[i]; }
    if (tid < 64) qb[tid] = qkv_b[tid];
    sgall[tid] = g_s[b*Cn + tid];

    int p   = tid & 127;
    int sub = tid >> 7;
    size_t P = (size_t)b*HWn + n0 + p;

    for (int cg = 0; cg < 8; cg++) {
        int c0 = cg*32;
        #pragma unroll
        for (int i = tid; i < 32*128; i += 256) {
            int r = i >> 7, n = i & 127;
            t[r][n] = x[((size_t)b*Cn + c0 + r)*HWn + n0 + n];
        }
        __syncthreads();

        if (cg == 0) {
            float acc[32];
            #pragma unroll
            for (int o = 0; o < 32; o++) acc[o] = qb[sub*32 + o];
            #pragma unroll 4
            for (int c = 0; c < SCn; c++) {
                float xv = t[c][p] * sgall[c];
                #pragma unroll
                for (int o4 = 0; o4 < 8; o4++) {
                    float4 w = *(const float4*)&ws[c][sub*32 + o4*4];
                    acc[o4*4+0] += w.x*xv;
                    acc[o4*4+1] += w.y*xv;
                    acc[o4*4+2] += w.z*xv;
                    acc[o4*4+3] += w.w*xv;
                }
            }
            __align__(16) uint32_t pk[16];
            if (sub == 0) {
                #pragma unroll
                for (int i = 0; i < 8; i++) pk[i] = pack2h(acc[2*i]*0.25f, acc[2*i+1]*0.25f);
                #pragma unroll
                for (int i = 8; i < 16; i++) pk[i] = pack2h(acc[2*i], acc[2*i+1]);
                *(uint4*)(g_q + P*ADn)     = *(uint4*)&pk[0];
                *(uint4*)(g_q + P*ADn + 8) = *(uint4*)&pk[4];
                *(uint4*)(g_k + P*ADn)     = *(uint4*)&pk[8];
                *(uint4*)(g_k + P*ADn + 8) = *(uint4*)&pk[12];
            } else {
                #pragma unroll
                for (int i = 0; i < 16; i++) pk[i] = pack2h(acc[2*i], acc[2*i+1]);
                #pragma unroll
                for (int q = 0; q < 4; q++)
                    *(uint4*)(g_v + P*SCn + q*8) = *(uint4*)&pk[4*q];
            }
        } else {
            __align__(16) uint32_t pk[8];
            #pragma unroll
            for (int i = 0; i < 8; i++) {
                int c = sub*16 + 2*i;
                pk[i] = pack2h(t[c][p]*sgall[c0+c], t[c+1][p]*sgall[c0+c+1]);
            }
            *(uint4*)(g_y + P*Cn + c0 + sub*16)     = *(uint4*)&pk[0];
            *(uint4*)(g_y + P*Cn + c0 + sub*16 + 8) = *(uint4*)&pk[4];
        }
        __syncthreads();
    }
}

// ======================= kernel 3: flash attention, fp16 1-term =======================
#define ATT_Q  0
#define ATT_K  3072
#define ATT_V  6144
#define ATT_PW 11264
#define ATT_SMEM_BYTES (12544*2)

__global__ __launch_bounds__(256) void attn_mma_kernel(
    const float* __restrict__ proj_w, const float* __restrict__ proj_b)
{
    extern __shared__ __half smb[];
    const uint32_t sb = smem_to_u32(smb);
    const int tid = threadIdx.x, lane = tid & 31, wid = tid >> 5;
    const int b = blockIdx.y;
    const int m0 = blockIdx.x*128;
    const size_t pixbase = (size_t)b*HWn + m0;

    { // stage Q + proj weights (single fp16)
        int row = tid >> 1, half = tid & 1;
        *(uint4*)(smb + ATT_Q + row*24 + half*8) = *(const uint4*)(g_q + (pixbase + row)*ADn + half*8);
    }
    for (int i = tid; i < SCn*SCn; i += 256) {
        int o = i >> 5, c = i & 31;
        smb[ATT_PW + o*40 + c] = __float2half_rn(proj_w[i]);
    }
    __syncthreads();

    uint32_t aq[4];
    ldsm_x4(aq, sb + (ATT_Q + (wid*16 + (lane & 15))*24 + (lane >> 4)*8)*2);

    float o_acc[4][4];
    #pragma unroll
    for (int nt = 0; nt < 4; nt++)
        #pragma unroll
        for (int i = 0; i < 4; i++) o_acc[nt][i] = 0.f;
    float mA = -1e30f, mB = -1e30f, lA = 0.f, lB = 0.f;

    for (int kc = 0; kc < 8; kc++) {
        { // stage K, V chunk
            size_t kb = (size_t)b*HWn + kc*128;
            int row = tid >> 1, half = tid & 1;
            *(uint4*)(smb + ATT_K + row*24 + half*8) = *(const uint4*)(g_k + (kb + row)*ADn + half*8);
            #pragma unroll
            for (int q = 0; q < 2; q++) {
                int idx = tid + q*256;
                int vr = idx >> 2, part = idx & 3;
                *(uint4*)(smb + ATT_V + vr*40 + part*8) = *(const uint4*)(g_v + (kb + vr)*SCn + part*8);
            }
        }
        __syncthreads();

        // S = QK^T (1-term)
        float s[16][4];
        #pragma unroll
        for (int t = 0; t < 16; t++)
            #pragma unroll
            for (int i = 0; i < 4; i++) s[t][i] = 0.f;

        #pragma unroll
        for (int pr = 0; pr < 8; pr++) {
            uint32_t k4[4];
            ldsm_x4(k4, sb + (ATT_K + (pr*16 + (lane & 15))*24 + (lane >> 4)*8)*2);
            uint32_t b0[2] = {k4[0], k4[2]}, b1[2] = {k4[1], k4[3]};
            mma_f16(s[2*pr],   aq, b0);
            mma_f16(s[2*pr+1], aq, b1);
        }

        // online softmax
        float cmA = -1e30f, cmB = -1e30f;
        #pragma unroll
        for (int t = 0; t < 16; t++) {
            cmA = fmaxf(cmA, fmaxf(s[t][0], s[t][1]));
            cmB = fmaxf(cmB, fmaxf(s[t][2], s[t][3]));
        }
        #pragma unroll
        for (int off = 1; off < 4; off <<= 1) {
            cmA = fmaxf(cmA, __shfl_xor_sync(0xffffffffu, cmA, off));
            cmB = fmaxf(cmB, __shfl_xor_sync(0xffffffffu, cmB, off));
        }
        float nmA = fmaxf(mA, cmA), nmB = fmaxf(mB, cmB);
        float alA = __expf(mA - nmA), alB = __expf(mB - nmB);
        mA = nmA; mB = nmB;
        float sumA = 0.f, sumB = 0.f;
        #pragma unroll
        for (int t = 0; t < 16; t++) {
            s[t][0] = __expf(s[t][0] - mA);
            s[t][1] = __expf(s[t][1] - mA);
            s[t][2] = __expf(s[t][2] - mB);
            s[t][3] = __expf(s[t][3] - mB);
            sumA += s[t][0] + s[t][1];
            sumB += s[t][2] + s[t][3];
        }
        #pragma unroll
        for (int off = 1; off < 4; off <<= 1) {
            sumA += __shfl_xor_sync(0xffffffffu, sumA, off);
            sumB += __shfl_xor_sync(0xffffffffu, sumB, off);
        }
        lA = lA*alA + sumA;
        lB = lB*alB + sumB;
        #pragma unroll
        for (int nt = 0; nt < 4; nt++) {
            o_acc[nt][0] *= alA; o_acc[nt][1] *= alA;
            o_acc[nt][2] *= alB; o_acc[nt][3] *= alB;
        }

        // O += P @ V (P packed single fp16)
        #pragma unroll
        for (int j = 0; j < 8; j++) {
            uint32_t ap[4];
            ap[0] = pack2h(s[2*j][0],   s[2*j][1]);
            ap[1] = pack2h(s[2*j][2],   s[2*j][3]);
            ap[2] = pack2h(s[2*j+1][0], s[2*j+1][1]);
            ap[3] = pack2h(s[2*j+1][2], s[2*j+1][3]);
            #pragma unroll
            for (int cb = 0; cb < 2; cb++) {
                uint32_t rv[4];
                ldsm_x4_t(rv, sb + (ATT_V + (j*16 + (lane & 15))*40 + cb*16 + (lane >> 4)*8)*2);
                uint32_t b0[2] = {rv[0], rv[1]}, b1[2] = {rv[2], rv[3]};
                mma_f16(o_acc[cb*2],   ap, b0);
                mma_f16(o_acc[cb*2+1], ap, b1);
            }
        }
        __syncthreads();
    }

    float invA = 1.f/lA, invB = 1.f/lB;
    #pragma unroll
    for (int nt = 0; nt < 4; nt++) {
        o_acc[nt][0] *= invA; o_acc[nt][1] *= invA;
        o_acc[nt][2] *= invB; o_acc[nt][3] *= invB;
    }

    // proj (32x32), 1-term
    float r[4][4];
    #pragma unroll
    for (int nt = 0; nt < 4; nt++)
        #pragma unroll
        for (int i = 0; i < 4; i++) r[nt][i] = 0.f;

    #pragma unroll
    for (int j = 0; j < 2; j++) {
        uint32_t ao[4];
        ao[0] = pack2h(o_acc[2*j][0],   o_acc[2*j][1]);
        ao[1] = pack2h(o_acc[2*j][2],   o_acc[2*j][3]);
        ao[2] = pack2h(o_acc[2*j+1][0], o_acc[2*j+1][1]);
        ao[3] = pack2h(o_acc[2*j+1][2], o_acc[2*j+1][3]);
        #pragma unroll
        for (int pr = 0; pr < 2; pr++) {
            uint32_t p4[4];
            ldsm_x4(p4, sb + (ATT_PW + (pr*16 + (lane & 15))*40 + j*16 + (lane >> 4)*8)*2);
            uint32_t b0[2] = {p4[0], p4[2]}, b1[2] = {p4[1], p4[3]};
            mma_f16(r[pr*2],   ao, b0);
            mma_f16(r[pr*2+1], ao, b1);
        }
    }

    {
        size_t pA = pixbase + wid*16 + (lane >> 2);
        size_t pB = pA + 8;
        #pragma unroll
        for (int nt = 0; nt < 4; nt++) {
            int col = nt*8 + (lane & 3)*2;
            float b0 = proj_b[col], b1 = proj_b[col+1];
            *(uint32_t*)(g_y + pA*Cn + col) = pack2h(r[nt][0] + b0, r[nt][1] + b1);
            *(uint32_t*)(g_y + pB*Cn + col) = pack2h(r[nt][2] + b0, r[nt][3] + b1);
        }
    }
}

// ======================= kernels 4/5: fp16 1-term GEMM, cp.async 4-stage ============
#define KCh 32
#define A_STRIDE 56
#define W_STRIDE 136
#define OFF_A  0
#define OFF_W  (128*A_STRIDE*2)                          // 14336
#define STAGE_BYTES (128*A_STRIDE*2 + KCh*W_STRIDE*2)    // 23040
#define NSTAGE 4
#define GEMM_SMEM (NSTAGE*STAGE_BYTES)                   // 92160

template<int NTOT, int KTOT, int MODE>
__global__ __launch_bounds__(256)
void mma_gemm_kernel(const __half* __restrict__ Ag, const __half* __restrict__ Wg,
                     const float* __restrict__ bias,
                     __half* __restrict__ H, float* __restrict__ Out)
{
    extern __shared__ char smraw[];
    const uint32_t smem_base = smem_to_u32(smraw);

    const int tid = threadIdx.x;
    const int lane = tid & 31, wid = tid >> 5;
    const int warp_m = wid & 3;
    const int warp_n = wid >> 2;
    const int m0 = blockIdx.y*128, n0 = blockIdx.x*128;
    constexpr int NC = KTOT / KCh;

    float acc[2][8][4];
    #pragma unroll
    for (int mt = 0; mt < 2; mt++)
        #pragma unroll
        for (int nt = 0; nt < 8; nt++)
            #pragma unroll
            for (int i = 0; i < 4; i++) acc[mt][nt][i] = 0.f;

    auto ISSUE = [&](int kc, int buf) {
        uint32_t sbase = smem_base + buf*STAGE_BYTES;
        #pragma unroll
        for (int q = 0; q < 2; q++) {
            int idx = tid + q*256;
            int row = idx >> 2, seg = idx & 3;
            uint32_t dst = sbase + OFF_A + row*(A_STRIDE*2) + seg*16;
            const __half* src = Ag + (size_t)(m0 + row)*KTOT + kc*KCh + seg*8;
            CP_ASYNC16(dst, src);
        }
        #pragma unroll
        for (int q = 0; q < 2; q++) {
            int idx = tid + q*256;
            int row = idx >> 4, seg = idx & 15;
            uint32_t dst = sbase + OFF_W + row*(W_STRIDE*2) + seg*16;
            const __half* src = Wg + (size_t)(kc*KCh + row)*NTOT + n0 + seg*8;
            CP_ASYNC16(dst, src);
        }
    };

    auto COMPUTE = [&](int buf) {
        uint32_t sbx = smem_base + buf*STAGE_BYTES;
        #pragma unroll
        for (int ks = 0; ks < 2; ks++) {
            int k0 = ks*16;
            uint32_t a[2][4];
            #pragma unroll
            for (int mt = 0; mt < 2; mt++) {
                uint32_t off = ((warp_m*32 + mt*16 + (lane & 15))*A_STRIDE + k0 + ((lane >> 4) << 3))*2;
                ldsm_x4(a[mt], sbx + OFF_A + off);
            }
            #pragma unroll
            for (int np = 0; np < 4; np++) {
                uint32_t off = ((k0 + (lane & 15))*W_STRIDE + warp_n*64 + np*16 + ((lane >> 4) << 3))*2;
                uint32_t rw[4];
                ldsm_x4_t(rw, sbx + OFF_W + off);
                uint32_t b0[2] = {rw[0], rw[1]}, b1[2] = {rw[2], rw[3]};
                #pragma unroll
                for (int mt = 0; mt < 2; mt++) {
                    mma_f16(acc[mt][2*np],   a[mt], b0);
                    mma_f16(acc[mt][2*np+1], a[mt], b1);
                }
            }
        }
    };

    #pragma unroll
    for (int s = 0; s < NSTAGE-1; s++) {
        if (s < NC) ISSUE(s, s);
        CP_COMMIT();
    }
    for (int kc = 0; kc < NC; kc++) {
        CP_WAIT(NSTAGE-2);
        __syncthreads();
        COMPUTE(kc % NSTAGE);
        int nx = kc + NSTAGE - 1;
        if (nx < NC) ISSUE(nx, nx % NSTAGE);
        CP_COMMIT();
    }
    CP_WAIT(0);

    if (MODE == 1) {
        #pragma unroll
        for (int mt = 0; mt < 2; mt++)
            #pragma unroll
            for (int half = 0; half < 2; half++) {
                int row = m0 + warp_m*32 + mt*16 + (lane >> 2) + half*8;
                #pragma unroll
                for (int nt = 0; nt < 8; nt++) {
                    int col = n0 + warp_n*64 + nt*8 + (lane & 3)*2;
                    float f0 = fmaxf(acc[mt][nt][half*2+0] + bias[col],   0.f);
                    float f1 = fmaxf(acc[mt][nt][half*2+1] + bias[col+1], 0.f);
                    *(uint32_t*)(H + (size_t)row*NTOT + col) = pack2h(f0, f1);
                }
            }
    } else {
        __syncthreads();
        float* Ct = (float*)smraw;    // [128][129]
        #pragma unroll
        for (int mt = 0; mt < 2; mt++)
            #pragma unroll
            for (int half = 0; half < 2; half++) {
                int rl = warp_m*32 + mt*16 + (lane >> 2) + half*8;
                #pragma unroll
                for (int nt = 0; nt < 8; nt++) {
                    int cl = warp_n*64 + nt*8 + (lane & 3)*2;
                    Ct[rl*129 + cl]     = acc[mt][nt][half*2+0];
                    Ct[rl*129 + cl + 1] = acc[mt][nt][half*2+1];
                }
            }
        __syncthreads();
        int bb = m0 >> 10, nn0 = m0 & (HWn-1);
        #pragma unroll
        for (int cc = 0; cc < 16; cc++) {
            int col = wid*16 + cc;
            int co = n0 + col;
            float bi = bias[co];
            float* ob = Out + (size_t)bb*Cn*HWn + (size_t)co*HWn + nn0;
            #pragma unroll
            for (int j = 0; j < 4; j++) {
                int rr = lane + 32*j;
                ob[rr] = Ct[rr*129 + col] + bi;
            }
        }
    }
}

// ======================= launch =======================
extern "C" void kernel_launch(void* const* d_in, const int* in_sizes, int n_in,
                              void* d_out, int out_size)
{
    const float* x      = (const float*)d_in[0];
    const float* fc1_w  = (const float*)d_in[1];
    const float* fc1_b  = (const float*)d_in[2];
    const float* fc2_w  = (const float*)d_in[3];
    const float* fc2_b  = (const float*)d_in[4];
    const float* qkv_w  = (const float*)d_in[5];
    const float* qkv_b  = (const float*)d_in[6];
    const float* proj_w = (const float*)d_in[7];
    const float* proj_b = (const float*)d_in[8];
    const float* ffn1_w = (const float*)d_in[9];
    const float* ffn1_b = (const float*)d_in[10];
    const float* ffn2_w = (const float*)d_in[11];
    const float* ffn2_b = (const float*)d_in[12];
    float* out = (float*)d_out;

    cudaFuncSetAttribute(attn_mma_kernel, cudaFuncAttributeMaxDynamicSharedMemorySize, ATT_SMEM_BYTES);
    cudaFuncSetAttribute((const void*)mma_gemm_kernel<C4n, Cn, 1>, cudaFuncAttributeMaxDynamicSharedMemorySize, GEMM_SMEM);
    cudaFuncSetAttribute((const void*)mma_gemm_kernel<Cn, C4n, 2>, cudaFuncAttributeMaxDynamicSharedMemorySize, GEMM_SMEM);

    __half *yp, *hp, *w1, *w2;
    cudaGetSymbolAddress((void**)&yp, g_y);
    cudaGetSymbolAddress((void**)&hp, g_h);
    cudaGetSymbolAddress((void**)&w1, g_w1);
    cudaGetSymbolAddress((void**)&w2, g_w2);

    convertw_T<<<dim3(Cn/32, C4n/32), 256>>>(ffn1_w, w1, C4n, Cn);
    convertw_T<<<dim3(C4n/32, Cn/32), 256>>>(ffn2_w, w2, Cn, C4n);

    se_kernel<<<Bn, 256>>>(x, fc1_w, fc1_b, fc2_w, fc2_b);
    gate_all_kernel<<<dim3(8, Bn), 256>>>(x, qkv_w, qkv_b);
    attn_mma_kernel<<<dim3(8, Bn), 256, ATT_SMEM_BYTES>>>(proj_w, proj_b);

    mma_gemm_kernel<C4n, Cn, 1><<<dim3(C4n/128, NPIX/128), 256, GEMM_SMEM>>>(
        yp, w1, ffn1_b, hp, nullptr);
    mma_gemm_kernel<Cn, C4n, 2><<<dim3(Cn/128, NPIX/128), 256, GEMM_SMEM>>>(
        hp, w2, ffn2_b, nullptr, out);
}

// round 10
// speedup vs baseline: 5.2396x; 1.1822x over previous
#include <cuda_runtime.h>
#include <cuda_fp16.h>
#include <cstdint>
#include <math.h>

#define Bn   16
#define Cn   256
#define HWn  1024
#define ADn  16
#define SCn  32
#define CRn  64
#define C4n  1024
#define NPIX (Bn*HWn)   // 16384

// ======================= device scratch =======================
__device__ float g_part[Bn*8*Cn];
__device__ float g_s[Bn*Cn];
__device__ __align__(256) __half g_q[Bn*HWn*ADn];
__device__ __align__(256) __half g_k[Bn*HWn*ADn];
__device__ __align__(256) __half g_v[Bn*HWn*SCn];
__device__ __align__(256) __half g_y[NPIX*Cn];
__device__ __align__(256) __half g_h[NPIX*C4n];
__device__ __align__(256) __half g_w1[Cn*C4n];
__device__ __align__(256) __half g_w2[C4n*Cn];

// ======================= PTX helpers =======================
__device__ __forceinline__ uint32_t smem_to_u32(const void* p) {
    uint32_t a;
    asm("{ .reg .u64 t; cvta.to.shared.u64 t, %1; cvt.u32.u64 %0, t; }" : "=r"(a) : "l"(p));
    return a;
}
__device__ __forceinline__ void ldsm_x4(uint32_t r[4], uint32_t addr) {
    asm volatile("ldmatrix.sync.aligned.m8n8.x4.shared.b16 {%0,%1,%2,%3}, [%4];"
        : "=r"(r[0]), "=r"(r[1]), "=r"(r[2]), "=r"(r[3]) : "r"(addr));
}
__device__ __forceinline__ void ldsm_x4_t(uint32_t r[4], uint32_t addr) {
    asm volatile("ldmatrix.sync.aligned.m8n8.x4.trans.shared.b16 {%0,%1,%2,%3}, [%4];"
        : "=r"(r[0]), "=r"(r[1]), "=r"(r[2]), "=r"(r[3]) : "r"(addr));
}
__device__ __forceinline__ void mma_f16(float c[4], const uint32_t a[4], const uint32_t b[2]) {
    asm volatile("mma.sync.aligned.m16n8k16.row.col.f32.f16.f16.f32 "
        "{%0,%1,%2,%3}, {%4,%5,%6,%7}, {%8,%9}, {%0,%1,%2,%3};"
        : "+f"(c[0]), "+f"(c[1]), "+f"(c[2]), "+f"(c[3])
        : "r"(a[0]), "r"(a[1]), "r"(a[2]), "r"(a[3]), "r"(b[0]), "r"(b[1]));
}
#define CP_ASYNC16(dst, src) \
    asm volatile("cp.async.cg.shared.global [%0], [%1], 16;" :: "r"(dst), "l"(src))
#define CP_COMMIT() asm volatile("cp.async.commit_group;")
#define CP_WAIT(n)  asm volatile("cp.async.wait_group %0;" :: "n"(n))

__device__ __forceinline__ uint32_t pack2h(float f0, float f1) {
    __half2 h = __floats2half2_rn(f0, f1);
    return *(uint32_t*)&h;
}

// ======================= weight convert+transpose (tiled) =======================
__global__ __launch_bounds__(256) void convertw_T(
    const float* __restrict__ w, __half* __restrict__ t, int O, int K)
{
    __shared__ float s[32][33];
    int k0 = blockIdx.x*32, o0 = blockIdx.y*32;
    int tid = threadIdx.x;
    #pragma unroll
    for (int i = tid; i < 1024; i += 256) {
        int o = i >> 5, k = i & 31;
        s[k][o] = w[(size_t)(o0 + o)*K + k0 + k];
    }
    __syncthreads();
    #pragma unroll
    for (int i = tid; i < 1024; i += 256) {
        int k = i >> 5, o = i & 31;
        t[(size_t)(k0 + k)*O + o0 + o] = __float2half_rn(s[k][o]);
    }
}

// ======================= kernel 1a: SE partial means (128 blocks) ==================
__global__ __launch_bounds__(256) void se1_kernel(const float* __restrict__ x)
{
    int s = blockIdx.x & 7, b = blockIdx.x >> 3;
    int tid = threadIdx.x, warp = tid >> 5, lane = tid & 31;
    #pragma unroll
    for (int c = warp; c < Cn; c += 8) {
        float4 v = *(const float4*)(x + ((size_t)b*Cn + c)*HWn + s*128 + lane*4);
        float sum = v.x + v.y + v.z + v.w;
        #pragma unroll
        for (int o = 16; o > 0; o >>= 1) sum += __shfl_xor_sync(0xffffffffu, sum, o);
        if (lane == 0) g_part[(b*8 + s)*Cn + c] = sum;
    }
}

// ======================= kernel 1b: SE finish =======================
__global__ __launch_bounds__(256) void se2_kernel(
    const float* __restrict__ fc1_w, const float* __restrict__ fc1_b,
    const float* __restrict__ fc2_w, const float* __restrict__ fc2_b)
{
    __shared__ float mean[Cn];
    __shared__ float s1[CRn];
    int b = blockIdx.x, tid = threadIdx.x;
    {
        float sum = 0.f;
        #pragma unroll
        for (int s = 0; s < 8; s++) sum += g_part[(b*8 + s)*Cn + tid];
        mean[tid] = sum * (1.0f/HWn);
    }
    __syncthreads();
    if (tid < CRn) {
        float acc = fc1_b[tid];
        const float* wr = fc1_w + tid*Cn;
        #pragma unroll 8
        for (int c = 0; c < Cn; c++) acc += wr[c]*mean[c];
        s1[tid] = fmaxf(acc, 0.f);
    }
    __syncthreads();
    {
        float acc = fc2_b[tid];
        const float* wr = fc2_w + tid*CRn;
        #pragma unroll 8
        for (int j = 0; j < CRn; j++) acc += wr[j]*s1[j];
        g_s[b*Cn + tid] = 1.f/(1.f + __expf(-acc));
    }
}

// ======================= kernel 2: fused gate + qkv (cp.async double-buffered) =====
__global__ __launch_bounds__(256) void gate_all_kernel(
    const float* __restrict__ x,
    const float* __restrict__ qkv_w, const float* __restrict__ qkv_b)
{
    __shared__ float t[2*32*132];
    __shared__ float ws[32][64];
    __shared__ float sgall[Cn];
    __shared__ float qb[64];

    int b = blockIdx.y, n0 = blockIdx.x*128;
    int tid = threadIdx.x;
    const uint32_t tbase = smem_to_u32(t);

    for (int i = tid; i < 64*SCn; i += 256) { int o = i >> 5, c = i & 31; ws[c][o] = qkv_w[i]; }
    if (tid < 64) qb[tid] = qkv_b[tid];
    sgall[tid] = g_s[b*Cn + tid];

    int p   = tid & 127;
    int sub = tid >> 7;
    size_t P = (size_t)b*HWn + n0 + p;

    auto ISSUE_X = [&](int cg, int buf) {
        #pragma unroll
        for (int q = 0; q < 4; q++) {
            int idx = tid + q*256;
            int row = idx >> 5, seg = idx & 31;
            uint32_t dst = tbase + (uint32_t)(buf*4224 + row*132)*4 + seg*16;
            const float* src = x + ((size_t)b*Cn + cg*32 + row)*HWn + n0 + seg*4;
            CP_ASYNC16(dst, src);
        }
    };

    ISSUE_X(0, 0); CP_COMMIT();

    for (int cg = 0; cg < 8; cg++) {
        int buf = cg & 1;
        if (cg < 7) { ISSUE_X(cg + 1, buf ^ 1); CP_COMMIT(); CP_WAIT(1); }
        else        { CP_WAIT(0); }
        __syncthreads();
        const float* tb = t + buf*4224;

        if (cg == 0) {
            float acc[32];
            #pragma unroll
            for (int o = 0; o < 32; o++) acc[o] = qb[sub*32 + o];
            #pragma unroll 4
            for (int c = 0; c < SCn; c++) {
                float xv = tb[c*132 + p] * sgall[c];
                #pragma unroll
                for (int o4 = 0; o4 < 8; o4++) {
                    float4 w = *(const float4*)&ws[c][sub*32 + o4*4];
                    acc[o4*4+0] += w.x*xv;
                    acc[o4*4+1] += w.y*xv;
                    acc[o4*4+2] += w.z*xv;
                    acc[o4*4+3] += w.w*xv;
                }
            }
            __align__(16) uint32_t pk[16];
            if (sub == 0) {
                #pragma unroll
                for (int i = 0; i < 8; i++) pk[i] = pack2h(acc[2*i]*0.25f, acc[2*i+1]*0.25f);
                #pragma unroll
                for (int i = 8; i < 16; i++) pk[i] = pack2h(acc[2*i], acc[2*i+1]);
                *(uint4*)(g_q + P*ADn)     = *(uint4*)&pk[0];
                *(uint4*)(g_q + P*ADn + 8) = *(uint4*)&pk[4];
                *(uint4*)(g_k + P*ADn)     = *(uint4*)&pk[8];
                *(uint4*)(g_k + P*ADn + 8) = *(uint4*)&pk[12];
            } else {
                #pragma unroll
                for (int i = 0; i < 16; i++) pk[i] = pack2h(acc[2*i], acc[2*i+1]);
                #pragma unroll
                for (int q = 0; q < 4; q++)
                    *(uint4*)(g_v + P*SCn + q*8) = *(uint4*)&pk[4*q];
            }
        } else {
            int c0 = cg*32;
            __align__(16) uint32_t pk[8];
            #pragma unroll
            for (int i = 0; i < 8; i++) {
                int c = sub*16 + 2*i;
                pk[i] = pack2h(tb[c*132 + p]*sgall[c0+c], tb[(c+1)*132 + p]*sgall[c0+c+1]);
            }
            *(uint4*)(g_y + P*Cn + c0 + sub*16)     = *(uint4*)&pk[0];
            *(uint4*)(g_y + P*Cn + c0 + sub*16 + 8) = *(uint4*)&pk[4];
        }
        __syncthreads();
    }
}

// ======================= kernel 3: flash attention (cp.async K/V pipeline) =========
#define ATT_Q   0
#define ATT_K0  3072
#define ATT_K1  6144
#define ATT_V0  9216
#define ATT_V1  14336
#define ATT_PW  19456
#define ATT_SMEM_BYTES (20736*2)   // 41472

__global__ __launch_bounds__(256) void attn_mma_kernel(
    const float* __restrict__ proj_w, const float* __restrict__ proj_b)
{
    extern __shared__ __half smb[];
    const uint32_t sb = smem_to_u32(smb);
    const int tid = threadIdx.x, lane = tid & 31, wid = tid >> 5;
    const int b = blockIdx.y;
    const int m0 = blockIdx.x*128;
    const size_t pixbase = (size_t)b*HWn + m0;

    { // stage Q + proj weights
        int row = tid >> 1, half = tid & 1;
        *(uint4*)(smb + ATT_Q + row*24 + half*8) = *(const uint4*)(g_q + (pixbase + row)*ADn + half*8);
    }
    for (int i = tid; i < SCn*SCn; i += 256) {
        int o = i >> 5, c = i & 31;
        smb[ATT_PW + o*40 + c] = __float2half_rn(proj_w[i]);
    }

    auto ISSUE_KV = [&](int kc, int buf) {
        size_t kb = (size_t)b*HWn + kc*128;
        int row = tid >> 1, half = tid & 1;
        uint32_t kdst = sb + (uint32_t)((buf ? ATT_K1 : ATT_K0) + row*24 + half*8)*2;
        CP_ASYNC16(kdst, g_k + (kb + row)*ADn + half*8);
        #pragma unroll
        for (int q = 0; q < 2; q++) {
            int idx = tid + q*256;
            int vr = idx >> 2, part = idx & 3;
            uint32_t vdst = sb + (uint32_t)((buf ? ATT_V1 : ATT_V0) + vr*40 + part*8)*2;
            CP_ASYNC16(vdst, g_v + (kb + vr)*SCn + part*8);
        }
    };

    ISSUE_KV(0, 0); CP_COMMIT();
    __syncthreads();

    uint32_t aq[4];
    ldsm_x4(aq, sb + (ATT_Q + (wid*16 + (lane & 15))*24 + (lane >> 4)*8)*2);

    float o_acc[4][4];
    #pragma unroll
    for (int nt = 0; nt < 4; nt++)
        #pragma unroll
        for (int i = 0; i < 4; i++) o_acc[nt][i] = 0.f;
    float mA = -1e30f, mB = -1e30f, lA = 0.f, lB = 0.f;

    for (int kc = 0; kc < 8; kc++) {
        int buf = kc & 1;
        if (kc < 7) { ISSUE_KV(kc + 1, buf ^ 1); CP_COMMIT(); CP_WAIT(1); }
        else        { CP_WAIT(0); }
        __syncthreads();
        const uint32_t KB = buf ? ATT_K1 : ATT_K0;
        const uint32_t VB = buf ? ATT_V1 : ATT_V0;

        // S = QK^T
        float s[16][4];
        #pragma unroll
        for (int t = 0; t < 16; t++)
            #pragma unroll
            for (int i = 0; i < 4; i++) s[t][i] = 0.f;

        #pragma unroll
        for (int pr = 0; pr < 8; pr++) {
            uint32_t k4[4];
            ldsm_x4(k4, sb + (KB + (pr*16 + (lane & 15))*24 + (lane >> 4)*8)*2);
            uint32_t b0[2] = {k4[0], k4[2]}, b1[2] = {k4[1], k4[3]};
            mma_f16(s[2*pr],   aq, b0);
            mma_f16(s[2*pr+1], aq, b1);
        }

        // online softmax
        float cmA = -1e30f, cmB = -1e30f;
        #pragma unroll
        for (int t = 0; t < 16; t++) {
            cmA = fmaxf(cmA, fmaxf(s[t][0], s[t][1]));
            cmB = fmaxf(cmB, fmaxf(s[t][2], s[t][3]));
        }
        #pragma unroll
        for (int off = 1; off < 4; off <<= 1) {
            cmA = fmaxf(cmA, __shfl_xor_sync(0xffffffffu, cmA, off));
            cmB = fmaxf(cmB, __shfl_xor_sync(0xffffffffu, cmB, off));
        }
        float nmA = fmaxf(mA, cmA), nmB = fmaxf(mB, cmB);
        float alA = __expf(mA - nmA), alB = __expf(mB - nmB);
        mA = nmA; mB = nmB;
        float sumA = 0.f, sumB = 0.f;
        #pragma unroll
        for (int t = 0; t < 16; t++) {
            s[t][0] = __expf(s[t][0] - mA);
            s[t][1] = __expf(s[t][1] - mA);
            s[t][2] = __expf(s[t][2] - mB);
            s[t][3] = __expf(s[t][3] - mB);
            sumA += s[t][0] + s[t][1];
            sumB += s[t][2] + s[t][3];
        }
        #pragma unroll
        for (int off = 1; off < 4; off <<= 1) {
            sumA += __shfl_xor_sync(0xffffffffu, sumA, off);
            sumB += __shfl_xor_sync(0xffffffffu, sumB, off);
        }
        lA = lA*alA + sumA;
        lB = lB*alB + sumB;
        #pragma unroll
        for (int nt = 0; nt < 4; nt++) {
            o_acc[nt][0] *= alA; o_acc[nt][1] *= alA;
            o_acc[nt][2] *= alB; o_acc[nt][3] *= alB;
        }

        // O += P @ V
        #pragma unroll
        for (int j = 0; j < 8; j++) {
            uint32_t ap[4];
            ap[0] = pack2h(s[2*j][0],   s[2*j][1]);
            ap[1] = pack2h(s[2*j][2],   s[2*j][3]);
            ap[2] = pack2h(s[2*j+1][0], s[2*j+1][1]);
            ap[3] = pack2h(s[2*j+1][2], s[2*j+1][3]);
            #pragma unroll
            for (int cb = 0; cb < 2; cb++) {
                uint32_t rv[4];
                ldsm_x4_t(rv, sb + (VB + (j*16 + (lane & 15))*40 + cb*16 + (lane >> 4)*8)*2);
                uint32_t b0[2] = {rv[0], rv[1]}, b1[2] = {rv[2], rv[3]};
                mma_f16(o_acc[cb*2],   ap, b0);
                mma_f16(o_acc[cb*2+1], ap, b1);
            }
        }
        __syncthreads();
    }

    float invA = 1.f/lA, invB = 1.f/lB;
    #pragma unroll
    for (int nt = 0; nt < 4; nt++) {
        o_acc[nt][0] *= invA; o_acc[nt][1] *= invA;
        o_acc[nt][2] *= invB; o_acc[nt][3] *= invB;
    }

    // proj (32x32)
    float r[4][4];
    #pragma unroll
    for (int nt = 0; nt < 4; nt++)
        #pragma unroll
        for (int i = 0; i < 4; i++) r[nt][i] = 0.f;

    #pragma unroll
    for (int j = 0; j < 2; j++) {
        uint32_t ao[4];
        ao[0] = pack2h(o_acc[2*j][0],   o_acc[2*j][1]);
        ao[1] = pack2h(o_acc[2*j][2],   o_acc[2*j][3]);
        ao[2] = pack2h(o_acc[2*j+1][0], o_acc[2*j+1][1]);
        ao[3] = pack2h(o_acc[2*j+1][2], o_acc[2*j+1][3]);
        #pragma unroll
        for (int pr = 0; pr < 2; pr++) {
            uint32_t p4[4];
            ldsm_x4(p4, sb + (ATT_PW + (pr*16 + (lane & 15))*40 + j*16 + (lane >> 4)*8)*2);
            uint32_t b0[2] = {p4[0], p4[2]}, b1[2] = {p4[1], p4[3]};
            mma_f16(r[pr*2],   ao, b0);
            mma_f16(r[pr*2+1], ao, b1);
        }
    }

    {
        size_t pA = pixbase + wid*16 + (lane >> 2);
        size_t pB = pA + 8;
        #pragma unroll
        for (int nt = 0; nt < 4; nt++) {
            int col = nt*8 + (lane & 3)*2;
            float b0 = proj_b[col], b1 = proj_b[col+1];
            *(uint32_t*)(g_y + pA*Cn + col) = pack2h(r[nt][0] + b0, r[nt][1] + b1);
            *(uint32_t*)(g_y + pB*Cn + col) = pack2h(r[nt][2] + b0, r[nt][3] + b1);
        }
    }
}

// ======================= kernels 4/5: fp16 GEMM, 256x128 block, 64x64 warp tile =====
#define KCh 32
#define A_STRIDE 40
#define W_STRIDE 136
#define OFF_A  0
#define OFF_W  (256*A_STRIDE*2)                          // 20480
#define STAGE_BYTES (256*A_STRIDE*2 + KCh*W_STRIDE*2)    // 29184
#define NSTAGE 4
#define GEMM_SMEM (NSTAGE*STAGE_BYTES)                   // 116736

template<int NTOT, int KTOT, int MODE>
__global__ __launch_bounds__(256)
void mma_gemm_kernel(const __half* __restrict__ Ag, const __half* __restrict__ Wg,
                     const float* __restrict__ bias,
                     __half* __restrict__ H, float* __restrict__ Out)
{
    extern __shared__ char smraw[];
    const uint32_t smem_base = smem_to_u32(smraw);

    const int tid = threadIdx.x;
    const int lane = tid & 31, wid = tid >> 5;
    const int warp_m = wid & 3;          // 4 warps over M (64 rows each)
    const int warp_n = wid >> 2;         // 2 warps over N (64 cols each)
    const int m0 = blockIdx.y*256, n0 = blockIdx.x*128;
    constexpr int NC = KTOT / KCh;

    float acc[4][8][4];
    #pragma unroll
    for (int mt = 0; mt < 4; mt++)
        #pragma unroll
        for (int nt = 0; nt < 8; nt++)
            #pragma unroll
            for (int i = 0; i < 4; i++) acc[mt][nt][i] = 0.f;

    auto ISSUE = [&](int kc, int buf) {
        uint32_t sbase = smem_base + buf*STAGE_BYTES;
        #pragma unroll
        for (int q = 0; q < 4; q++) {
            int idx = tid + q*256;
            int row = idx >> 2, seg = idx & 3;
            uint32_t dst = sbase + OFF_A + row*(A_STRIDE*2) + seg*16;
            const __half* src = Ag + (size_t)(m0 + row)*KTOT + kc*KCh + seg*8;
            CP_ASYNC16(dst, src);
        }
        #pragma unroll
        for (int q = 0; q < 2; q++) {
            int idx = tid + q*256;
            int row = idx >> 4, seg = idx & 15;
            uint32_t dst = sbase + OFF_W + row*(W_STRIDE*2) + seg*16;
            const __half* src = Wg + (size_t)(kc*KCh + row)*NTOT + n0 + seg*8;
            CP_ASYNC16(dst, src);
        }
    };

    auto COMPUTE = [&](int buf) {
        uint32_t sbx = smem_base + buf*STAGE_BYTES;
        #pragma unroll
        for (int ks = 0; ks < 2; ks++) {
            int k0 = ks*16;
            uint32_t a[4][4];
            #pragma unroll
            for (int mt = 0; mt < 4; mt++) {
                uint32_t off = ((warp_m*64 + mt*16 + (lane & 15))*A_STRIDE + k0 + ((lane >> 4) << 3))*2;
                ldsm_x4(a[mt], sbx + OFF_A + off);
            }
            #pragma unroll
            for (int np = 0; np < 4; np++) {
                uint32_t off = ((k0 + (lane & 15))*W_STRIDE + warp_n*64 + np*16 + ((lane >> 4) << 3))*2;
                uint32_t rw[4];
                ldsm_x4_t(rw, sbx + OFF_W + off);
                uint32_t b0[2] = {rw[0], rw[1]}, b1[2] = {rw[2], rw[3]};
                #pragma unroll
                for (int mt = 0; mt < 4; mt++) {
                    mma_f16(acc[mt][2*np],   a[mt], b0);
                    mma_f16(acc[mt][2*np+1], a[mt], b1);
                }
            }
        }
    };

    #pragma unroll
    for (int s = 0; s < NSTAGE-1; s++) {
        if (s < NC) ISSUE(s, s);
        CP_COMMIT();
    }
    for (int kc = 0; kc < NC; kc++) {
        CP_WAIT(NSTAGE-2);
        __syncthreads();
        COMPUTE(kc % NSTAGE);
        int nx = kc + NSTAGE - 1;
        if (nx < NC) ISSUE(nx, nx % NSTAGE);
        CP_COMMIT();
    }
    CP_WAIT(0);

    if (MODE == 1) {
        #pragma unroll
        for (int mt = 0; mt < 4; mt++)
            #pragma unroll
            for (int half = 0; half < 2; half++) {
                int row = m0 + warp_m*64 + mt*16 + (lane >> 2) + half*8;
                #pragma unroll
                for (int nt = 0; nt < 8; nt++) {
                    int col = n0 + warp_n*64 + nt*8 + (lane & 3)*2;
                    float f0 = fmaxf(acc[mt][nt][half*2+0] + bias[col],   0.f);
                    float f1 = fmaxf(acc[mt][nt][half*2+1] + bias[col+1], 0.f);
                    *(uint32_t*)(H + (size_t)row*NTOT + col) = pack2h(f0, f1);
                }
            }
    } else {
        float* Ct = (float*)smraw;    // [128][129]
        #pragma unroll
        for (int mh = 0; mh < 2; mh++) {
            __syncthreads();
            if ((warp_m >> 1) == mh) {
                #pragma unroll
                for (int mt = 0; mt < 4; mt++)
                    #pragma unroll
                    for (int half = 0; half < 2; half++) {
                        int rl = (warp_m & 1)*64 + mt*16 + (lane >> 2) + half*8;
                        #pragma unroll
                        for (int nt = 0; nt < 8; nt++) {
                            int cl = warp_n*64 + nt*8 + (lane & 3)*2;
                            Ct[rl*129 + cl]     = acc[mt][nt][half*2+0];
                            Ct[rl*129 + cl + 1] = acc[mt][nt][half*2+1];
                        }
                    }
            }
            __syncthreads();
            int pix0 = m0 + mh*128;
            int bb = pix0 >> 10, nn0 = pix0 & (HWn-1);
            #pragma unroll
            for (int cc = 0; cc < 16; cc++) {
                int col = wid*16 + cc;
                int co = n0 + col;
                float bi = bias[co];
                float* ob = Out + (size_t)bb*Cn*HWn + (size_t)co*HWn + nn0;
                #pragma unroll
                for (int j = 0; j < 4; j++) {
                    int rr = lane + 32*j;
                    ob[rr] = Ct[rr*129 + col] + bi;
                }
            }
        }
    }
}

// ======================= launch =======================
extern "C" void kernel_launch(void* const* d_in, const int* in_sizes, int n_in,
                              void* d_out, int out_size)
{
    const float* x      = (const float*)d_in[0];
    const float* fc1_w  = (const float*)d_in[1];
    const float* fc1_b  = (const float*)d_in[2];
    const float* fc2_w  = (const float*)d_in[3];
    const float* fc2_b  = (const float*)d_in[4];
    const float* qkv_w  = (const float*)d_in[5];
    const float* qkv_b  = (const float*)d_in[6];
    const float* proj_w = (const float*)d_in[7];
    const float* proj_b = (const float*)d_in[8];
    const float* ffn1_w = (const float*)d_in[9];
    const float* ffn1_b = (const float*)d_in[10];
    const float* ffn2_w = (const float*)d_in[11];
    const float* ffn2_b = (const float*)d_in[12];
    float* out = (float*)d_out;

    cudaFuncSetAttribute(attn_mma_kernel, cudaFuncAttributeMaxDynamicSharedMemorySize, ATT_SMEM_BYTES);
    cudaFuncSetAttribute((const void*)mma_gemm_kernel<C4n, Cn, 1>, cudaFuncAttributeMaxDynamicSharedMemorySize, GEMM_SMEM);
    cudaFuncSetAttribute((const void*)mma_gemm_kernel<Cn, C4n, 2>, cudaFuncAttributeMaxDynamicSharedMemorySize, GEMM_SMEM);

    __half *yp, *hp, *w1, *w2;
    cudaGetSymbolAddress((void**)&yp, g_y);
    cudaGetSymbolAddress((void**)&hp, g_h);
    cudaGetSymbolAddress((void**)&w1, g_w1);
    cudaGetSymbolAddress((void**)&w2, g_w2);

    convertw_T<<<dim3(Cn/32, C4n/32), 256>>>(ffn1_w, w1, C4n, Cn);
    convertw_T<<<dim3(C4n/32, Cn/32), 256>>>(ffn2_w, w2, Cn, C4n);

    se1_kernel<<<128, 256>>>(x);
    se2_kernel<<<Bn, 256>>>(fc1_w, fc1_b, fc2_w, fc2_b);
    gate_all_kernel<<<dim3(8, Bn), 256>>>(x, qkv_w, qkv_b);
    attn_mma_kernel<<<dim3(8, Bn), 256, ATT_SMEM_BYTES>>>(proj_w, proj_b);

    mma_gemm_kernel<C4n, Cn, 1><<<dim3(C4n/128, NPIX/256), 256, GEMM_SMEM>>>(
        yp, w1, ffn1_b, hp, nullptr);
    mma_gemm_kernel<Cn, C4n, 2><<<dim3(Cn/128, NPIX/256), 256, GEMM_SMEM>>>(
        hp, w2, ffn2_b, nullptr, out);
}

// round 13
// speedup vs baseline: 5.4504x; 1.0402x over previous
#include <cuda_runtime.h>
#include <cuda_fp16.h>
#include <cstdint>
#include <math.h>

#define Bn   16
#define Cn   256
#define HWn  1024
#define ADn  16
#define SCn  32
#define CRn  64
#define C4n  1024
#define NPIX (Bn*HWn)   // 16384

// ======================= device scratch =======================
__device__ float g_part[Bn*8*Cn];
__device__ float g_s[Bn*Cn];
__device__ __align__(256) __half g_q[Bn*HWn*ADn];
__device__ __align__(256) __half g_k[Bn*HWn*ADn];
__device__ __align__(256) __half g_v[Bn*HWn*SCn];
__device__ __align__(256) __half g_y[NPIX*Cn];
__device__ __align__(256) __half g_h[NPIX*C4n];
__device__ __align__(256) __half g_w1[Cn*C4n];
__device__ __align__(256) __half g_w2[C4n*Cn];

// ======================= PTX helpers =======================
__device__ __forceinline__ uint32_t smem_to_u32(const void* p) {
    uint32_t a;
    asm("{ .reg .u64 t; cvta.to.shared.u64 t, %1; cvt.u32.u64 %0, t; }" : "=r"(a) : "l"(p));
    return a;
}
__device__ __forceinline__ void ldsm_x4(uint32_t r[4], uint32_t addr) {
    asm volatile("ldmatrix.sync.aligned.m8n8.x4.shared.b16 {%0,%1,%2,%3}, [%4];"
        : "=r"(r[0]), "=r"(r[1]), "=r"(r[2]), "=r"(r[3]) : "r"(addr));
}
__device__ __forceinline__ void ldsm_x4_t(uint32_t r[4], uint32_t addr) {
    asm volatile("ldmatrix.sync.aligned.m8n8.x4.trans.shared.b16 {%0,%1,%2,%3}, [%4];"
        : "=r"(r[0]), "=r"(r[1]), "=r"(r[2]), "=r"(r[3]) : "r"(addr));
}
__device__ __forceinline__ void mma_f16(float c[4], const uint32_t a[4], const uint32_t b[2]) {
    asm volatile("mma.sync.aligned.m16n8k16.row.col.f32.f16.f16.f32 "
        "{%0,%1,%2,%3}, {%4,%5,%6,%7}, {%8,%9}, {%0,%1,%2,%3};"
        : "+f"(c[0]), "+f"(c[1]), "+f"(c[2]), "+f"(c[3])
        : "r"(a[0]), "r"(a[1]), "r"(a[2]), "r"(a[3]), "r"(b[0]), "r"(b[1]));
}
#define CP_ASYNC16(dst, src) \
    asm volatile("cp.async.cg.shared.global [%0], [%1], 16;" :: "r"(dst), "l"(src))
#define CP_COMMIT() asm volatile("cp.async.commit_group;")
#define CP_WAIT(n)  asm volatile("cp.async.wait_group %0;" :: "n"(n))

__device__ __forceinline__ uint32_t pack2h(float f0, float f1) {
    __half2 h = __floats2half2_rn(f0, f1);
    return *(uint32_t*)&h;
}

// ======================= weight convert+transpose (tiled) =======================
__global__ __launch_bounds__(256) void convertw_T(
    const float* __restrict__ w, __half* __restrict__ t, int O, int K)
{
    __shared__ float s[32][33];
    int k0 = blockIdx.x*32, o0 = blockIdx.y*32;
    int tid = threadIdx.x;
    #pragma unroll
    for (int i = tid; i < 1024; i += 256) {
        int o = i >> 5, k = i & 31;
        s[k][o] = w[(size_t)(o0 + o)*K + k0 + k];
    }
    __syncthreads();
    #pragma unroll
    for (int i = tid; i < 1024; i += 256) {
        int k = i >> 5, o = i & 31;
        t[(size_t)(k0 + k)*O + o0 + o] = __float2half_rn(s[k][o]);
    }
}

// ======================= kernel 1a: SE partial means (128 blocks) ==================
__global__ __launch_bounds__(256) void se1_kernel(const float* __restrict__ x)
{
    int s = blockIdx.x & 7, b = blockIdx.x >> 3;
    int tid = threadIdx.x, warp = tid >> 5, lane = tid & 31;
    #pragma unroll
    for (int c = warp; c < Cn; c += 8) {
        float4 v = *(const float4*)(x + ((size_t)b*Cn + c)*HWn + s*128 + lane*4);
        float sum = v.x + v.y + v.z + v.w;
        #pragma unroll
        for (int o = 16; o > 0; o >>= 1) sum += __shfl_xor_sync(0xffffffffu, sum, o);
        if (lane == 0) g_part[(b*8 + s)*Cn + c] = sum;
    }
}

// ======================= kernel 1b: SE finish (coalesced warp reductions) ==========
__global__ __launch_bounds__(256) void se2_kernel(
    const float* __restrict__ fc1_w, const float* __restrict__ fc1_b,
    const float* __restrict__ fc2_w, const float* __restrict__ fc2_b)
{
    __shared__ float mean[Cn];
    __shared__ float s1[CRn];
    int b = blockIdx.x, tid = threadIdx.x, lane = tid & 31, warp = tid >> 5;
    {
        float sum = 0.f;
        #pragma unroll
        for (int s = 0; s < 8; s++) sum += g_part[(b*8 + s)*Cn + tid];
        mean[tid] = sum * (1.0f/HWn);
    }
    __syncthreads();
    // fc1: 8 warps x 8 outputs; lanes stride K=256 (coalesced)
    #pragma unroll
    for (int i = 0; i < 8; i++) {
        int o = warp*8 + i;
        const float* wr = fc1_w + o*Cn;
        float sum = 0.f;
        #pragma unroll
        for (int j = 0; j < 8; j++) {
            int c = lane + 32*j;
            sum += wr[c]*mean[c];
        }
        #pragma unroll
        for (int off = 16; off > 0; off >>= 1) sum += __shfl_xor_sync(0xffffffffu, sum, off);
        if (lane == 0) s1[o] = fmaxf(sum + fc1_b[o], 0.f);
    }
    __syncthreads();
    // fc2: 8 warps x 32 outputs; lanes split K=64 (coalesced)
    #pragma unroll
    for (int i = 0; i < 32; i++) {
        int o = warp*32 + i;
        const float* wr = fc2_w + o*CRn;
        float sum = wr[lane]*s1[lane] + wr[lane+32]*s1[lane+32];
        #pragma unroll
        for (int off = 16; off > 0; off >>= 1) sum += __shfl_xor_sync(0xffffffffu, sum, off);
        if (lane == 0) g_s[b*Cn + o] = 1.f/(1.f + __expf(-(sum + fc2_b[o])));
    }
}

// ======================= kernel 2: fused gate + qkv (cp.async double-buffered) =====
__global__ __launch_bounds__(256) void gate_all_kernel(
    const float* __restrict__ x,
    const float* __restrict__ qkv_w, const float* __restrict__ qkv_b)
{
    __shared__ float t[2*32*132];
    __shared__ float ws[32][64];
    __shared__ float sgall[Cn];
    __shared__ float qb[64];

    int b = blockIdx.y, n0 = blockIdx.x*128;
    int tid = threadIdx.x;
    const uint32_t tbase = smem_to_u32(t);

    for (int i = tid; i < 64*SCn; i += 256) { int o = i >> 5, c = i & 31; ws[c][o] = qkv_w[i]; }
    if (tid < 64) qb[tid] = qkv_b[tid];
    sgall[tid] = g_s[b*Cn + tid];

    int p   = tid & 127;
    int sub = tid >> 7;
    size_t P = (size_t)b*HWn + n0 + p;

    auto ISSUE_X = [&](int cg, int buf) {
        #pragma unroll
        for (int q = 0; q < 4; q++) {
            int idx = tid + q*256;
            int row = idx >> 5, seg = idx & 31;
            uint32_t dst = tbase + (uint32_t)(buf*4224 + row*132)*4 + seg*16;
            const float* src = x + ((size_t)b*Cn + cg*32 + row)*HWn + n0 + seg*4;
            CP_ASYNC16(dst, src);
        }
    };

    ISSUE_X(0, 0); CP_COMMIT();

    for (int cg = 0; cg < 8; cg++) {
        int buf = cg & 1;
        if (cg < 7) { ISSUE_X(cg + 1, buf ^ 1); CP_COMMIT(); CP_WAIT(1); }
        else        { CP_WAIT(0); }
        __syncthreads();
        const float* tb = t + buf*4224;

        if (cg == 0) {
            float acc[32];
            #pragma unroll
            for (int o = 0; o < 32; o++) acc[o] = qb[sub*32 + o];
            #pragma unroll 4
            for (int c = 0; c < SCn; c++) {
                float xv = tb[c*132 + p] * sgall[c];
                #pragma unroll
                for (int o4 = 0; o4 < 8; o4++) {
                    float4 w = *(const float4*)&ws[c][sub*32 + o4*4];
                    acc[o4*4+0] += w.x*xv;
                    acc[o4*4+1] += w.y*xv;
                    acc[o4*4+2] += w.z*xv;
                    acc[o4*4+3] += w.w*xv;
                }
            }
            __align__(16) uint32_t pk[16];
            if (sub == 0) {
                #pragma unroll
                for (int i = 0; i < 8; i++) pk[i] = pack2h(acc[2*i]*0.25f, acc[2*i+1]*0.25f);
                #pragma unroll
                for (int i = 8; i < 16; i++) pk[i] = pack2h(acc[2*i], acc[2*i+1]);
                *(uint4*)(g_q + P*ADn)     = *(uint4*)&pk[0];
                *(uint4*)(g_q + P*ADn + 8) = *(uint4*)&pk[4];
                *(uint4*)(g_k + P*ADn)     = *(uint4*)&pk[8];
                *(uint4*)(g_k + P*ADn + 8) = *(uint4*)&pk[12];
            } else {
                #pragma unroll
                for (int i = 0; i < 16; i++) pk[i] = pack2h(acc[2*i], acc[2*i+1]);
                #pragma unroll
                for (int q = 0; q < 4; q++)
                    *(uint4*)(g_v + P*SCn + q*8) = *(uint4*)&pk[4*q];
            }
        } else {
            int c0 = cg*32;
            __align__(16) uint32_t pk[8];
            #pragma unroll
            for (int i = 0; i < 8; i++) {
                int c = sub*16 + 2*i;
                pk[i] = pack2h(tb[c*132 + p]*sgall[c0+c], tb[(c+1)*132 + p]*sgall[c0+c+1]);
            }
            *(uint4*)(g_y + P*Cn + c0 + sub*16)     = *(uint4*)&pk[0];
            *(uint4*)(g_y + P*Cn + c0 + sub*16 + 8) = *(uint4*)&pk[4];
        }
        __syncthreads();
    }
}

// ======================= kernel 3: flash attention (64-row tiles, 128 thr) =========
#define ATT_Q   0
#define ATT_K0  1536
#define ATT_K1  4608
#define ATT_V0  7680
#define ATT_V1  12800
#define ATT_PW  17920
#define ATT_SMEM_BYTES (19200*2)   // 38400

__global__ __launch_bounds__(128) void attn_mma_kernel(
    const float* __restrict__ proj_w, const float* __restrict__ proj_b)
{
    extern __shared__ __half smb[];
    const uint32_t sb = smem_to_u32(smb);
    const int tid = threadIdx.x, lane = tid & 31, wid = tid >> 5;
    const int b = blockIdx.y;
    const int m0 = blockIdx.x*64;
    const size_t pixbase = (size_t)b*HWn + m0;

    { // stage Q (64 rows) + proj weights
        int row = tid >> 1, half = tid & 1;
        *(uint4*)(smb + ATT_Q + row*24 + half*8) = *(const uint4*)(g_q + (pixbase + row)*ADn + half*8);
    }
    for (int i = tid; i < SCn*SCn; i += 128) {
        int o = i >> 5, c = i & 31;
        smb[ATT_PW + o*40 + c] = __float2half_rn(proj_w[i]);
    }

    auto ISSUE_KV = [&](int kc, int buf) {
        size_t kb = (size_t)b*HWn + kc*128;
        #pragma unroll
        for (int q = 0; q < 2; q++) {
            int idx = tid + q*128;
            int row = idx >> 1, half = idx & 1;
            uint32_t kdst = sb + (uint32_t)((buf ? ATT_K1 : ATT_K0) + row*24 + half*8)*2;
            CP_ASYNC16(kdst, g_k + (kb + row)*ADn + half*8);
        }
        #pragma unroll
        for (int q = 0; q < 4; q++) {
            int idx = tid + q*128;
            int vr = idx >> 2, part = idx & 3;
            uint32_t vdst = sb + (uint32_t)((buf ? ATT_V1 : ATT_V0) + vr*40 + part*8)*2;
            CP_ASYNC16(vdst, g_v + (kb + vr)*SCn + part*8);
        }
    };

    ISSUE_KV(0, 0); CP_COMMIT();
    __syncthreads();

    uint32_t aq[4];
    ldsm_x4(aq, sb + (ATT_Q + (wid*16 + (lane & 15))*24 + (lane >> 4)*8)*2);

    float o_acc[4][4];
    #pragma unroll
    for (int nt = 0; nt < 4; nt++)
        #pragma unroll
        for (int i = 0; i < 4; i++) o_acc[nt][i] = 0.f;
    float mA = -1e30f, mB = -1e30f, lA = 0.f, lB = 0.f;

    for (int kc = 0; kc < 8; kc++) {
        int buf = kc & 1;
        if (kc < 7) { ISSUE_KV(kc + 1, buf ^ 1); CP_COMMIT(); CP_WAIT(1); }
        else        { CP_WAIT(0); }
        __syncthreads();
        const uint32_t KB = buf ? ATT_K1 : ATT_K0;
        const uint32_t VB = buf ? ATT_V1 : ATT_V0;

        // S = QK^T
        float s[16][4];
        #pragma unroll
        for (int t = 0; t < 16; t++)
            #pragma unroll
            for (int i = 0; i < 4; i++) s[t][i] = 0.f;

        #pragma unroll
        for (int pr = 0; pr < 8; pr++) {
            uint32_t k4[4];
            ldsm_x4(k4, sb + (KB + (pr*16 + (lane & 15))*24 + (lane >> 4)*8)*2);
            uint32_t b0[2] = {k4[0], k4[2]}, b1[2] = {k4[1], k4[3]};
            mma_f16(s[2*pr],   aq, b0);
            mma_f16(s[2*pr+1], aq, b1);
        }

        // online softmax
        float cmA = -1e30f, cmB = -1e30f;
        #pragma unroll
        for (int t = 0; t < 16; t++) {
            cmA = fmaxf(cmA, fmaxf(s[t][0], s[t][1]));
            cmB = fmaxf(cmB, fmaxf(s[t][2], s[t][3]));
        }
        #pragma unroll
        for (int off = 1; off < 4; off <<= 1) {
            cmA = fmaxf(cmA, __shfl_xor_sync(0xffffffffu, cmA, off));
            cmB = fmaxf(cmB, __shfl_xor_sync(0xffffffffu, cmB, off));
        }
        float nmA = fmaxf(mA, cmA), nmB = fmaxf(mB, cmB);
        float alA = __expf(mA - nmA), alB = __expf(mB - nmB);
        mA = nmA; mB = nmB;
        float sumA = 0.f, sumB = 0.f;
        #pragma unroll
        for (int t = 0; t < 16; t++) {
            s[t][0] = __expf(s[t][0] - mA);
            s[t][1] = __expf(s[t][1] - mA);
            s[t][2] = __expf(s[t][2] - mB);
            s[t][3] = __expf(s[t][3] - mB);
            sumA += s[t][0] + s[t][1];
            sumB += s[t][2] + s[t][3];
        }
        #pragma unroll
        for (int off = 1; off < 4; off <<= 1) {
            sumA += __shfl_xor_sync(0xffffffffu, sumA, off);
            sumB += __shfl_xor_sync(0xffffffffu, sumB, off);
        }
        lA = lA*alA + sumA;
        lB = lB*alB + sumB;
        #pragma unroll
        for (int nt = 0; nt < 4; nt++) {
            o_acc[nt][0] *= alA; o_acc[nt][1] *= alA;
            o_acc[nt][2] *= alB; o_acc[nt][3] *= alB;
        }

        // O += P @ V
        #pragma unroll
        for (int j = 0; j < 8; j++) {
            uint32_t ap[4];
            ap[0] = pack2h(s[2*j][0],   s[2*j][1]);
            ap[1] = pack2h(s[2*j][2],   s[2*j][3]);
            ap[2] = pack2h(s[2*j+1][0], s[2*j+1][1]);
            ap[3] = pack2h(s[2*j+1][2], s[2*j+1][3]);
            #pragma unroll
            for (int cb = 0; cb < 2; cb++) {
                uint32_t rv[4];
                ldsm_x4_t(rv, sb + (VB + (j*16 + (lane & 15))*40 + cb*16 + (lane >> 4)*8)*2);
                uint32_t b0[2] = {rv[0], rv[1]}, b1[2] = {rv[2], rv[3]};
                mma_f16(o_acc[cb*2],   ap, b0);
                mma_f16(o_acc[cb*2+1], ap, b1);
            }
        }
        __syncthreads();
    }

    float invA = 1.f/lA, invB = 1.f/lB;
    #pragma unroll
    for (int nt = 0; nt < 4; nt++) {
        o_acc[nt][0] *= invA; o_acc[nt][1] *= invA;
        o_acc[nt][2] *= invB; o_acc[nt][3] *= invB;
    }

    // proj (32x32)
    float r[4][4];
    #pragma unroll
    for (int nt = 0; nt < 4; nt++)
        #pragma unroll
        for (int i = 0; i < 4; i++) r[nt][i] = 0.f;

    #pragma unroll
    for (int j = 0; j < 2; j++) {
        uint32_t ao[4];
        ao[0] = pack2h(o_acc[2*j][0],   o_acc[2*j][1]);
        ao[1] = pack2h(o_acc[2*j][2],   o_acc[2*j][3]);
        ao[2] = pack2h(o_acc[2*j+1][0], o_acc[2*j+1][1]);
        ao[3] = pack2h(o_acc[2*j+1][2], o_acc[2*j+1][3]);
        #pragma unroll
        for (int pr = 0; pr < 2; pr++) {
            uint32_t p4[4];
            ldsm_x4(p4, sb + (ATT_PW + (pr*16 + (lane & 15))*40 + j*16 + (lane >> 4)*8)*2);
            uint32_t b0[2] = {p4[0], p4[2]}, b1[2] = {p4[1], p4[3]};
            mma_f16(r[pr*2],   ao, b0);
            mma_f16(r[pr*2+1], ao, b1);
        }
    }

    {
        size_t pA = pixbase + wid*16 + (lane >> 2);
        size_t pB = pA + 8;
        #pragma unroll
        for (int nt = 0; nt < 4; nt++) {
            int col = nt*8 + (lane & 3)*2;
            float b0 = proj_b[col], b1 = proj_b[col+1];
            *(uint32_t*)(g_y + pA*Cn + col) = pack2h(r[nt][0] + b0, r[nt][1] + b1);
            *(uint32_t*)(g_y + pB*Cn + col) = pack2h(r[nt][2] + b0, r[nt][3] + b1);
        }
    }
}

// ======================= kernels 4/5: fp16 GEMM, 256x128 block, 64x64 warp tile =====
#define KCh 32
#define A_STRIDE 40
#define W_STRIDE 136
#define OFF_A  0
#define OFF_W  (256*A_STRIDE*2)                          // 20480
#define STAGE_BYTES (256*A_STRIDE*2 + KCh*W_STRIDE*2)    // 29184
#define NSTAGE 4
#define GEMM_SMEM (NSTAGE*STAGE_BYTES)                   // 116736

template<int NTOT, int KTOT, int MODE>
__global__ __launch_bounds__(256)
void mma_gemm_kernel(const __half* __restrict__ Ag, const __half* __restrict__ Wg,
                     const float* __restrict__ bias,
                     __half* __restrict__ H, float* __restrict__ Out)
{
    extern __shared__ char smraw[];
    const uint32_t smem_base = smem_to_u32(smraw);

    const int tid = threadIdx.x;
    const int lane = tid & 31, wid = tid >> 5;
    const int warp_m = wid & 3;
    const int warp_n = wid >> 2;
    const int m0 = blockIdx.y*256, n0 = blockIdx.x*128;
    constexpr int NC = KTOT / KCh;

    float acc[4][8][4];
    #pragma unroll
    for (int mt = 0; mt < 4; mt++)
        #pragma unroll
        for (int nt = 0; nt < 8; nt++)
            #pragma unroll
            for (int i = 0; i < 4; i++) acc[mt][nt][i] = 0.f;

    auto ISSUE = [&](int kc, int buf) {
        uint32_t sbase = smem_base + buf*STAGE_BYTES;
        #pragma unroll
        for (int q = 0; q < 4; q++) {
            int idx = tid + q*256;
            int row = idx >> 2, seg = idx & 3;
            uint32_t dst = sbase + OFF_A + row*(A_STRIDE*2) + seg*16;
            const __half* src = Ag + (size_t)(m0 + row)*KTOT + kc*KCh + seg*8;
            CP_ASYNC16(dst, src);
        }
        #pragma unroll
        for (int q = 0; q < 2; q++) {
            int idx = tid + q*256;
            int row = idx >> 4, seg = idx & 15;
            uint32_t dst = sbase + OFF_W + row*(W_STRIDE*2) + seg*16;
            const __half* src = Wg + (size_t)(kc*KCh + row)*NTOT + n0 + seg*8;
            CP_ASYNC16(dst, src);
        }
    };

    auto COMPUTE = [&](int buf) {
        uint32_t sbx = smem_base + buf*STAGE_BYTES;
        #pragma unroll
        for (int ks = 0; ks < 2; ks++) {
            int k0 = ks*16;
            uint32_t a[4][4];
            #pragma unroll
            for (int mt = 0; mt < 4; mt++) {
                uint32_t off = ((warp_m*64 + mt*16 + (lane & 15))*A_STRIDE + k0 + ((lane >> 4) << 3))*2;
                ldsm_x4(a[mt], sbx + OFF_A + off);
            }
            #pragma unroll
            for (int np = 0; np < 4; np++) {
                uint32_t off = ((k0 + (lane & 15))*W_STRIDE + warp_n*64 + np*16 + ((lane >> 4) << 3))*2;
                uint32_t rw[4];
                ldsm_x4_t(rw, sbx + OFF_W + off);
                uint32_t b0[2] = {rw[0], rw[1]}, b1[2] = {rw[2], rw[3]};
                #pragma unroll
                for (int mt = 0; mt < 4; mt++) {
                    mma_f16(acc[mt][2*np],   a[mt], b0);
                    mma_f16(acc[mt][2*np+1], a[mt], b1);
                }
            }
        }
    };

    #pragma unroll
    for (int s = 0; s < NSTAGE-1; s++) {
        if (s < NC) ISSUE(s, s);
        CP_COMMIT();
    }
    for (int kc = 0; kc < NC; kc++) {
        CP_WAIT(NSTAGE-2);
        __syncthreads();
        COMPUTE(kc % NSTAGE);
        int nx = kc + NSTAGE - 1;
        if (nx < NC) ISSUE(nx, nx % NSTAGE);
        CP_COMMIT();
    }
    CP_WAIT(0);

    if (MODE == 1) {
        #pragma unroll
        for (int mt = 0; mt < 4; mt++)
            #pragma unroll
            for (int half = 0; half < 2; half++) {
                int row = m0 + warp_m*64 + mt*16 + (lane >> 2) + half*8;
                #pragma unroll
                for (int nt = 0; nt < 8; nt++) {
                    int col = n0 + warp_n*64 + nt*8 + (lane & 3)*2;
                    float f0 = fmaxf(acc[mt][nt][half*2+0] + bias[col],   0.f);
                    float f1 = fmaxf(acc[mt][nt][half*2+1] + bias[col+1], 0.f);
                    *(uint32_t*)(H + (size_t)row*NTOT + col) = pack2h(f0, f1);
                }
            }
    } else {
        float* Ct = (float*)smraw;    // [128][129]
        #pragma unroll
        for (int mh = 0; mh < 2; mh++) {
            __syncthreads();
            if ((warp_m >> 1) == mh) {
                #pragma unroll
                for (int mt = 0; mt < 4; mt++)
                    #pragma unroll
                    for (int half = 0; half < 2; half++) {
                        int rl = (warp_m & 1)*64 + mt*16 + (lane >> 2) + half*8;
                        #pragma unroll
                        for (int nt = 0; nt < 8; nt++) {
                            int cl = warp_n*64 + nt*8 + (lane & 3)*2;
                            Ct[rl*129 + cl]     = acc[mt][nt][half*2+0];
                            Ct[rl*129 + cl + 1] = acc[mt][nt][half*2+1];
                        }
                    }
            }
            __syncthreads();
            int pix0 = m0 + mh*128;
            int bb = pix0 >> 10, nn0 = pix0 & (HWn-1);
            #pragma unroll
            for (int cc = 0; cc < 16; cc++) {
                int col = wid*16 + cc;
                int co = n0 + col;
                float bi = bias[co];
                float* ob = Out + (size_t)bb*Cn*HWn + (size_t)co*HWn + nn0;
                #pragma unroll
                for (int j = 0; j < 4; j++) {
                    int rr = lane + 32*j;
                    ob[rr] = Ct[rr*129 + col] + bi;
                }
            }
        }
    }
}

// ======================= launch =======================
extern "C" void kernel_launch(void* const* d_in, const int* in_sizes, int n_in,
                              void* d_out, int out_size)
{
    const float* x      = (const float*)d_in[0];
    const float* fc1_w  = (const float*)d_in[1];
    const float* fc1_b  = (const float*)d_in[2];
    const float* fc2_w  = (const float*)d_in[3];
    const float* fc2_b  = (const float*)d_in[4];
    const float* qkv_w  = (const float*)d_in[5];
    const float* qkv_b  = (const float*)d_in[6];
    const float* proj_w = (const float*)d_in[7];
    const float* proj_b = (const float*)d_in[8];
    const float* ffn1_w = (const float*)d_in[9];
    const float* ffn1_b = (const float*)d_in[10];
    const float* ffn2_w = (const float*)d_in[11];
    const float* ffn2_b = (const float*)d_in[12];
    float* out = (float*)d_out;

    cudaFuncSetAttribute(attn_mma_kernel, cudaFuncAttributeMaxDynamicSharedMemorySize, ATT_SMEM_BYTES);
    cudaFuncSetAttribute((const void*)mma_gemm_kernel<C4n, Cn, 1>, cudaFuncAttributeMaxDynamicSharedMemorySize, GEMM_SMEM);
    cudaFuncSetAttribute((const void*)mma_gemm_kernel<Cn, C4n, 2>, cudaFuncAttributeMaxDynamicSharedMemorySize, GEMM_SMEM);

    __half *yp, *hp, *w1, *w2;
    cudaGetSymbolAddress((void**)&yp, g_y);
    cudaGetSymbolAddress((void**)&hp, g_h);
    cudaGetSymbolAddress((void**)&w1, g_w1);
    cudaGetSymbolAddress((void**)&w2, g_w2);

    convertw_T<<<dim3(Cn/32, C4n/32), 256>>>(ffn1_w, w1, C4n, Cn);
    convertw_T<<<dim3(C4n/32, Cn/32), 256>>>(ffn2_w, w2, Cn, C4n);

    se1_kernel<<<128, 256>>>(x);
    se2_kernel<<<Bn, 256>>>(fc1_w, fc1_b, fc2_w, fc2_b);
    gate_all_kernel<<<dim3(8, Bn), 256>>>(x, qkv_w, qkv_b);
    attn_mma_kernel<<<dim3(16, Bn), 128, ATT_SMEM_BYTES>>>(proj_w, proj_b);

    mma_gemm_kernel<C4n, Cn, 1><<<dim3(C4n/128, NPIX/256), 256, GEMM_SMEM>>>(
        yp, w1, ffn1_b, hp, nullptr);
    mma_gemm_kernel<Cn, C4n, 2><<<dim3(Cn/128, NPIX/256), 256, GEMM_SMEM>>>(
        hp, w2, ffn2_b, nullptr, out);
}